// round 3
// baseline (speedup 1.0000x reference)
#include <cuda_runtime.h>
#include <float.h>
#include <math.h>

#define NN   2048
#define BBATCH 4
#define SS   1024
#define SFZ  384
#define IFZ  256
#define HH   8
#define AA   64
#define HA   512
#define MAXT 36

// ---------------- static device scratch (no allocations) -------------------
__device__ float g_q[NN * HA];
__device__ float g_gate[NN * HA];
__device__ float g_k[BBATCH * SS * HA];
__device__ float g_v[BBATCH * SS * HA];
__device__ float g_feat[NN * HA];
__device__ float g_y[NN * IFZ];
__device__ unsigned char g_mask[BBATCH * SS];
__device__ int g_tb[MAXT], g_ts[MAXT], g_tc[MAXT], g_nt;

// ---------------- 4x4 outer-product FMA ------------------------------------
__device__ __forceinline__ void fma16(float (&acc)[4][4], float4 a, float4 b) {
    acc[0][0] += a.x * b.x; acc[0][1] += a.x * b.y; acc[0][2] += a.x * b.z; acc[0][3] += a.x * b.w;
    acc[1][0] += a.y * b.x; acc[1][1] += a.y * b.y; acc[1][2] += a.y * b.z; acc[1][3] += a.y * b.w;
    acc[2][0] += a.z * b.x; acc[2][1] += a.z * b.y; acc[2][2] += a.z * b.z; acc[2][3] += a.z * b.w;
    acc[3][0] += a.w * b.x; acc[3][1] += a.w * b.y; acc[3][2] += a.w * b.z; acc[3][3] += a.w * b.w;
}

// ---------------- prep: dtype canonicalization + node tiles ----------------
__global__ void prep_k(const void* mask_in, const void* batch_in) {
    __shared__ int flg[2];      // [0]=batch is int32, [1]=mask is bool
    __shared__ int cnt[BBATCH];
    int tid = threadIdx.x;
    if (tid < 2) flg[tid] = 0;
    if (tid < BBATCH) cnt[tid] = 0;
    __syncthreads();

    // batch dtype probe: if int64, odd 32-bit words (high halves) are all 0.
    const unsigned int* bw = (const unsigned int*)batch_in;
    unsigned int o = 0;
    for (int i = tid * 2 + 1; i < NN; i += blockDim.x * 2) o |= bw[i];
    if (o) atomicOr(&flg[0], 1);

    // mask dtype probe: bool array has nonzero bytes at (i&3)!=0 positions.
    const unsigned char* mb = (const unsigned char*)mask_in;
    int f = 0;
    for (int i = tid; i < BBATCH * SS; i += blockDim.x)
        if ((i & 3) && mb[i]) f = 1;
    if (f) atomicOr(&flg[1], 1);
    __syncthreads();

    int is32 = flg[0], isb = flg[1];
    int lc[BBATCH] = {0, 0, 0, 0};
    for (int i = tid; i < NN; i += blockDim.x) {
        int v = is32 ? ((const int*)batch_in)[i]
                     : (int)((const long long*)batch_in)[i];
        lc[v & 3]++;
    }
    #pragma unroll
    for (int b = 0; b < BBATCH; b++) if (lc[b]) atomicAdd(&cnt[b], lc[b]);

    for (int i = tid; i < BBATCH * SS; i += blockDim.x)
        g_mask[i] = isb ? (mb[i] ? 1 : 0) : (((const int*)mask_in)[i] ? 1 : 0);
    __syncthreads();

    if (tid == 0) {
        int st = 0, t = 0;
        for (int b = 0; b < BBATCH; b++) {
            int e = st + cnt[b];
            for (int s = st; s < e; s += 64) {
                g_tb[t] = b; g_ts[t] = s; g_tc[t] = min(64, e - s); t++;
            }
            st = e;
        }
        g_nt = t;
    }
}

// ---------------- q = x@Wq ; gate = sigmoid(x@Wg + bg) ---------------------
__global__ void __launch_bounds__(256) proj_qg_k(const float* __restrict__ x,
                                                 const float* __restrict__ Wq,
                                                 const float* __restrict__ Wg,
                                                 const float* __restrict__ bg) {
    __shared__ float As[16][68];
    __shared__ float Bs[16][64];
    int tid = threadIdx.x, tx = tid & 15, ty = tid >> 4;
    int m0 = blockIdx.x * 64, n0 = blockIdx.y * 64;
    bool isg = (n0 >= HA);
    const float* W = isg ? Wg : Wq;
    int nc0 = isg ? (n0 - HA) : n0;
    float acc[4][4] = {};
    int lm = tid >> 2, lk = (tid & 3) * 4;
    int bk = tid >> 4, bn = (tid & 15) * 4;
    for (int k0 = 0; k0 < IFZ; k0 += 16) {
        float4 a = *(const float4*)(x + (size_t)(m0 + lm) * IFZ + k0 + lk);
        As[lk + 0][lm] = a.x; As[lk + 1][lm] = a.y; As[lk + 2][lm] = a.z; As[lk + 3][lm] = a.w;
        *(float4*)&Bs[bk][bn] = *(const float4*)(W + (size_t)(k0 + bk) * HA + nc0 + bn);
        __syncthreads();
        #pragma unroll
        for (int kk = 0; kk < 16; kk++) {
            float4 a4 = *(float4*)&As[kk][ty * 4];
            float4 b4 = *(float4*)&Bs[kk][tx * 4];
            fma16(acc, a4, b4);
        }
        __syncthreads();
    }
    if (isg) {
        float4 bgv = *(const float4*)(bg + nc0 + tx * 4);
        #pragma unroll
        for (int i = 0; i < 4; i++) {
            int row = m0 + ty * 4 + i;
            float4 o;
            o.x = 1.0f / (1.0f + __expf(-(acc[i][0] + bgv.x)));
            o.y = 1.0f / (1.0f + __expf(-(acc[i][1] + bgv.y)));
            o.z = 1.0f / (1.0f + __expf(-(acc[i][2] + bgv.z)));
            o.w = 1.0f / (1.0f + __expf(-(acc[i][3] + bgv.w)));
            *(float4*)&g_gate[(size_t)row * HA + nc0 + tx * 4] = o;
        }
    } else {
        #pragma unroll
        for (int i = 0; i < 4; i++) {
            int row = m0 + ty * 4 + i;
            *(float4*)&g_q[(size_t)row * HA + nc0 + tx * 4] =
                make_float4(acc[i][0], acc[i][1], acc[i][2], acc[i][3]);
        }
    }
}

// ---------------- k = emb@Wk ; v = emb@Wv ----------------------------------
__global__ void __launch_bounds__(256) proj_kv_k(const float* __restrict__ emb,
                                                 const float* __restrict__ Wk,
                                                 const float* __restrict__ Wv) {
    __shared__ float As[16][68];
    __shared__ float Bs[16][64];
    int tid = threadIdx.x, tx = tid & 15, ty = tid >> 4;
    int m0 = blockIdx.x * 64, n0 = blockIdx.y * 64;
    bool isv = (n0 >= HA);
    const float* W = isv ? Wv : Wk;
    float* Cout = isv ? g_v : g_k;
    int nc0 = isv ? (n0 - HA) : n0;
    float acc[4][4] = {};
    int lm = tid >> 2, lk = (tid & 3) * 4;
    int bk = tid >> 4, bn = (tid & 15) * 4;
    for (int k0 = 0; k0 < SFZ; k0 += 16) {
        float4 a = *(const float4*)(emb + (size_t)(m0 + lm) * SFZ + k0 + lk);
        As[lk + 0][lm] = a.x; As[lk + 1][lm] = a.y; As[lk + 2][lm] = a.z; As[lk + 3][lm] = a.w;
        *(float4*)&Bs[bk][bn] = *(const float4*)(W + (size_t)(k0 + bk) * HA + nc0 + bn);
        __syncthreads();
        #pragma unroll
        for (int kk = 0; kk < 16; kk++) {
            float4 a4 = *(float4*)&As[kk][ty * 4];
            float4 b4 = *(float4*)&Bs[kk][tx * 4];
            fma16(acc, a4, b4);
        }
        __syncthreads();
    }
    #pragma unroll
    for (int i = 0; i < 4; i++) {
        int row = m0 + ty * 4 + i;
        *(float4*)&Cout[(size_t)row * HA + nc0 + tx * 4] =
            make_float4(acc[i][0], acc[i][1], acc[i][2], acc[i][3]);
    }
}

// ---------------- attention: flash masked softmax + gated feature ----------
// grid (MAXT, HH), 256 threads. One 64-node tile x one head per block.
__global__ void __launch_bounds__(256) attn_k(float* __restrict__ logits) {
    int t = blockIdx.x;
    if (t >= g_nt) return;
    int h = blockIdx.y;
    int b = g_tb[t], n0 = g_ts[t], cnt = g_tc[t];
    __shared__ float Qs[64 * 64];   // Q^T  [a][i]
    __shared__ float KP[64 * 64];   // K^T [a][j], then P^T [j][i]
    __shared__ float Vs[64 * 64];   // V   [j][a]
    int tid = threadIdx.x, tx = tid & 15, ty = tid >> 4;
    int lr = tid >> 2, la = (tid & 3) * 16;

    // load Q tile transposed (zero-pad invalid rows); loaded ONCE per block
    #pragma unroll
    for (int q = 0; q < 4; q++) {
        float4 v = make_float4(0.f, 0.f, 0.f, 0.f);
        if (lr < cnt)
            v = *(const float4*)&g_q[(size_t)(n0 + lr) * HA + h * AA + la + q * 4];
        int a = la + q * 4;
        Qs[(a + 0) * 64 + lr] = v.x; Qs[(a + 1) * 64 + lr] = v.y;
        Qs[(a + 2) * 64 + lr] = v.z; Qs[(a + 3) * 64 + lr] = v.w;
    }

    float m[4], l[4], feat[4][4];
    #pragma unroll
    for (int r = 0; r < 4; r++) {
        m[r] = -FLT_MAX; l[r] = 0.f;
        #pragma unroll
        for (int c = 0; c < 4; c++) feat[r][c] = 0.f;
    }

    for (int s0 = 0; s0 < SS; s0 += 64) {
        __syncthreads();   // prior P consumption done before overwriting KP
        #pragma unroll
        for (int q = 0; q < 4; q++) {
            int a = la + q * 4;
            size_t rb = (size_t)((b << 10) + s0 + lr) * HA + h * AA + a;
            float4 kv = *(const float4*)&g_k[rb];
            KP[(a + 0) * 64 + lr] = kv.x; KP[(a + 1) * 64 + lr] = kv.y;
            KP[(a + 2) * 64 + lr] = kv.z; KP[(a + 3) * 64 + lr] = kv.w;
            *(float4*)&Vs[lr * 64 + a] = *(const float4*)&g_v[rb];
        }
        __syncthreads();

        // scores chunk: Sc = Q @ K^T / 8
        float sc[4][4] = {};
        #pragma unroll 8
        for (int a = 0; a < 64; a++) {
            float4 q4 = *(float4*)&Qs[a * 64 + ty * 4];
            float4 k4 = *(float4*)&KP[a * 64 + tx * 4];
            fma16(sc, q4, k4);
        }
        #pragma unroll
        for (int r = 0; r < 4; r++)
            #pragma unroll
            for (int c = 0; c < 4; c++) sc[r][c] *= 0.125f;

        // raw-score logits from heads 0,1 (exactly 2 adds/element, zeroed buffer)
        if (h < 2) {
            #pragma unroll
            for (int r = 0; r < 4; r++) {
                int i = ty * 4 + r;
                if (i < cnt) {
                    #pragma unroll
                    for (int c = 0; c < 4; c++)
                        atomicAdd(&logits[(size_t)(n0 + i) * SS + s0 + tx * 4 + c],
                                  sc[r][c]);
                }
            }
        }

        // mask for this thread's 4 columns
        unsigned int mw = *(const unsigned int*)&g_mask[b * SS + s0 + tx * 4];
        float mk[4] = {(float)(mw & 255u), (float)((mw >> 8) & 255u),
                       (float)((mw >> 16) & 255u), (float)((mw >> 24) & 255u)};

        // online softmax update per row (16-lane shuffle groups == rows)
        #pragma unroll
        for (int r = 0; r < 4; r++) {
            float v = -FLT_MAX;
            #pragma unroll
            for (int c = 0; c < 4; c++)
                v = fmaxf(v, mk[c] > 0.f ? sc[r][c] : -FLT_MAX);
            #pragma unroll
            for (int d = 8; d; d >>= 1)
                v = fmaxf(v, __shfl_xor_sync(0xffffffffu, v, d, 16));
            float mn = fmaxf(m[r], v);
            float alpha = __expf(m[r] - mn);
            float sum = 0.f;
            #pragma unroll
            for (int c = 0; c < 4; c++) {
                float p = mk[c] > 0.f ? __expf(sc[r][c] - mn) : 0.f;
                sc[r][c] = p; sum += p;
            }
            #pragma unroll
            for (int d = 8; d; d >>= 1)
                sum += __shfl_xor_sync(0xffffffffu, sum, d, 16);
            l[r] = l[r] * alpha + sum;
            m[r] = mn;
            #pragma unroll
            for (int c = 0; c < 4; c++) feat[r][c] *= alpha;
        }

        // stage P^T into KP (reuse), then feat += P @ V
        __syncthreads();
        #pragma unroll
        for (int r = 0; r < 4; r++)
            #pragma unroll
            for (int c = 0; c < 4; c++)
                KP[(tx * 4 + c) * 64 + ty * 4 + r] = sc[r][c];
        __syncthreads();
        #pragma unroll 8
        for (int j = 0; j < 64; j++) {
            float4 p4 = *(float4*)&KP[j * 64 + ty * 4];
            float4 v4 = *(float4*)&Vs[j * 64 + tx * 4];
            fma16(feat, p4, v4);
        }
    }

    // epilogue: normalize (sum + 1e-9), apply gate, store
    #pragma unroll
    for (int r = 0; r < 4; r++) {
        int i = ty * 4 + r;
        if (i >= cnt) continue;
        float inv = 1.f / (l[r] + 1e-9f);
        size_t base = (size_t)(n0 + i) * HA + h * AA + tx * 4;
        float4 g = *(const float4*)&g_gate[base];
        float4 o;
        o.x = feat[r][0] * inv * g.x; o.y = feat[r][1] * inv * g.y;
        o.z = feat[r][2] * inv * g.z; o.w = feat[r][3] * inv * g.w;
        *(float4*)&g_feat[base] = o;
    }
}

// ---------------- y = sqrt(2)*x + gatedfeat @ Wback + bback ----------------
__global__ void __launch_bounds__(256) back_k(const float* __restrict__ x,
                                              const float* __restrict__ Wback,
                                              const float* __restrict__ bback) {
    __shared__ float As[16][68];
    __shared__ float Bs[16][64];
    int tid = threadIdx.x, tx = tid & 15, ty = tid >> 4;
    int m0 = blockIdx.x * 64, n0 = blockIdx.y * 64;
    float acc[4][4] = {};
    int lm = tid >> 2, lk = (tid & 3) * 4;
    int bk = tid >> 4, bn = (tid & 15) * 4;
    for (int k0 = 0; k0 < HA; k0 += 16) {
        float4 a = *(const float4*)&g_feat[(size_t)(m0 + lm) * HA + k0 + lk];
        As[lk + 0][lm] = a.x; As[lk + 1][lm] = a.y; As[lk + 2][lm] = a.z; As[lk + 3][lm] = a.w;
        *(float4*)&Bs[bk][bn] = *(const float4*)&Wback[(size_t)(k0 + bk) * IFZ + n0 + bn];
        __syncthreads();
        #pragma unroll
        for (int kk = 0; kk < 16; kk++) {
            float4 a4 = *(float4*)&As[kk][ty * 4];
            float4 b4 = *(float4*)&Bs[kk][tx * 4];
            fma16(acc, a4, b4);
        }
        __syncthreads();
    }
    const float rt2 = 1.41421356237309515f;
    float4 bb = *(const float4*)&bback[n0 + tx * 4];
    #pragma unroll
    for (int i = 0; i < 4; i++) {
        int row = m0 + ty * 4 + i;
        float4 xv = *(const float4*)&x[(size_t)row * IFZ + n0 + tx * 4];
        float4 o;
        o.x = rt2 * xv.x + acc[i][0] + bb.x;
        o.y = rt2 * xv.y + acc[i][1] + bb.y;
        o.z = rt2 * xv.z + acc[i][2] + bb.z;
        o.w = rt2 * xv.w + acc[i][3] + bb.w;
        *(float4*)&g_y[(size_t)row * IFZ + n0 + tx * 4] = o;
    }
}

// ---------------- LayerNorm: warp per row ----------------------------------
__global__ void __launch_bounds__(256) ln_k(const float* __restrict__ gamma,
                                            const float* __restrict__ beta,
                                            float* __restrict__ out) {
    int warp = threadIdx.x >> 5, lane = threadIdx.x & 31;
    int row = blockIdx.x * 8 + warp;
    float4 v0 = *(const float4*)&g_y[(size_t)row * IFZ + lane * 4];
    float4 v1 = *(const float4*)&g_y[(size_t)row * IFZ + 128 + lane * 4];
    float s = v0.x + v0.y + v0.z + v0.w + v1.x + v1.y + v1.z + v1.w;
    #pragma unroll
    for (int d = 16; d; d >>= 1) s += __shfl_xor_sync(0xffffffffu, s, d);
    float mu = s * (1.f / 256.f);
    float q = 0.f;
    q += (v0.x - mu) * (v0.x - mu); q += (v0.y - mu) * (v0.y - mu);
    q += (v0.z - mu) * (v0.z - mu); q += (v0.w - mu) * (v0.w - mu);
    q += (v1.x - mu) * (v1.x - mu); q += (v1.y - mu) * (v1.y - mu);
    q += (v1.z - mu) * (v1.z - mu); q += (v1.w - mu) * (v1.w - mu);
    #pragma unroll
    for (int d = 16; d; d >>= 1) q += __shfl_xor_sync(0xffffffffu, q, d);
    float inv = rsqrtf(q * (1.f / 256.f) + 1e-5f);
    float4 g0 = *(const float4*)&gamma[lane * 4];
    float4 b0 = *(const float4*)&beta[lane * 4];
    float4 g1 = *(const float4*)&gamma[128 + lane * 4];
    float4 b1 = *(const float4*)&beta[128 + lane * 4];
    float4 o0, o1;
    o0.x = (v0.x - mu) * inv * g0.x + b0.x;
    o0.y = (v0.y - mu) * inv * g0.y + b0.y;
    o0.z = (v0.z - mu) * inv * g0.z + b0.z;
    o0.w = (v0.w - mu) * inv * g0.w + b0.w;
    o1.x = (v1.x - mu) * inv * g1.x + b1.x;
    o1.y = (v1.y - mu) * inv * g1.y + b1.y;
    o1.z = (v1.z - mu) * inv * g1.z + b1.z;
    o1.w = (v1.w - mu) * inv * g1.w + b1.w;
    *(float4*)&out[(size_t)row * IFZ + lane * 4] = o0;
    *(float4*)&out[(size_t)row * IFZ + 128 + lane * 4] = o1;
}

// ---------------- launch ---------------------------------------------------
extern "C" void kernel_launch(void* const* d_in, const int* in_sizes, int n_in,
                              void* d_out, int out_size) {
    const float* x     = (const float*)d_in[0];
    const float* emb   = (const float*)d_in[1];
    const void*  mask  = d_in[2];
    const void*  batch = d_in[3];
    const float* Wq    = (const float*)d_in[4];
    const float* Wk    = (const float*)d_in[5];
    const float* Wv    = (const float*)d_in[6];
    const float* Wg    = (const float*)d_in[7];
    const float* bg    = (const float*)d_in[8];
    const float* Wback = (const float*)d_in[9];
    const float* bback = (const float*)d_in[10];
    const float* gamma = (const float*)d_in[11];
    const float* beta  = (const float*)d_in[12];
    float* out    = (float*)d_out;
    float* logits = out + (size_t)NN * IFZ;

    cudaMemsetAsync(logits, 0, (size_t)NN * SS * sizeof(float), 0);
    prep_k<<<1, 256>>>(mask, batch);
    proj_qg_k<<<dim3(32, 16), 256>>>(x, Wq, Wg, bg);
    proj_kv_k<<<dim3(64, 16), 256>>>(emb, Wk, Wv);
    attn_k<<<dim3(MAXT, HH), 256>>>(logits);
    back_k<<<dim3(32, 4), 256>>>(x, Wback, bback);
    ln_k<<<256, 256>>>(gamma, beta, out);
}

// round 4
// speedup vs baseline: 1.0244x; 1.0244x over previous
#include <cuda_runtime.h>
#include <float.h>
#include <math.h>

#define NN   2048
#define BBATCH 4
#define SS   1024
#define SFZ  384
#define IFZ  256
#define HH   8
#define AA   64
#define HA   512
#define MAXT 36

typedef unsigned long long ull;

__device__ float g_q[NN * HA];
__device__ float g_gate[NN * HA];
__device__ float g_k[BBATCH * SS * HA];
__device__ float g_v[BBATCH * SS * HA];
__device__ float g_feat[NN * HA];
__device__ float g_y[NN * IFZ];
__device__ unsigned char g_mask[BBATCH * SS];
__device__ int g_tb[MAXT], g_ts[MAXT], g_tc[MAXT], g_nt;

// ---- packed f32x2 helpers (bit-identical fp32 FMA, 2x throughput) ----
__device__ __forceinline__ void ffma2(ull &d, ull a, ull b) {
    asm("fma.rn.f32x2 %0, %1, %2, %0;" : "+l"(d) : "l"(a), "l"(b));
}
__device__ __forceinline__ ull pk2(float lo, float hi) {
    ull r; asm("mov.b64 %0, {%1, %2};" : "=l"(r) : "f"(lo), "f"(hi)); return r;
}
__device__ __forceinline__ float2 upk2(ull v) {
    float2 r; asm("mov.b64 {%0, %1}, %2;" : "=f"(r.x), "=f"(r.y) : "l"(v)); return r;
}
// 4 rows x 4 cols via 8 FFMA2; b points at 4 contiguous smem floats (16B aligned)
__device__ __forceinline__ void fma8x2(ull (&acc)[4][2], float4 a, const float* bp) {
    ull b0 = *(const ull*)bp, b1 = *(const ull*)(bp + 2);
    ull a0 = pk2(a.x, a.x), a1 = pk2(a.y, a.y), a2 = pk2(a.z, a.z), a3 = pk2(a.w, a.w);
    ffma2(acc[0][0], a0, b0); ffma2(acc[0][1], a0, b1);
    ffma2(acc[1][0], a1, b0); ffma2(acc[1][1], a1, b1);
    ffma2(acc[2][0], a2, b0); ffma2(acc[2][1], a2, b1);
    ffma2(acc[3][0], a3, b0); ffma2(acc[3][1], a3, b1);
}
__device__ __forceinline__ float4 row4(ull p0, ull p1) {
    float2 a = upk2(p0), b = upk2(p1);
    return make_float4(a.x, a.y, b.x, b.y);
}

// ---------------- prep: dtype canonicalization + node tiles ----------------
__global__ void prep_k(const void* mask_in, const void* batch_in) {
    __shared__ int flg[2];
    __shared__ int cnt[BBATCH];
    int tid = threadIdx.x;
    if (tid < 2) flg[tid] = 0;
    if (tid < BBATCH) cnt[tid] = 0;
    __syncthreads();
    const unsigned int* bw = (const unsigned int*)batch_in;
    unsigned int o = 0;
    for (int i = tid * 2 + 1; i < NN; i += blockDim.x * 2) o |= bw[i];
    if (o) atomicOr(&flg[0], 1);
    const unsigned char* mb = (const unsigned char*)mask_in;
    int f = 0;
    for (int i = tid; i < BBATCH * SS; i += blockDim.x)
        if ((i & 3) && mb[i]) f = 1;
    if (f) atomicOr(&flg[1], 1);
    __syncthreads();
    int is32 = flg[0], isb = flg[1];
    int lc[BBATCH] = {0, 0, 0, 0};
    for (int i = tid; i < NN; i += blockDim.x) {
        int v = is32 ? ((const int*)batch_in)[i]
                     : (int)((const long long*)batch_in)[i];
        lc[v & 3]++;
    }
    #pragma unroll
    for (int b = 0; b < BBATCH; b++) if (lc[b]) atomicAdd(&cnt[b], lc[b]);
    for (int i = tid; i < BBATCH * SS; i += blockDim.x)
        g_mask[i] = isb ? (mb[i] ? 1 : 0) : (((const int*)mask_in)[i] ? 1 : 0);
    __syncthreads();
    if (tid == 0) {
        int st = 0, t = 0;
        for (int b = 0; b < BBATCH; b++) {
            int e = st + cnt[b];
            for (int s = st; s < e; s += 64) {
                g_tb[t] = b; g_ts[t] = s; g_tc[t] = min(64, e - s); t++;
            }
            st = e;
        }
        g_nt = t;
    }
}

// ---------------- q = x@Wq ; gate = sigmoid(x@Wg + bg) ---------------------
__global__ void __launch_bounds__(256) proj_qg_k(const float* __restrict__ x,
                                                 const float* __restrict__ Wq,
                                                 const float* __restrict__ Wg,
                                                 const float* __restrict__ bg) {
    __shared__ float As[16][68];
    __shared__ float Bs[16][64];
    int tid = threadIdx.x, tx = tid & 15, ty = tid >> 4;
    int m0 = blockIdx.x * 64, n0 = blockIdx.y * 64;
    bool isg = (n0 >= HA);
    const float* W = isg ? Wg : Wq;
    int nc0 = isg ? (n0 - HA) : n0;
    ull acc[4][2] = {};
    int lm = tid >> 2, lk = (tid & 3) * 4;
    int bk = tid >> 4, bn = (tid & 15) * 4;
    for (int k0 = 0; k0 < IFZ; k0 += 16) {
        float4 a = *(const float4*)(x + (size_t)(m0 + lm) * IFZ + k0 + lk);
        As[lk + 0][lm] = a.x; As[lk + 1][lm] = a.y; As[lk + 2][lm] = a.z; As[lk + 3][lm] = a.w;
        *(float4*)&Bs[bk][bn] = *(const float4*)(W + (size_t)(k0 + bk) * HA + nc0 + bn);
        __syncthreads();
        #pragma unroll
        for (int kk = 0; kk < 16; kk++)
            fma8x2(acc, *(float4*)&As[kk][ty * 4], &Bs[kk][tx * 4]);
        __syncthreads();
    }
    if (isg) {
        float4 bgv = *(const float4*)(bg + nc0 + tx * 4);
        #pragma unroll
        for (int i = 0; i < 4; i++) {
            int row = m0 + ty * 4 + i;
            float4 c = row4(acc[i][0], acc[i][1]);
            float4 ov;
            ov.x = 1.0f / (1.0f + __expf(-(c.x + bgv.x)));
            ov.y = 1.0f / (1.0f + __expf(-(c.y + bgv.y)));
            ov.z = 1.0f / (1.0f + __expf(-(c.z + bgv.z)));
            ov.w = 1.0f / (1.0f + __expf(-(c.w + bgv.w)));
            *(float4*)&g_gate[(size_t)row * HA + nc0 + tx * 4] = ov;
        }
    } else {
        #pragma unroll
        for (int i = 0; i < 4; i++) {
            int row = m0 + ty * 4 + i;
            *(float4*)&g_q[(size_t)row * HA + nc0 + tx * 4] = row4(acc[i][0], acc[i][1]);
        }
    }
}

// ---------------- k = emb@Wk ; v = emb@Wv ----------------------------------
__global__ void __launch_bounds__(256) proj_kv_k(const float* __restrict__ emb,
                                                 const float* __restrict__ Wk,
                                                 const float* __restrict__ Wv) {
    __shared__ float As[16][68];
    __shared__ float Bs[16][64];
    int tid = threadIdx.x, tx = tid & 15, ty = tid >> 4;
    int m0 = blockIdx.x * 64, n0 = blockIdx.y * 64;
    bool isv = (n0 >= HA);
    const float* W = isv ? Wv : Wk;
    float* Cout = isv ? g_v : g_k;
    int nc0 = isv ? (n0 - HA) : n0;
    ull acc[4][2] = {};
    int lm = tid >> 2, lk = (tid & 3) * 4;
    int bk = tid >> 4, bn = (tid & 15) * 4;
    for (int k0 = 0; k0 < SFZ; k0 += 16) {
        float4 a = *(const float4*)(emb + (size_t)(m0 + lm) * SFZ + k0 + lk);
        As[lk + 0][lm] = a.x; As[lk + 1][lm] = a.y; As[lk + 2][lm] = a.z; As[lk + 3][lm] = a.w;
        *(float4*)&Bs[bk][bn] = *(const float4*)(W + (size_t)(k0 + bk) * HA + nc0 + bn);
        __syncthreads();
        #pragma unroll
        for (int kk = 0; kk < 16; kk++)
            fma8x2(acc, *(float4*)&As[kk][ty * 4], &Bs[kk][tx * 4]);
        __syncthreads();
    }
    #pragma unroll
    for (int i = 0; i < 4; i++) {
        int row = m0 + ty * 4 + i;
        *(float4*)&Cout[(size_t)row * HA + nc0 + tx * 4] = row4(acc[i][0], acc[i][1]);
    }
}

// ---------------- attention: flash masked softmax + gated feature ----------
__global__ void __launch_bounds__(256) attn_k(float* __restrict__ logits) {
    int t = blockIdx.x;
    if (t >= g_nt) return;
    int h = blockIdx.y;
    int b = g_tb[t], n0 = g_ts[t], cnt = g_tc[t];
    __shared__ float Qs[64 * 64];   // Q^T [a][i]
    __shared__ float KP[64 * 64];   // K^T [a][j], then P^T [j][i]
    __shared__ float Vs[64 * 64];   // V   [j][a]
    int tid = threadIdx.x, tx = tid & 15, ty = tid >> 4;
    int lr = tid >> 2, la = (tid & 3) * 16;

    #pragma unroll
    for (int q = 0; q < 4; q++) {
        float4 v = make_float4(0.f, 0.f, 0.f, 0.f);
        if (lr < cnt)
            v = *(const float4*)&g_q[(size_t)(n0 + lr) * HA + h * AA + la + q * 4];
        int a = la + q * 4;
        Qs[(a + 0) * 64 + lr] = v.x; Qs[(a + 1) * 64 + lr] = v.y;
        Qs[(a + 2) * 64 + lr] = v.z; Qs[(a + 3) * 64 + lr] = v.w;
    }

    float m[4], l[4];
    ull feat[4][2] = {};
    #pragma unroll
    for (int r = 0; r < 4; r++) { m[r] = -FLT_MAX; l[r] = 0.f; }

    for (int s0 = 0; s0 < SS; s0 += 64) {
        __syncthreads();
        #pragma unroll
        for (int q = 0; q < 4; q++) {
            int a = la + q * 4;
            size_t rb = (size_t)((b << 10) + s0 + lr) * HA + h * AA + a;
            float4 kv = *(const float4*)&g_k[rb];
            KP[(a + 0) * 64 + lr] = kv.x; KP[(a + 1) * 64 + lr] = kv.y;
            KP[(a + 2) * 64 + lr] = kv.z; KP[(a + 3) * 64 + lr] = kv.w;
            *(float4*)&Vs[lr * 64 + a] = *(const float4*)&g_v[rb];
        }
        __syncthreads();

        // Sc = Q @ K^T / 8  (packed FFMA2)
        ull acc[4][2] = {};
        #pragma unroll 8
        for (int a = 0; a < 64; a++)
            fma8x2(acc, *(float4*)&Qs[a * 64 + ty * 4], &KP[a * 64 + tx * 4]);
        float sc[4][4];
        #pragma unroll
        for (int r = 0; r < 4; r++) {
            float4 c = row4(acc[r][0], acc[r][1]);
            sc[r][0] = c.x * 0.125f; sc[r][1] = c.y * 0.125f;
            sc[r][2] = c.z * 0.125f; sc[r][3] = c.w * 0.125f;
        }

        if (h < 2) {
            #pragma unroll
            for (int r = 0; r < 4; r++) {
                int i = ty * 4 + r;
                if (i < cnt) {
                    #pragma unroll
                    for (int c = 0; c < 4; c++)
                        atomicAdd(&logits[(size_t)(n0 + i) * SS + s0 + tx * 4 + c],
                                  sc[r][c]);
                }
            }
        }

        unsigned int mw = *(const unsigned int*)&g_mask[b * SS + s0 + tx * 4];
        float mk[4] = {(float)(mw & 255u), (float)((mw >> 8) & 255u),
                       (float)((mw >> 16) & 255u), (float)((mw >> 24) & 255u)};

        #pragma unroll
        for (int r = 0; r < 4; r++) {
            float v = -FLT_MAX;
            #pragma unroll
            for (int c = 0; c < 4; c++)
                v = fmaxf(v, mk[c] > 0.f ? sc[r][c] : -FLT_MAX);
            #pragma unroll
            for (int d = 8; d; d >>= 1)
                v = fmaxf(v, __shfl_xor_sync(0xffffffffu, v, d, 16));
            float mn = fmaxf(m[r], v);
            float alpha = __expf(m[r] - mn);
            float sum = 0.f;
            #pragma unroll
            for (int c = 0; c < 4; c++) {
                float p = mk[c] > 0.f ? __expf(sc[r][c] - mn) : 0.f;
                sc[r][c] = p; sum += p;
            }
            #pragma unroll
            for (int d = 8; d; d >>= 1)
                sum += __shfl_xor_sync(0xffffffffu, sum, d, 16);
            l[r] = l[r] * alpha + sum;
            m[r] = mn;
            ull al = pk2(alpha, alpha);
            asm("mul.rn.f32x2 %0, %0, %1;" : "+l"(feat[r][0]) : "l"(al));
            asm("mul.rn.f32x2 %0, %0, %1;" : "+l"(feat[r][1]) : "l"(al));
        }

        __syncthreads();
        #pragma unroll
        for (int r = 0; r < 4; r++)
            #pragma unroll
            for (int c = 0; c < 4; c++)
                KP[(tx * 4 + c) * 64 + ty * 4 + r] = sc[r][c];
        __syncthreads();
        #pragma unroll 8
        for (int j = 0; j < 64; j++)
            fma8x2(feat, *(float4*)&KP[j * 64 + ty * 4], &Vs[j * 64 + tx * 4]);
    }

    #pragma unroll
    for (int r = 0; r < 4; r++) {
        int i = ty * 4 + r;
        if (i >= cnt) continue;
        float inv = 1.f / (l[r] + 1e-9f);
        size_t base = (size_t)(n0 + i) * HA + h * AA + tx * 4;
        float4 g = *(const float4*)&g_gate[base];
        float4 fv = row4(feat[r][0], feat[r][1]);
        float4 ov;
        ov.x = fv.x * inv * g.x; ov.y = fv.y * inv * g.y;
        ov.z = fv.z * inv * g.z; ov.w = fv.w * inv * g.w;
        *(float4*)&g_feat[base] = ov;
    }
}

// ---------------- y = sqrt(2)*x + gatedfeat @ Wback + bback ----------------
__global__ void __launch_bounds__(256) back_k(const float* __restrict__ x,
                                              const float* __restrict__ Wback,
                                              const float* __restrict__ bback) {
    __shared__ float As[16][68];
    __shared__ float Bs[16][64];
    int tid = threadIdx.x, tx = tid & 15, ty = tid >> 4;
    int m0 = blockIdx.x * 64, n0 = blockIdx.y * 64;
    ull acc[4][2] = {};
    int lm = tid >> 2, lk = (tid & 3) * 4;
    int bk = tid >> 4, bn = (tid & 15) * 4;
    for (int k0 = 0; k0 < HA; k0 += 16) {
        float4 a = *(const float4*)&g_feat[(size_t)(m0 + lm) * HA + k0 + lk];
        As[lk + 0][lm] = a.x; As[lk + 1][lm] = a.y; As[lk + 2][lm] = a.z; As[lk + 3][lm] = a.w;
        *(float4*)&Bs[bk][bn] = *(const float4*)&Wback[(size_t)(k0 + bk) * IFZ + n0 + bn];
        __syncthreads();
        #pragma unroll
        for (int kk = 0; kk < 16; kk++)
            fma8x2(acc, *(float4*)&As[kk][ty * 4], &Bs[kk][tx * 4]);
        __syncthreads();
    }
    const float rt2 = 1.41421356237309515f;
    float4 bb = *(const float4*)&bback[n0 + tx * 4];
    #pragma unroll
    for (int i = 0; i < 4; i++) {
        int row = m0 + ty * 4 + i;
        float4 xv = *(const float4*)&x[(size_t)row * IFZ + n0 + tx * 4];
        float4 c = row4(acc[i][0], acc[i][1]);
        float4 ov;
        ov.x = rt2 * xv.x + c.x + bb.x;
        ov.y = rt2 * xv.y + c.y + bb.y;
        ov.z = rt2 * xv.z + c.z + bb.z;
        ov.w = rt2 * xv.w + c.w + bb.w;
        *(float4*)&g_y[(size_t)row * IFZ + n0 + tx * 4] = ov;
    }
}

// ---------------- LayerNorm: warp per row ----------------------------------
__global__ void __launch_bounds__(256) ln_k(const float* __restrict__ gamma,
                                            const float* __restrict__ beta,
                                            float* __restrict__ out) {
    int warp = threadIdx.x >> 5, lane = threadIdx.x & 31;
    int row = blockIdx.x * 8 + warp;
    float4 v0 = *(const float4*)&g_y[(size_t)row * IFZ + lane * 4];
    float4 v1 = *(const float4*)&g_y[(size_t)row * IFZ + 128 + lane * 4];
    float s = v0.x + v0.y + v0.z + v0.w + v1.x + v1.y + v1.z + v1.w;
    #pragma unroll
    for (int d = 16; d; d >>= 1) s += __shfl_xor_sync(0xffffffffu, s, d);
    float mu = s * (1.f / 256.f);
    float q = 0.f;
    q += (v0.x - mu) * (v0.x - mu); q += (v0.y - mu) * (v0.y - mu);
    q += (v0.z - mu) * (v0.z - mu); q += (v0.w - mu) * (v0.w - mu);
    q += (v1.x - mu) * (v1.x - mu); q += (v1.y - mu) * (v1.y - mu);
    q += (v1.z - mu) * (v1.z - mu); q += (v1.w - mu) * (v1.w - mu);
    #pragma unroll
    for (int d = 16; d; d >>= 1) q += __shfl_xor_sync(0xffffffffu, q, d);
    float inv = rsqrtf(q * (1.f / 256.f) + 1e-5f);
    float4 g0 = *(const float4*)&gamma[lane * 4];
    float4 b0 = *(const float4*)&beta[lane * 4];
    float4 g1 = *(const float4*)&gamma[128 + lane * 4];
    float4 b1 = *(const float4*)&beta[128 + lane * 4];
    float4 o0, o1;
    o0.x = (v0.x - mu) * inv * g0.x + b0.x;
    o0.y = (v0.y - mu) * inv * g0.y + b0.y;
    o0.z = (v0.z - mu) * inv * g0.z + b0.z;
    o0.w = (v0.w - mu) * inv * g0.w + b0.w;
    o1.x = (v1.x - mu) * inv * g1.x + b1.x;
    o1.y = (v1.y - mu) * inv * g1.y + b1.y;
    o1.z = (v1.z - mu) * inv * g1.z + b1.z;
    o1.w = (v1.w - mu) * inv * g1.w + b1.w;
    *(float4*)&out[(size_t)row * IFZ + lane * 4] = o0;
    *(float4*)&out[(size_t)row * IFZ + 128 + lane * 4] = o1;
}

// ---------------- launch ---------------------------------------------------
extern "C" void kernel_launch(void* const* d_in, const int* in_sizes, int n_in,
                              void* d_out, int out_size) {
    const float* x     = (const float*)d_in[0];
    const float* emb   = (const float*)d_in[1];
    const void*  mask  = d_in[2];
    const void*  batch = d_in[3];
    const float* Wq    = (const float*)d_in[4];
    const float* Wk    = (const float*)d_in[5];
    const float* Wv    = (const float*)d_in[6];
    const float* Wg    = (const float*)d_in[7];
    const float* bg    = (const float*)d_in[8];
    const float* Wback = (const float*)d_in[9];
    const float* bback = (const float*)d_in[10];
    const float* gamma = (const float*)d_in[11];
    const float* beta  = (const float*)d_in[12];
    float* out    = (float*)d_out;
    float* logits = out + (size_t)NN * IFZ;

    cudaMemsetAsync(logits, 0, (size_t)NN * SS * sizeof(float), 0);
    prep_k<<<1, 256>>>(mask, batch);
    proj_qg_k<<<dim3(32, 16), 256>>>(x, Wq, Wg, bg);
    proj_kv_k<<<dim3(64, 16), 256>>>(emb, Wk, Wv);
    attn_k<<<dim3(MAXT, HH), 256>>>(logits);
    back_k<<<dim3(32, 4), 256>>>(x, Wback, bback);
    ln_k<<<256, 256>>>(gamma, beta, out);
}

// round 5
// speedup vs baseline: 1.1196x; 1.0930x over previous
#include <cuda_runtime.h>
#include <float.h>
#include <math.h>

#define NN   2048
#define BBATCH 4
#define SS   1024
#define SFZ  384
#define IFZ  256
#define HH   8
#define AA   64
#define HA   512
#define MAXT 36
// attn smem (floats): Qs 64x64, Ks(64x128)/Ps(128x68) alias, Vs 128x68
#define OFF_KS 4096
#define OFF_VS 12800
#define ATTN_SMEM ((16384 + 34816 + 34816))

typedef unsigned long long ull;

__device__ float g_q[NN * HA];
__device__ float g_gate[NN * HA];
__device__ float g_k[BBATCH * SS * HA];
__device__ float g_v[BBATCH * SS * HA];
__device__ float g_feat[NN * HA];
__device__ float g_y[NN * IFZ];
__device__ unsigned char g_mask[BBATCH * SS];
__device__ int g_tb[MAXT], g_ts[MAXT], g_tc[MAXT], g_nt;

// ---- packed f32x2 helpers ----
__device__ __forceinline__ void ffma2(ull &d, ull a, ull b) {
    asm("fma.rn.f32x2 %0, %1, %2, %0;" : "+l"(d) : "l"(a), "l"(b));
}
__device__ __forceinline__ ull pk2(float lo, float hi) {
    ull r; asm("mov.b64 %0, {%1, %2};" : "=l"(r) : "f"(lo), "f"(hi)); return r;
}
__device__ __forceinline__ float2 upk2(ull v) {
    float2 r; asm("mov.b64 {%0, %1}, %2;" : "=f"(r.x), "=f"(r.y) : "l"(v)); return r;
}
__device__ __forceinline__ void fma8x2(ull (&acc)[4][2], float4 a, const float* bp) {
    ull b0 = *(const ull*)bp, b1 = *(const ull*)(bp + 2);
    ull a0 = pk2(a.x, a.x), a1 = pk2(a.y, a.y), a2 = pk2(a.z, a.z), a3 = pk2(a.w, a.w);
    ffma2(acc[0][0], a0, b0); ffma2(acc[0][1], a0, b1);
    ffma2(acc[1][0], a1, b0); ffma2(acc[1][1], a1, b1);
    ffma2(acc[2][0], a2, b0); ffma2(acc[2][1], a2, b1);
    ffma2(acc[3][0], a3, b0); ffma2(acc[3][1], a3, b1);
}
__device__ __forceinline__ float4 row4(ull p0, ull p1) {
    float2 a = upk2(p0), b = upk2(p1);
    return make_float4(a.x, a.y, b.x, b.y);
}

// ---------------- prep ------------------------------------------------------
__global__ void prep_k(const void* mask_in, const void* batch_in) {
    __shared__ int flg[2];
    __shared__ int cnt[BBATCH];
    int tid = threadIdx.x;
    if (tid < 2) flg[tid] = 0;
    if (tid < BBATCH) cnt[tid] = 0;
    __syncthreads();
    const unsigned int* bw = (const unsigned int*)batch_in;
    unsigned int o = 0;
    for (int i = tid * 2 + 1; i < NN; i += blockDim.x * 2) o |= bw[i];
    if (o) atomicOr(&flg[0], 1);
    const unsigned char* mb = (const unsigned char*)mask_in;
    int f = 0;
    for (int i = tid; i < BBATCH * SS; i += blockDim.x)
        if ((i & 3) && mb[i]) f = 1;
    if (f) atomicOr(&flg[1], 1);
    __syncthreads();
    int is32 = flg[0], isb = flg[1];
    int lc[BBATCH] = {0, 0, 0, 0};
    for (int i = tid; i < NN; i += blockDim.x) {
        int v = is32 ? ((const int*)batch_in)[i]
                     : (int)((const long long*)batch_in)[i];
        lc[v & 3]++;
    }
    #pragma unroll
    for (int b = 0; b < BBATCH; b++) if (lc[b]) atomicAdd(&cnt[b], lc[b]);
    for (int i = tid; i < BBATCH * SS; i += blockDim.x)
        g_mask[i] = isb ? (mb[i] ? 1 : 0) : (((const int*)mask_in)[i] ? 1 : 0);
    __syncthreads();
    if (tid == 0) {
        int st = 0, t = 0;
        for (int b = 0; b < BBATCH; b++) {
            int e = st + cnt[b];
            for (int s = st; s < e; s += 64) {
                g_tb[t] = b; g_ts[t] = s; g_tc[t] = min(64, e - s); t++;
            }
            st = e;
        }
        g_nt = t;
    }
}

// ---------------- q = x@Wq ; gate = sigmoid(x@Wg + bg) ---------------------
__global__ void __launch_bounds__(256) proj_qg_k(const float* __restrict__ x,
                                                 const float* __restrict__ Wq,
                                                 const float* __restrict__ Wg,
                                                 const float* __restrict__ bg) {
    __shared__ float As[16][68];
    __shared__ float Bs[16][64];
    int tid = threadIdx.x, tx = tid & 15, ty = tid >> 4;
    int m0 = blockIdx.x * 64, n0 = blockIdx.y * 64;
    bool isg = (n0 >= HA);
    const float* W = isg ? Wg : Wq;
    int nc0 = isg ? (n0 - HA) : n0;
    ull acc[4][2] = {};
    int lm = tid >> 2, lk = (tid & 3) * 4;
    int bk = tid >> 4, bn = (tid & 15) * 4;
    for (int k0 = 0; k0 < IFZ; k0 += 16) {
        float4 a = *(const float4*)(x + (size_t)(m0 + lm) * IFZ + k0 + lk);
        As[lk + 0][lm] = a.x; As[lk + 1][lm] = a.y; As[lk + 2][lm] = a.z; As[lk + 3][lm] = a.w;
        *(float4*)&Bs[bk][bn] = *(const float4*)(W + (size_t)(k0 + bk) * HA + nc0 + bn);
        __syncthreads();
        #pragma unroll
        for (int kk = 0; kk < 16; kk++)
            fma8x2(acc, *(float4*)&As[kk][ty * 4], &Bs[kk][tx * 4]);
        __syncthreads();
    }
    if (isg) {
        float4 bgv = *(const float4*)(bg + nc0 + tx * 4);
        #pragma unroll
        for (int i = 0; i < 4; i++) {
            int row = m0 + ty * 4 + i;
            float4 c = row4(acc[i][0], acc[i][1]);
            float4 ov;
            ov.x = 1.0f / (1.0f + __expf(-(c.x + bgv.x)));
            ov.y = 1.0f / (1.0f + __expf(-(c.y + bgv.y)));
            ov.z = 1.0f / (1.0f + __expf(-(c.z + bgv.z)));
            ov.w = 1.0f / (1.0f + __expf(-(c.w + bgv.w)));
            *(float4*)&g_gate[(size_t)row * HA + nc0 + tx * 4] = ov;
        }
    } else {
        #pragma unroll
        for (int i = 0; i < 4; i++) {
            int row = m0 + ty * 4 + i;
            *(float4*)&g_q[(size_t)row * HA + nc0 + tx * 4] = row4(acc[i][0], acc[i][1]);
        }
    }
}

// ---------------- k = emb@Wk ; v = emb@Wv ----------------------------------
__global__ void __launch_bounds__(256) proj_kv_k(const float* __restrict__ emb,
                                                 const float* __restrict__ Wk,
                                                 const float* __restrict__ Wv) {
    __shared__ float As[16][68];
    __shared__ float Bs[16][64];
    int tid = threadIdx.x, tx = tid & 15, ty = tid >> 4;
    int m0 = blockIdx.x * 64, n0 = blockIdx.y * 64;
    bool isv = (n0 >= HA);
    const float* W = isv ? Wv : Wk;
    float* Cout = isv ? g_v : g_k;
    int nc0 = isv ? (n0 - HA) : n0;
    ull acc[4][2] = {};
    int lm = tid >> 2, lk = (tid & 3) * 4;
    int bk = tid >> 4, bn = (tid & 15) * 4;
    for (int k0 = 0; k0 < SFZ; k0 += 16) {
        float4 a = *(const float4*)(emb + (size_t)(m0 + lm) * SFZ + k0 + lk);
        As[lk + 0][lm] = a.x; As[lk + 1][lm] = a.y; As[lk + 2][lm] = a.z; As[lk + 3][lm] = a.w;
        *(float4*)&Bs[bk][bn] = *(const float4*)(W + (size_t)(k0 + bk) * HA + nc0 + bn);
        __syncthreads();
        #pragma unroll
        for (int kk = 0; kk < 16; kk++)
            fma8x2(acc, *(float4*)&As[kk][ty * 4], &Bs[kk][tx * 4]);
        __syncthreads();
    }
    #pragma unroll
    for (int i = 0; i < 4; i++) {
        int row = m0 + ty * 4 + i;
        *(float4*)&Cout[(size_t)row * HA + nc0 + tx * 4] = row4(acc[i][0], acc[i][1]);
    }
}

// ---------------- attention: 128 thr, 64 nodes x 128-S chunks, 8x8/thread --
__global__ void __launch_bounds__(128) attn_k(float* __restrict__ logits) {
    extern __shared__ float sm[];
    float* Qs = sm;              // [a 64][i 64]
    float* Ks = sm + OFF_KS;     // [a 64][j 128]  (aliased by Ps [j 128][68])
    float* Ps = sm + OFF_KS;
    float* Vs = sm + OFF_VS;     // [j 128][68]
    int t = blockIdx.x;
    if (t >= g_nt) return;
    int h = blockIdx.y;
    int b = g_tb[t], n0 = g_ts[t], cnt = g_tc[t];
    int tid = threadIdx.x, tx = tid & 15, ty = tid >> 4;   // ty 0..7

    // ---- stage Q^T once: thread -> row i=tid>>1, a-half=(tid&1)*32
    {
        int i = tid >> 1, a0 = (tid & 1) * 32;
        const float* src = &g_q[(size_t)(n0 + i) * HA + h * AA + a0];
        #pragma unroll
        for (int p = 0; p < 8; p++) {
            float4 v = (i < cnt) ? *(const float4*)(src + p * 4)
                                 : make_float4(0.f, 0.f, 0.f, 0.f);
            int a = a0 + p * 4;
            Qs[(a + 0) * 64 + i] = v.x; Qs[(a + 1) * 64 + i] = v.y;
            Qs[(a + 2) * 64 + i] = v.z; Qs[(a + 3) * 64 + i] = v.w;
        }
    }

    float m_[8], l_[8];
    ull feat[8][2] = {};
    #pragma unroll
    for (int r = 0; r < 8; r++) { m_[r] = -FLT_MAX; l_[r] = 0.f; }

    for (int s0 = 0; s0 < SS; s0 += 128) {
        __syncthreads();   // prior PV reads of Ps/Vs done
        // ---- stage K^T [a][j] and V [j][a] ; thread owns j = tid
        {
            const float* kr = &g_k[(size_t)((b << 10) + s0 + tid) * HA + h * AA];
            const float* vr = &g_v[(size_t)((b << 10) + s0 + tid) * HA + h * AA];
            #pragma unroll
            for (int p = 0; p < 16; p++) {
                float4 kv = *(const float4*)(kr + p * 4);
                int a = p * 4;
                Ks[(a + 0) * 128 + tid] = kv.x; Ks[(a + 1) * 128 + tid] = kv.y;
                Ks[(a + 2) * 128 + tid] = kv.z; Ks[(a + 3) * 128 + tid] = kv.w;
                *(float4*)&Vs[tid * 68 + a] = *(const float4*)(vr + p * 4);
            }
        }
        __syncthreads();

        // ---- QK: sc[8 rows][8 cols], rows {ty*4+r,32+ty*4+r}, cols {tx*4+c,64+tx*4+c}
        ull acc[8][4] = {};
        #pragma unroll 8
        for (int a = 0; a < 64; a++) {
            float4 q0 = *(float4*)&Qs[a * 64 + ty * 4];
            float4 q1 = *(float4*)&Qs[a * 64 + 32 + ty * 4];
            ulonglong2 k0 = *(ulonglong2*)&Ks[a * 128 + tx * 4];
            ulonglong2 k1 = *(ulonglong2*)&Ks[a * 128 + 64 + tx * 4];
            ull qq[8] = {pk2(q0.x, q0.x), pk2(q0.y, q0.y), pk2(q0.z, q0.z), pk2(q0.w, q0.w),
                         pk2(q1.x, q1.x), pk2(q1.y, q1.y), pk2(q1.z, q1.z), pk2(q1.w, q1.w)};
            #pragma unroll
            for (int r = 0; r < 8; r++) {
                ffma2(acc[r][0], qq[r], k0.x); ffma2(acc[r][1], qq[r], k0.y);
                ffma2(acc[r][2], qq[r], k1.x); ffma2(acc[r][3], qq[r], k1.y);
            }
        }
        float sc[8][8];
        #pragma unroll
        for (int r = 0; r < 8; r++) {
            float4 cA = row4(acc[r][0], acc[r][1]);
            float4 cB = row4(acc[r][2], acc[r][3]);
            sc[r][0] = cA.x * 0.125f; sc[r][1] = cA.y * 0.125f;
            sc[r][2] = cA.z * 0.125f; sc[r][3] = cA.w * 0.125f;
            sc[r][4] = cB.x * 0.125f; sc[r][5] = cB.y * 0.125f;
            sc[r][6] = cB.z * 0.125f; sc[r][7] = cB.w * 0.125f;
        }

        // ---- logits (heads 0,1): raw scores
        if (h < 2) {
            #pragma unroll
            for (int r = 0; r < 8; r++) {
                int i = (r < 4) ? (ty * 4 + r) : (32 + ty * 4 + r - 4);
                if (i < cnt) {
                    float* lp = &logits[(size_t)(n0 + i) * SS + s0];
                    #pragma unroll
                    for (int c = 0; c < 8; c++) {
                        int j = (c < 4) ? (tx * 4 + c) : (64 + tx * 4 + c - 4);
                        atomicAdd(lp + j, sc[r][c]);
                    }
                }
            }
        }

        // ---- mask for this thread's 8 cols
        unsigned int mw0 = *(const unsigned int*)&g_mask[b * SS + s0 + tx * 4];
        unsigned int mw1 = *(const unsigned int*)&g_mask[b * SS + s0 + 64 + tx * 4];
        float mk[8];
        mk[0] = (float)(mw0 & 255u); mk[1] = (float)((mw0 >> 8) & 255u);
        mk[2] = (float)((mw0 >> 16) & 255u); mk[3] = (float)(mw0 >> 24);
        mk[4] = (float)(mw1 & 255u); mk[5] = (float)((mw1 >> 8) & 255u);
        mk[6] = (float)((mw1 >> 16) & 255u); mk[7] = (float)(mw1 >> 24);

        // ---- online softmax (row group = 16 lanes)
        #pragma unroll
        for (int r = 0; r < 8; r++) {
            float v = -FLT_MAX;
            #pragma unroll
            for (int c = 0; c < 8; c++)
                v = fmaxf(v, mk[c] > 0.f ? sc[r][c] : -FLT_MAX);
            #pragma unroll
            for (int d = 8; d; d >>= 1)
                v = fmaxf(v, __shfl_xor_sync(0xffffffffu, v, d, 16));
            float mn = fmaxf(m_[r], v);
            float alpha = __expf(m_[r] - mn);
            float sum = 0.f;
            #pragma unroll
            for (int c = 0; c < 8; c++) {
                float p = mk[c] > 0.f ? __expf(sc[r][c] - mn) : 0.f;
                sc[r][c] = p; sum += p;
            }
            #pragma unroll
            for (int d = 8; d; d >>= 1)
                sum += __shfl_xor_sync(0xffffffffu, sum, d, 16);
            l_[r] = l_[r] * alpha + sum;
            m_[r] = mn;
            ull al = pk2(alpha, alpha);
            asm("mul.rn.f32x2 %0, %0, %1;" : "+l"(feat[r][0]) : "l"(al));
            asm("mul.rn.f32x2 %0, %0, %1;" : "+l"(feat[r][1]) : "l"(al));
        }

        // ---- stage P^T [j][i] (aliases Ks), then PV
        __syncthreads();
        #pragma unroll
        for (int c = 0; c < 8; c++) {
            int j = (c < 4) ? (tx * 4 + c) : (64 + tx * 4 + c - 4);
            *(float4*)&Ps[j * 68 + ty * 4] =
                make_float4(sc[0][c], sc[1][c], sc[2][c], sc[3][c]);
            *(float4*)&Ps[j * 68 + 32 + ty * 4] =
                make_float4(sc[4][c], sc[5][c], sc[6][c], sc[7][c]);
        }
        __syncthreads();
        #pragma unroll 8
        for (int j = 0; j < 128; j++) {
            float4 p0 = *(float4*)&Ps[j * 68 + ty * 4];
            float4 p1 = *(float4*)&Ps[j * 68 + 32 + ty * 4];
            ulonglong2 vv = *(ulonglong2*)&Vs[j * 68 + tx * 4];
            ull pp[8] = {pk2(p0.x, p0.x), pk2(p0.y, p0.y), pk2(p0.z, p0.z), pk2(p0.w, p0.w),
                         pk2(p1.x, p1.x), pk2(p1.y, p1.y), pk2(p1.z, p1.z), pk2(p1.w, p1.w)};
            #pragma unroll
            for (int r = 0; r < 8; r++) {
                ffma2(feat[r][0], pp[r], vv.x); ffma2(feat[r][1], pp[r], vv.y);
            }
        }
    }

    // ---- epilogue: normalize, gate, store
    #pragma unroll
    for (int r = 0; r < 8; r++) {
        int i = (r < 4) ? (ty * 4 + r) : (32 + ty * 4 + r - 4);
        if (i >= cnt) continue;
        float inv = 1.f / (l_[r] + 1e-9f);
        size_t base = (size_t)(n0 + i) * HA + h * AA + tx * 4;
        float4 g = *(const float4*)&g_gate[base];
        float4 fv = row4(feat[r][0], feat[r][1]);
        float4 ov;
        ov.x = fv.x * inv * g.x; ov.y = fv.y * inv * g.y;
        ov.z = fv.z * inv * g.z; ov.w = fv.w * inv * g.w;
        *(float4*)&g_feat[base] = ov;
    }
}

// ---------------- y = sqrt(2)*x + gatedfeat @ Wback + bback ----------------
__global__ void __launch_bounds__(256) back_k(const float* __restrict__ x,
                                              const float* __restrict__ Wback,
                                              const float* __restrict__ bback) {
    __shared__ float As[16][68];
    __shared__ float Bs[16][64];
    int tid = threadIdx.x, tx = tid & 15, ty = tid >> 4;
    int m0 = blockIdx.x * 64, n0 = blockIdx.y * 64;
    ull acc[4][2] = {};
    int lm = tid >> 2, lk = (tid & 3) * 4;
    int bk = tid >> 4, bn = (tid & 15) * 4;
    for (int k0 = 0; k0 < HA; k0 += 16) {
        float4 a = *(const float4*)&g_feat[(size_t)(m0 + lm) * HA + k0 + lk];
        As[lk + 0][lm] = a.x; As[lk + 1][lm] = a.y; As[lk + 2][lm] = a.z; As[lk + 3][lm] = a.w;
        *(float4*)&Bs[bk][bn] = *(const float4*)&Wback[(size_t)(k0 + bk) * IFZ + n0 + bn];
        __syncthreads();
        #pragma unroll
        for (int kk = 0; kk < 16; kk++)
            fma8x2(acc, *(float4*)&As[kk][ty * 4], &Bs[kk][tx * 4]);
        __syncthreads();
    }
    const float rt2 = 1.41421356237309515f;
    float4 bb = *(const float4*)&bback[n0 + tx * 4];
    #pragma unroll
    for (int i = 0; i < 4; i++) {
        int row = m0 + ty * 4 + i;
        float4 xv = *(const float4*)&x[(size_t)row * IFZ + n0 + tx * 4];
        float4 c = row4(acc[i][0], acc[i][1]);
        float4 ov;
        ov.x = rt2 * xv.x + c.x + bb.x;
        ov.y = rt2 * xv.y + c.y + bb.y;
        ov.z = rt2 * xv.z + c.z + bb.z;
        ov.w = rt2 * xv.w + c.w + bb.w;
        *(float4*)&g_y[(size_t)row * IFZ + n0 + tx * 4] = ov;
    }
}

// ---------------- LayerNorm ------------------------------------------------
__global__ void __launch_bounds__(256) ln_k(const float* __restrict__ gamma,
                                            const float* __restrict__ beta,
                                            float* __restrict__ out) {
    int warp = threadIdx.x >> 5, lane = threadIdx.x & 31;
    int row = blockIdx.x * 8 + warp;
    float4 v0 = *(const float4*)&g_y[(size_t)row * IFZ + lane * 4];
    float4 v1 = *(const float4*)&g_y[(size_t)row * IFZ + 128 + lane * 4];
    float s = v0.x + v0.y + v0.z + v0.w + v1.x + v1.y + v1.z + v1.w;
    #pragma unroll
    for (int d = 16; d; d >>= 1) s += __shfl_xor_sync(0xffffffffu, s, d);
    float mu = s * (1.f / 256.f);
    float q = 0.f;
    q += (v0.x - mu) * (v0.x - mu); q += (v0.y - mu) * (v0.y - mu);
    q += (v0.z - mu) * (v0.z - mu); q += (v0.w - mu) * (v0.w - mu);
    q += (v1.x - mu) * (v1.x - mu); q += (v1.y - mu) * (v1.y - mu);
    q += (v1.z - mu) * (v1.z - mu); q += (v1.w - mu) * (v1.w - mu);
    #pragma unroll
    for (int d = 16; d; d >>= 1) q += __shfl_xor_sync(0xffffffffu, q, d);
    float inv = rsqrtf(q * (1.f / 256.f) + 1e-5f);
    float4 g0 = *(const float4*)&gamma[lane * 4];
    float4 b0 = *(const float4*)&beta[lane * 4];
    float4 g1 = *(const float4*)&gamma[128 + lane * 4];
    float4 b1 = *(const float4*)&beta[128 + lane * 4];
    float4 o0, o1;
    o0.x = (v0.x - mu) * inv * g0.x + b0.x;
    o0.y = (v0.y - mu) * inv * g0.y + b0.y;
    o0.z = (v0.z - mu) * inv * g0.z + b0.z;
    o0.w = (v0.w - mu) * inv * g0.w + b0.w;
    o1.x = (v1.x - mu) * inv * g1.x + b1.x;
    o1.y = (v1.y - mu) * inv * g1.y + b1.y;
    o1.z = (v1.z - mu) * inv * g1.z + b1.z;
    o1.w = (v1.w - mu) * inv * g1.w + b1.w;
    *(float4*)&out[(size_t)row * IFZ + lane * 4] = o0;
    *(float4*)&out[(size_t)row * IFZ + 128 + lane * 4] = o1;
}

// ---------------- launch ---------------------------------------------------
extern "C" void kernel_launch(void* const* d_in, const int* in_sizes, int n_in,
                              void* d_out, int out_size) {
    const float* x     = (const float*)d_in[0];
    const float* emb   = (const float*)d_in[1];
    const void*  mask  = d_in[2];
    const void*  batch = d_in[3];
    const float* Wq    = (const float*)d_in[4];
    const float* Wk    = (const float*)d_in[5];
    const float* Wv    = (const float*)d_in[6];
    const float* Wg    = (const float*)d_in[7];
    const float* bg    = (const float*)d_in[8];
    const float* Wback = (const float*)d_in[9];
    const float* bback = (const float*)d_in[10];
    const float* gamma = (const float*)d_in[11];
    const float* beta  = (const float*)d_in[12];
    float* out    = (float*)d_out;
    float* logits = out + (size_t)NN * IFZ;

    static int smem_set = 0;
    if (!smem_set) {
        cudaFuncSetAttribute(attn_k, cudaFuncAttributeMaxDynamicSharedMemorySize,
                             ATTN_SMEM * sizeof(float) / sizeof(float));
        smem_set = 1;
    }

    cudaMemsetAsync(logits, 0, (size_t)NN * SS * sizeof(float), 0);
    prep_k<<<1, 256>>>(mask, batch);
    proj_qg_k<<<dim3(32, 16), 256>>>(x, Wq, Wg, bg);
    proj_kv_k<<<dim3(64, 16), 256>>>(emb, Wk, Wv);
    attn_k<<<dim3(MAXT, HH), 128, ATTN_SMEM>>>(logits);
    back_k<<<dim3(32, 4), 256>>>(x, Wback, bback);
    ln_k<<<256, 256>>>(gamma, beta, out);
}

// round 9
// speedup vs baseline: 1.1520x; 1.0289x over previous
#include <cuda_runtime.h>
#include <cuda_bf16.h>
#include <float.h>
#include <math.h>

#define NN   2048
#define BBATCH 4
#define SS   1024
#define SFZ  384
#define IFZ  256
#define HH   8
#define AA   64
#define HA   512
#define MAXT 36

typedef unsigned long long ull;
typedef unsigned int u32;

__device__ __align__(16) float g_q[NN * HA];
__device__ __align__(16) float g_gate[NN * HA];
__device__ __align__(16) float g_k[BBATCH * SS * HA];
__device__ __align__(16) float g_v[BBATCH * SS * HA];
__device__ __align__(16) float g_feat[NN * HA];
__device__ __align__(16) float g_y[NN * IFZ];
__device__ __align__(16) unsigned char g_mask[BBATCH * SS];
__device__ int g_tb[MAXT], g_ts[MAXT], g_tc[MAXT], g_nt;
__device__ __align__(16) __nv_bfloat16 g_kh[BBATCH * SS * HA];
__device__ __align__(16) __nv_bfloat16 g_kl[BBATCH * SS * HA];
__device__ __align__(16) __nv_bfloat16 g_vh[BBATCH * HH * AA * SS];
__device__ __align__(16) __nv_bfloat16 g_vl[BBATCH * HH * AA * SS];
__device__ __align__(16) float g_sc0[NN * SS];
__device__ __align__(16) float g_sc1[NN * SS];

// ---- fp32 packed helpers (proj kernels) ----
__device__ __forceinline__ void ffma2(ull &d, ull a, ull b) {
    asm("fma.rn.f32x2 %0, %1, %2, %0;" : "+l"(d) : "l"(a), "l"(b));
}
__device__ __forceinline__ ull pk2(float lo, float hi) {
    ull r; asm("mov.b64 %0, {%1, %2};" : "=l"(r) : "f"(lo), "f"(hi)); return r;
}
__device__ __forceinline__ float2 upk2(ull v) {
    float2 r; asm("mov.b64 {%0, %1}, %2;" : "=f"(r.x), "=f"(r.y) : "l"(v)); return r;
}
__device__ __forceinline__ void fma8x2(ull (&acc)[4][2], float4 a, const float* bp) {
    ull b0 = *(const ull*)bp, b1 = *(const ull*)(bp + 2);
    ull a0 = pk2(a.x, a.x), a1 = pk2(a.y, a.y), a2 = pk2(a.z, a.z), a3 = pk2(a.w, a.w);
    ffma2(acc[0][0], a0, b0); ffma2(acc[0][1], a0, b1);
    ffma2(acc[1][0], a1, b0); ffma2(acc[1][1], a1, b1);
    ffma2(acc[2][0], a2, b0); ffma2(acc[2][1], a2, b1);
    ffma2(acc[3][0], a3, b0); ffma2(acc[3][1], a3, b1);
}
__device__ __forceinline__ float4 row4(ull p0, ull p1) {
    float2 a = upk2(p0), b = upk2(p1);
    return make_float4(a.x, a.y, b.x, b.y);
}

// ---- bf16 split helpers ----
__device__ __forceinline__ u32 pkbf(float a, float b) {
    __nv_bfloat162 t = __float22bfloat162_rn(make_float2(a, b));
    return *(u32*)&t;
}
__device__ __forceinline__ float2 unbf(u32 h) {
    return __bfloat1622float2(*(__nv_bfloat162*)&h);
}

// ---- legacy tensor core: ldmatrix + mma.sync (baseline PTX, sm_80+) ----
static __device__ __forceinline__ u32 s2u(const void* p) {
    u32 a; asm("{.reg .u64 t; cvta.to.shared.u64 t, %1; cvt.u32.u64 %0, t;}" : "=r"(a) : "l"(p));
    return a;
}
__device__ __forceinline__ void ldmx4(u32* r, u32 a) {
    asm volatile("ldmatrix.sync.aligned.m8n8.x4.shared.b16 {%0,%1,%2,%3},[%4];"
                 : "=r"(r[0]), "=r"(r[1]), "=r"(r[2]), "=r"(r[3]) : "r"(a));
}
__device__ __forceinline__ void ldmx2(u32* r, u32 a) {
    asm volatile("ldmatrix.sync.aligned.m8n8.x2.shared.b16 {%0,%1},[%2];"
                 : "=r"(r[0]), "=r"(r[1]) : "r"(a));
}
__device__ __forceinline__ void mma16816(float* d, const u32* a, const u32* bb) {
    asm volatile("mma.sync.aligned.m16n8k16.row.col.f32.bf16.bf16.f32 "
                 "{%0,%1,%2,%3},{%4,%5,%6,%7},{%8,%9},{%0,%1,%2,%3};"
                 : "+f"(d[0]), "+f"(d[1]), "+f"(d[2]), "+f"(d[3])
                 : "r"(a[0]), "r"(a[1]), "r"(a[2]), "r"(a[3]), "r"(bb[0]), "r"(bb[1]));
}

// attn smem byte offsets: bf16 tiles pitched 72 (9216 B each), Sc f32 pitch 68
#define O_QH 0
#define O_QL 9216
#define O_KH 18432
#define O_KL 27648
#define O_VH 36864
#define O_VL 46080
#define O_PH 55296
#define O_PL 64512
#define O_SC 73728
#define ATTN_SMEMB (73728 + 64 * 68 * 4)   // 91136

// ---------------- prep ------------------------------------------------------
__global__ void prep_k(const void* mask_in, const void* batch_in) {
    __shared__ int flg[2];
    __shared__ int cnt[BBATCH];
    int tid = threadIdx.x;
    if (tid < 2) flg[tid] = 0;
    if (tid < BBATCH) cnt[tid] = 0;
    __syncthreads();
    const unsigned int* bw = (const unsigned int*)batch_in;
    unsigned int o = 0;
    for (int i = tid * 2 + 1; i < NN; i += blockDim.x * 2) o |= bw[i];
    if (o) atomicOr(&flg[0], 1);
    const unsigned char* mb = (const unsigned char*)mask_in;
    int f = 0;
    for (int i = tid; i < BBATCH * SS; i += blockDim.x)
        if ((i & 3) && mb[i]) f = 1;
    if (f) atomicOr(&flg[1], 1);
    __syncthreads();
    int is32 = flg[0], isb = flg[1];
    int lc[BBATCH] = {0, 0, 0, 0};
    for (int i = tid; i < NN; i += blockDim.x) {
        int v = is32 ? ((const int*)batch_in)[i]
                     : (int)((const long long*)batch_in)[i];
        lc[v & 3]++;
    }
    #pragma unroll
    for (int b = 0; b < BBATCH; b++) if (lc[b]) atomicAdd(&cnt[b], lc[b]);
    for (int i = tid; i < BBATCH * SS; i += blockDim.x)
        g_mask[i] = isb ? (mb[i] ? 1 : 0) : (((const int*)mask_in)[i] ? 1 : 0);
    __syncthreads();
    if (tid == 0) {
        int st = 0, t = 0;
        for (int b = 0; b < BBATCH; b++) {
            int e = st + cnt[b];
            for (int s = st; s < e; s += 64) {
                g_tb[t] = b; g_ts[t] = s; g_tc[t] = min(64, e - s); t++;
            }
            st = e;
        }
        g_nt = t;
    }
}

// ---------------- q = x@Wq ; gate = sigmoid(x@Wg + bg) ---------------------
__global__ void __launch_bounds__(256) proj_qg_k(const float* __restrict__ x,
                                                 const float* __restrict__ Wq,
                                                 const float* __restrict__ Wg,
                                                 const float* __restrict__ bg) {
    __shared__ float As[16][68];
    __shared__ float Bs[16][64];
    int tid = threadIdx.x, tx = tid & 15, ty = tid >> 4;
    int m0 = blockIdx.x * 64, n0 = blockIdx.y * 64;
    bool isg = (n0 >= HA);
    const float* W = isg ? Wg : Wq;
    int nc0 = isg ? (n0 - HA) : n0;
    ull acc[4][2] = {};
    int lm = tid >> 2, lk = (tid & 3) * 4;
    int bk = tid >> 4, bn = (tid & 15) * 4;
    for (int k0 = 0; k0 < IFZ; k0 += 16) {
        float4 a = *(const float4*)(x + (size_t)(m0 + lm) * IFZ + k0 + lk);
        As[lk + 0][lm] = a.x; As[lk + 1][lm] = a.y; As[lk + 2][lm] = a.z; As[lk + 3][lm] = a.w;
        *(float4*)&Bs[bk][bn] = *(const float4*)(W + (size_t)(k0 + bk) * HA + nc0 + bn);
        __syncthreads();
        #pragma unroll
        for (int kk = 0; kk < 16; kk++)
            fma8x2(acc, *(float4*)&As[kk][ty * 4], &Bs[kk][tx * 4]);
        __syncthreads();
    }
    if (isg) {
        float4 bgv = *(const float4*)(bg + nc0 + tx * 4);
        #pragma unroll
        for (int i = 0; i < 4; i++) {
            int row = m0 + ty * 4 + i;
            float4 c = row4(acc[i][0], acc[i][1]);
            float4 ov;
            ov.x = 1.0f / (1.0f + __expf(-(c.x + bgv.x)));
            ov.y = 1.0f / (1.0f + __expf(-(c.y + bgv.y)));
            ov.z = 1.0f / (1.0f + __expf(-(c.z + bgv.z)));
            ov.w = 1.0f / (1.0f + __expf(-(c.w + bgv.w)));
            *(float4*)&g_gate[(size_t)row * HA + nc0 + tx * 4] = ov;
        }
    } else {
        #pragma unroll
        for (int i = 0; i < 4; i++) {
            int row = m0 + ty * 4 + i;
            *(float4*)&g_q[(size_t)row * HA + nc0 + tx * 4] = row4(acc[i][0], acc[i][1]);
        }
    }
}

// ---------------- k = emb@Wk ; v = emb@Wv ----------------------------------
__global__ void __launch_bounds__(256) proj_kv_k(const float* __restrict__ emb,
                                                 const float* __restrict__ Wk,
                                                 const float* __restrict__ Wv) {
    __shared__ float As[16][68];
    __shared__ float Bs[16][64];
    int tid = threadIdx.x, tx = tid & 15, ty = tid >> 4;
    int m0 = blockIdx.x * 64, n0 = blockIdx.y * 64;
    bool isv = (n0 >= HA);
    const float* W = isv ? Wv : Wk;
    float* Cout = isv ? g_v : g_k;
    int nc0 = isv ? (n0 - HA) : n0;
    ull acc[4][2] = {};
    int lm = tid >> 2, lk = (tid & 3) * 4;
    int bk = tid >> 4, bn = (tid & 15) * 4;
    for (int k0 = 0; k0 < SFZ; k0 += 16) {
        float4 a = *(const float4*)(emb + (size_t)(m0 + lm) * SFZ + k0 + lk);
        As[lk + 0][lm] = a.x; As[lk + 1][lm] = a.y; As[lk + 2][lm] = a.z; As[lk + 3][lm] = a.w;
        *(float4*)&Bs[bk][bn] = *(const float4*)(W + (size_t)(k0 + bk) * HA + nc0 + bn);
        __syncthreads();
        #pragma unroll
        for (int kk = 0; kk < 16; kk++)
            fma8x2(acc, *(float4*)&As[kk][ty * 4], &Bs[kk][tx * 4]);
        __syncthreads();
    }
    #pragma unroll
    for (int i = 0; i < 4; i++) {
        int row = m0 + ty * 4 + i;
        *(float4*)&Cout[(size_t)row * HA + nc0 + tx * 4] = row4(acc[i][0], acc[i][1]);
    }
}

// ---------------- K -> bf16 hi/lo ------------------------------------------
__global__ void conv_k_k() {
    size_t i = ((size_t)blockIdx.x * 256 + threadIdx.x) * 4;
    float4 v = *(const float4*)&g_k[i];
    u32 h0 = pkbf(v.x, v.y), h1 = pkbf(v.z, v.w);
    float2 f0 = unbf(h0), f1 = unbf(h1);
    u32 l0 = pkbf(v.x - f0.x, v.y - f0.y), l1 = pkbf(v.z - f1.x, v.w - f1.y);
    *(uint2*)&g_kh[i] = make_uint2(h0, h1);
    *(uint2*)&g_kl[i] = make_uint2(l0, l1);
}

// ---------------- V -> transposed [b][h][a][s] bf16 hi/lo ------------------
__global__ void __launch_bounds__(128) conv_v_k() {
    __shared__ float buf[64 * 68];   // pitch 68: 272B rows, float4-aligned
    int b = blockIdx.z, h = blockIdx.y, s0 = blockIdx.x * 64;
    int tid = threadIdx.x;
    #pragma unroll
    for (int p = 0; p < 8; p++) {
        int idx = tid + p * 128, s = idx >> 4, q = idx & 15;
        *(float4*)&buf[s * 68 + q * 4] =
            *(const float4*)&g_v[((size_t)(b << 10) + s0 + s) * HA + h * AA + q * 4];
    }
    __syncthreads();
    int aa = tid >> 1, sh = (tid & 1) * 32;
    u32 hv[16], lv[16];
    #pragma unroll
    for (int p = 0; p < 16; p++) {
        float x0 = buf[(sh + 2 * p) * 68 + aa], x1 = buf[(sh + 2 * p + 1) * 68 + aa];
        hv[p] = pkbf(x0, x1);
        float2 f = unbf(hv[p]);
        lv[p] = pkbf(x0 - f.x, x1 - f.y);
    }
    size_t o = ((size_t)(b * HH + h) * AA + aa) * SS + s0 + sh;
    #pragma unroll
    for (int p = 0; p < 4; p++) {
        *(uint4*)&g_vh[o + p * 8] = make_uint4(hv[4*p], hv[4*p+1], hv[4*p+2], hv[4*p+3]);
        *(uint4*)&g_vl[o + p * 8] = make_uint4(lv[4*p], lv[4*p+1], lv[4*p+2], lv[4*p+3]);
    }
}

// ---------------- attention: mma.sync bf16 3-term, two-pass ----------------
__global__ void __launch_bounds__(128) attn_mma() {
    extern __shared__ unsigned char sm8[];
    const int t = blockIdx.x;
    if (t >= g_nt) return;
    const int h = blockIdx.y;
    const int b = g_tb[t], n0 = g_ts[t], cnt = g_tc[t];
    const int tid = threadIdx.x, lane = tid & 31, w = tid >> 5;
    const u32 SB = s2u(sm8);
    float* Sc = (float*)(sm8 + O_SC);

    // stage Q hi/lo (once)
    {
        int i = tid >> 1, ah = (tid & 1) * 32;
        bool val = i < cnt;
        const float* q = &g_q[(size_t)(n0 + i) * HA + h * AA + ah];
        u32 ro = (u32)(i * 72 + ah) * 2;
        #pragma unroll
        for (int u = 0; u < 4; u++) {
            float4 x0 = val ? *(const float4*)(q + u * 8) : make_float4(0, 0, 0, 0);
            float4 x1 = val ? *(const float4*)(q + u * 8 + 4) : make_float4(0, 0, 0, 0);
            u32 h0 = pkbf(x0.x, x0.y), h1 = pkbf(x0.z, x0.w);
            u32 h2 = pkbf(x1.x, x1.y), h3 = pkbf(x1.z, x1.w);
            float2 f0 = unbf(h0), f1 = unbf(h1), f2 = unbf(h2), f3 = unbf(h3);
            u32 l0 = pkbf(x0.x - f0.x, x0.y - f0.y), l1 = pkbf(x0.z - f1.x, x0.w - f1.y);
            u32 l2 = pkbf(x1.x - f2.x, x1.y - f2.y), l3 = pkbf(x1.z - f3.x, x1.w - f3.y);
            *(uint4*)(sm8 + O_QH + ro + u * 16) = make_uint4(h0, h1, h2, h3);
            *(uint4*)(sm8 + O_QL + ro + u * 16) = make_uint4(l0, l1, l2, l3);
        }
    }
    __syncthreads();

    // persistent A fragments for Q
    u32 qhf[4][4], qlf[4][4];
    {
        u32 arow = 16 * w + (lane & 7) + ((lane >> 3) & 1) * 8;
        u32 acol = ((lane >> 4) & 1) * 8;
        #pragma unroll
        for (int k = 0; k < 4; k++) {
            ldmx4(qhf[k], SB + O_QH + (arow * 72 + acol + 16 * k) * 2);
            ldmx4(qlf[k], SB + O_QL + (arow * 72 + acol + 16 * k) * 2);
        }
    }

    const int lr = lane & 15;
    const u32 brow = lr & 7, bc8 = (lr >> 3) * 8;
    const int r0 = 16 * w + (lane >> 2), cc0 = (lane & 3) * 2;
    float mrow = -FLT_MAX;

    // ---- pass 1: hi-only QK row max
    for (int s0 = 0; s0 < SS; s0 += 64) {
        {
            int j = tid >> 1, ah = (tid & 1) * 32;
            const uint4* kp = (const uint4*)&g_kh[((size_t)(b << 10) + s0 + j) * HA + h * AA + ah];
            u32 ro = (u32)(j * 72 + ah) * 2;
            #pragma unroll
            for (int u = 0; u < 4; u++)
                *(uint4*)(sm8 + O_KH + ro + u * 16) = kp[u];
        }
        __syncthreads();
        #pragma unroll
        for (int cg = 0; cg < 8; cg++) {
            float d[4] = {0.f, 0.f, 0.f, 0.f};
            #pragma unroll
            for (int k = 0; k < 4; k++) {
                u32 bh[2];
                ldmx2(bh, SB + O_KH + ((cg * 8 + brow) * 72 + 16 * k + bc8) * 2);
                mma16816(d, qhf[k], bh);
            }
            *(float2*)&Sc[r0 * 68 + cg * 8 + cc0] = make_float2(d[0], d[1]);
            *(float2*)&Sc[(r0 + 8) * 68 + cg * 8 + cc0] = make_float2(d[2], d[3]);
        }
        __syncthreads();
        if (tid < 64) {
            const u32* mp = (const u32*)&g_mask[b * SS + s0];
            const float* sr = &Sc[tid * 68];
            #pragma unroll
            for (int x = 0; x < 16; x++) {
                u32 mw = mp[x];
                float4 v = *(const float4*)(sr + x * 4);
                if (mw & 255u) mrow = fmaxf(mrow, v.x);
                if ((mw >> 8) & 255u) mrow = fmaxf(mrow, v.y);
                if ((mw >> 16) & 255u) mrow = fmaxf(mrow, v.z);
                if (mw >> 24) mrow = fmaxf(mrow, v.w);
            }
        }
        __syncthreads();
    }
    float mfix = (mrow == -FLT_MAX) ? 0.f : mrow * 0.125f;
    float lsum = 0.f;
    float feat[8][4];
    #pragma unroll
    for (int cg = 0; cg < 8; cg++)
        feat[cg][0] = feat[cg][1] = feat[cg][2] = feat[cg][3] = 0.f;

    // ---- pass 2: exact 3-term scores, softmax, PV accumulate
    for (int s0 = 0; s0 < SS; s0 += 64) {
        {
            int j = tid >> 1, ah = (tid & 1) * 32;
            size_t kr = ((size_t)(b << 10) + s0 + j) * HA + h * AA + ah;
            size_t vr = ((size_t)(b * HH + h) * AA + j) * SS + s0 + ah;
            u32 ro = (u32)(j * 72 + ah) * 2;
            #pragma unroll
            for (int u = 0; u < 4; u++) {
                *(uint4*)(sm8 + O_KH + ro + u * 16) = *(const uint4*)(&g_kh[kr] + u * 8);
                *(uint4*)(sm8 + O_KL + ro + u * 16) = *(const uint4*)(&g_kl[kr] + u * 8);
                *(uint4*)(sm8 + O_VH + ro + u * 16) = *(const uint4*)(&g_vh[vr] + u * 8);
                *(uint4*)(sm8 + O_VL + ro + u * 16) = *(const uint4*)(&g_vl[vr] + u * 8);
            }
        }
        __syncthreads();
        #pragma unroll
        for (int cg = 0; cg < 8; cg++) {
            float d[4] = {0.f, 0.f, 0.f, 0.f};
            #pragma unroll
            for (int k = 0; k < 4; k++) {
                u32 off = ((cg * 8 + brow) * 72 + 16 * k + bc8) * 2;
                u32 bh[2], bl[2];
                ldmx2(bh, SB + O_KH + off);
                ldmx2(bl, SB + O_KL + off);
                mma16816(d, qhf[k], bh);
                mma16816(d, qhf[k], bl);
                mma16816(d, qlf[k], bh);
            }
            *(float2*)&Sc[r0 * 68 + cg * 8 + cc0] = make_float2(d[0], d[1]);
            *(float2*)&Sc[(r0 + 8) * 68 + cg * 8 + cc0] = make_float2(d[2], d[3]);
        }
        __syncthreads();
        if (tid < 64) {
            float sc[64];
            const float* sr = &Sc[tid * 68];
            #pragma unroll
            for (int x = 0; x < 16; x++) {
                float4 v = *(const float4*)(sr + x * 4);
                sc[x*4] = v.x * 0.125f; sc[x*4+1] = v.y * 0.125f;
                sc[x*4+2] = v.z * 0.125f; sc[x*4+3] = v.w * 0.125f;
            }
            if (h < 2 && tid < cnt) {
                float* dst = (h == 0 ? g_sc0 : g_sc1) + (size_t)(n0 + tid) * SS + s0;
                #pragma unroll
                for (int x = 0; x < 16; x++)
                    *(float4*)(dst + x * 4) =
                        make_float4(sc[x*4], sc[x*4+1], sc[x*4+2], sc[x*4+3]);
            }
            const u32* mp = (const u32*)&g_mask[b * SS + s0];
            #pragma unroll
            for (int x = 0; x < 16; x++) {
                u32 mw = mp[x];
                float p0 = (mw & 255u) ? __expf(sc[x*4] - mfix) : 0.f;
                float p1 = ((mw >> 8) & 255u) ? __expf(sc[x*4+1] - mfix) : 0.f;
                float p2 = ((mw >> 16) & 255u) ? __expf(sc[x*4+2] - mfix) : 0.f;
                float p3 = (mw >> 24) ? __expf(sc[x*4+3] - mfix) : 0.f;
                sc[x*4] = p0; sc[x*4+1] = p1; sc[x*4+2] = p2; sc[x*4+3] = p3;
                lsum += p0 + p1 + p2 + p3;
            }
            u32 ro = (u32)(tid * 72) * 2;
            #pragma unroll
            for (int u = 0; u < 8; u++) {
                u32 h0 = pkbf(sc[u*8], sc[u*8+1]), h1 = pkbf(sc[u*8+2], sc[u*8+3]);
                u32 h2 = pkbf(sc[u*8+4], sc[u*8+5]), h3 = pkbf(sc[u*8+6], sc[u*8+7]);
                float2 f0 = unbf(h0), f1 = unbf(h1), f2 = unbf(h2), f3 = unbf(h3);
                u32 l0 = pkbf(sc[u*8]-f0.x, sc[u*8+1]-f0.y), l1 = pkbf(sc[u*8+2]-f1.x, sc[u*8+3]-f1.y);
                u32 l2 = pkbf(sc[u*8+4]-f2.x, sc[u*8+5]-f2.y), l3 = pkbf(sc[u*8+6]-f3.x, sc[u*8+7]-f3.y);
                *(uint4*)(sm8 + O_PH + ro + u * 16) = make_uint4(h0, h1, h2, h3);
                *(uint4*)(sm8 + O_PL + ro + u * 16) = make_uint4(l0, l1, l2, l3);
            }
        }
        __syncthreads();
        // PV: A = P (k=j), B = Vt[a][j]
        {
            u32 arow = 16 * w + (lane & 7) + ((lane >> 3) & 1) * 8;
            u32 acol = ((lane >> 4) & 1) * 8;
            u32 phf[4][4], plf[4][4];
            #pragma unroll
            for (int k = 0; k < 4; k++) {
                ldmx4(phf[k], SB + O_PH + (arow * 72 + acol + 16 * k) * 2);
                ldmx4(plf[k], SB + O_PL + (arow * 72 + acol + 16 * k) * 2);
            }
            #pragma unroll
            for (int cg = 0; cg < 8; cg++) {
                #pragma unroll
                for (int k = 0; k < 4; k++) {
                    u32 off = ((cg * 8 + brow) * 72 + 16 * k + bc8) * 2;
                    u32 bh[2], bl[2];
                    ldmx2(bh, SB + O_VH + off);
                    ldmx2(bl, SB + O_VL + off);
                    mma16816(feat[cg], phf[k], bh);
                    mma16816(feat[cg], phf[k], bl);
                    mma16816(feat[cg], plf[k], bh);
                }
            }
        }
        __syncthreads();
    }

    // epilogue: frags -> Sc, then row threads gate+store
    #pragma unroll
    for (int cg = 0; cg < 8; cg++) {
        *(float2*)&Sc[r0 * 68 + cg * 8 + cc0] = make_float2(feat[cg][0], feat[cg][1]);
        *(float2*)&Sc[(r0 + 8) * 68 + cg * 8 + cc0] = make_float2(feat[cg][2], feat[cg][3]);
    }
    __syncthreads();
    if (tid < cnt) {
        float inv = 1.f / (lsum + 1e-9f);
        const float* gp = &g_gate[(size_t)(n0 + tid) * HA + h * AA];
        float* fp = &g_feat[(size_t)(n0 + tid) * HA + h * AA];
        const float* sr = &Sc[tid * 68];
        #pragma unroll
        for (int x = 0; x < 16; x++) {
            float4 v = *(const float4*)(sr + x * 4);
            float4 g = *(const float4*)(gp + x * 4);
            *(float4*)(fp + x * 4) =
                make_float4(v.x * inv * g.x, v.y * inv * g.y, v.z * inv * g.z, v.w * inv * g.w);
        }
    }
}

// ---------------- logits = sc0 + sc1 ---------------------------------------
__global__ void addlog_k(float* __restrict__ logits) {
    size_t i = ((size_t)blockIdx.x * 256 + threadIdx.x) * 4;
    float4 a = *(const float4*)&g_sc0[i];
    float4 b4 = *(const float4*)&g_sc1[i];
    *(float4*)&logits[i] = make_float4(a.x + b4.x, a.y + b4.y, a.z + b4.z, a.w + b4.w);
}

// ---------------- y = sqrt(2)*x + gatedfeat @ Wback + bback ----------------
__global__ void __launch_bounds__(256) back_k(const float* __restrict__ x,
                                              const float* __restrict__ Wback,
                                              const float* __restrict__ bback) {
    __shared__ float As[16][68];
    __shared__ float Bs[16][64];
    int tid = threadIdx.x, tx = tid & 15, ty = tid >> 4;
    int m0 = blockIdx.x * 64, n0 = blockIdx.y * 64;
    ull acc[4][2] = {};
    int lm = tid >> 2, lk = (tid & 3) * 4;
    int bk = tid >> 4, bn = (tid & 15) * 4;
    for (int k0 = 0; k0 < HA; k0 += 16) {
        float4 a = *(const float4*)&g_feat[(size_t)(m0 + lm) * HA + k0 + lk];
        As[lk + 0][lm] = a.x; As[lk + 1][lm] = a.y; As[lk + 2][lm] = a.z; As[lk + 3][lm] = a.w;
        *(float4*)&Bs[bk][bn] = *(const float4*)&Wback[(size_t)(k0 + bk) * IFZ + n0 + bn];
        __syncthreads();
        #pragma unroll
        for (int kk = 0; kk < 16; kk++)
            fma8x2(acc, *(float4*)&As[kk][ty * 4], &Bs[kk][tx * 4]);
        __syncthreads();
    }
    const float rt2 = 1.41421356237309515f;
    float4 bb = *(const float4*)&bback[n0 + tx * 4];
    #pragma unroll
    for (int i = 0; i < 4; i++) {
        int row = m0 + ty * 4 + i;
        float4 xv = *(const float4*)&x[(size_t)row * IFZ + n0 + tx * 4];
        float4 cc = row4(acc[i][0], acc[i][1]);
        float4 ov;
        ov.x = rt2 * xv.x + cc.x + bb.x;
        ov.y = rt2 * xv.y + cc.y + bb.y;
        ov.z = rt2 * xv.z + cc.z + bb.z;
        ov.w = rt2 * xv.w + cc.w + bb.w;
        *(float4*)&g_y[(size_t)row * IFZ + n0 + tx * 4] = ov;
    }
}

// ---------------- LayerNorm ------------------------------------------------
__global__ void __launch_bounds__(256) ln_k(const float* __restrict__ gamma,
                                            const float* __restrict__ beta,
                                            float* __restrict__ out) {
    int warp = threadIdx.x >> 5, lane = threadIdx.x & 31;
    int row = blockIdx.x * 8 + warp;
    float4 v0 = *(const float4*)&g_y[(size_t)row * IFZ + lane * 4];
    float4 v1 = *(const float4*)&g_y[(size_t)row * IFZ + 128 + lane * 4];
    float s = v0.x + v0.y + v0.z + v0.w + v1.x + v1.y + v1.z + v1.w;
    #pragma unroll
    for (int d = 16; d; d >>= 1) s += __shfl_xor_sync(0xffffffffu, s, d);
    float mu = s * (1.f / 256.f);
    float q = 0.f;
    q += (v0.x - mu) * (v0.x - mu); q += (v0.y - mu) * (v0.y - mu);
    q += (v0.z - mu) * (v0.z - mu); q += (v0.w - mu) * (v0.w - mu);
    q += (v1.x - mu) * (v1.x - mu); q += (v1.y - mu) * (v1.y - mu);
    q += (v1.z - mu) * (v1.z - mu); q += (v1.w - mu) * (v1.w - mu);
    #pragma unroll
    for (int d = 16; d; d >>= 1) q += __shfl_xor_sync(0xffffffffu, q, d);
    float inv = rsqrtf(q * (1.f / 256.f) + 1e-5f);
    float4 g0 = *(const float4*)&gamma[lane * 4];
    float4 b0 = *(const float4*)&beta[lane * 4];
    float4 g1 = *(const float4*)&gamma[128 + lane * 4];
    float4 b1 = *(const float4*)&beta[128 + lane * 4];
    float4 o0, o1;
    o0.x = (v0.x - mu) * inv * g0.x + b0.x;
    o0.y = (v0.y - mu) * inv * g0.y + b0.y;
    o0.z = (v0.z - mu) * inv * g0.z + b0.z;
    o0.w = (v0.w - mu) * inv * g0.w + b0.w;
    o1.x = (v1.x - mu) * inv * g1.x + b1.x;
    o1.y = (v1.y - mu) * inv * g1.y + b1.y;
    o1.z = (v1.z - mu) * inv * g1.z + b1.z;
    o1.w = (v1.w - mu) * inv * g1.w + b1.w;
    *(float4*)&out[(size_t)row * IFZ + lane * 4] = o0;
    *(float4*)&out[(size_t)row * IFZ + 128 + lane * 4] = o1;
}

// ---------------- launch ---------------------------------------------------
extern "C" void kernel_launch(void* const* d_in, const int* in_sizes, int n_in,
                              void* d_out, int out_size) {
    const float* x     = (const float*)d_in[0];
    const float* emb   = (const float*)d_in[1];
    const void*  mask  = d_in[2];
    const void*  batch = d_in[3];
    const float* Wq    = (const float*)d_in[4];
    const float* Wk    = (const float*)d_in[5];
    const float* Wv    = (const float*)d_in[6];
    const float* Wg    = (const float*)d_in[7];
    const float* bg    = (const float*)d_in[8];
    const float* Wback = (const float*)d_in[9];
    const float* bback = (const float*)d_in[10];
    const float* gamma = (const float*)d_in[11];
    const float* beta  = (const float*)d_in[12];
    float* out    = (float*)d_out;
    float* logits = out + (size_t)NN * IFZ;

    static int smem_set = 0;
    if (!smem_set) {
        cudaFuncSetAttribute(attn_mma, cudaFuncAttributeMaxDynamicSharedMemorySize,
                             ATTN_SMEMB);
        smem_set = 1;
    }

    prep_k<<<1, 256>>>(mask, batch);
    proj_qg_k<<<dim3(32, 16), 256>>>(x, Wq, Wg, bg);
    proj_kv_k<<<dim3(64, 16), 256>>>(emb, Wk, Wv);
    conv_k_k<<<2048, 256>>>();
    conv_v_k<<<dim3(16, HH, BBATCH), 128>>>();
    attn_mma<<<dim3(MAXT, HH), 128, ATTN_SMEMB>>>();
    addlog_k<<<2048, 256>>>(logits);
    back_k<<<dim3(32, 4), 256>>>(x, Wback, bback);
    ln_k<<<256, 256>>>(gamma, beta, out);
}

// round 10
// speedup vs baseline: 1.2222x; 1.0609x over previous
#include <cuda_runtime.h>
#include <cuda_bf16.h>
#include <float.h>
#include <math.h>

#define NN   2048
#define BBATCH 4
#define SS   1024
#define SFZ  384
#define IFZ  256
#define HH   8
#define AA   64
#define HA   512
#define MAXT 36

typedef unsigned long long ull;
typedef unsigned int u32;

__device__ __align__(16) float g_q[NN * HA];
__device__ __align__(16) float g_gate[NN * HA];
__device__ __align__(16) float g_k[BBATCH * SS * HA];
__device__ __align__(16) float g_v[BBATCH * SS * HA];
__device__ __align__(16) float g_feat[NN * HA];
__device__ __align__(16) float g_y[NN * IFZ];
__device__ __align__(16) unsigned char g_mask[BBATCH * SS];
__device__ int g_tb[MAXT], g_ts[MAXT], g_tc[MAXT], g_nt;
__device__ __align__(16) __nv_bfloat16 g_kh[BBATCH * SS * HA];
__device__ __align__(16) __nv_bfloat16 g_kl[BBATCH * SS * HA];
__device__ __align__(16) __nv_bfloat16 g_vh[BBATCH * HH * AA * SS];
__device__ __align__(16) __nv_bfloat16 g_vl[BBATCH * HH * AA * SS];
__device__ __align__(16) float g_sc0[NN * SS];
__device__ __align__(16) float g_sc1[NN * SS];

// ---- fp32 packed helpers (proj kernels) ----
__device__ __forceinline__ void ffma2(ull &d, ull a, ull b) {
    asm("fma.rn.f32x2 %0, %1, %2, %0;" : "+l"(d) : "l"(a), "l"(b));
}
__device__ __forceinline__ ull pk2(float lo, float hi) {
    ull r; asm("mov.b64 %0, {%1, %2};" : "=l"(r) : "f"(lo), "f"(hi)); return r;
}
__device__ __forceinline__ float2 upk2(ull v) {
    float2 r; asm("mov.b64 {%0, %1}, %2;" : "=f"(r.x), "=f"(r.y) : "l"(v)); return r;
}
__device__ __forceinline__ void fma8x2(ull (&acc)[4][2], float4 a, const float* bp) {
    ull b0 = *(const ull*)bp, b1 = *(const ull*)(bp + 2);
    ull a0 = pk2(a.x, a.x), a1 = pk2(a.y, a.y), a2 = pk2(a.z, a.z), a3 = pk2(a.w, a.w);
    ffma2(acc[0][0], a0, b0); ffma2(acc[0][1], a0, b1);
    ffma2(acc[1][0], a1, b0); ffma2(acc[1][1], a1, b1);
    ffma2(acc[2][0], a2, b0); ffma2(acc[2][1], a2, b1);
    ffma2(acc[3][0], a3, b0); ffma2(acc[3][1], a3, b1);
}
__device__ __forceinline__ float4 row4(ull p0, ull p1) {
    float2 a = upk2(p0), b = upk2(p1);
    return make_float4(a.x, a.y, b.x, b.y);
}

// ---- bf16 split helpers ----
__device__ __forceinline__ u32 pkbf(float a, float b) {
    __nv_bfloat162 t = __float22bfloat162_rn(make_float2(a, b));
    return *(u32*)&t;
}
__device__ __forceinline__ float2 unbf(u32 h) {
    return __bfloat1622float2(*(__nv_bfloat162*)&h);
}

// ---- legacy tensor core: ldmatrix + mma.sync (baseline PTX, sm_80+) ----
static __device__ __forceinline__ u32 s2u(const void* p) {
    u32 a; asm("{.reg .u64 t; cvta.to.shared.u64 t, %1; cvt.u32.u64 %0, t;}" : "=r"(a) : "l"(p));
    return a;
}
__device__ __forceinline__ void ldmx4(u32* r, u32 a) {
    asm volatile("ldmatrix.sync.aligned.m8n8.x4.shared.b16 {%0,%1,%2,%3},[%4];"
                 : "=r"(r[0]), "=r"(r[1]), "=r"(r[2]), "=r"(r[3]) : "r"(a));
}
__device__ __forceinline__ void ldmx2(u32* r, u32 a) {
    asm volatile("ldmatrix.sync.aligned.m8n8.x2.shared.b16 {%0,%1},[%2];"
                 : "=r"(r[0]), "=r"(r[1]) : "r"(a));
}
__device__ __forceinline__ void mma16816(float* d, const u32* a, const u32* bb) {
    asm volatile("mma.sync.aligned.m16n8k16.row.col.f32.bf16.bf16.f32 "
                 "{%0,%1,%2,%3},{%4,%5,%6,%7},{%8,%9},{%0,%1,%2,%3};"
                 : "+f"(d[0]), "+f"(d[1]), "+f"(d[2]), "+f"(d[3])
                 : "r"(a[0]), "r"(a[1]), "r"(a[2]), "r"(a[3]), "r"(bb[0]), "r"(bb[1]));
}

// attn smem byte offsets: bf16 tiles pitched 72 (9216 B each), Sc f32 pitch 68
#define O_QH 0
#define O_QL 9216
#define O_KH 18432
#define O_KL 27648
#define O_VH 36864
#define O_VL 46080
#define O_PH 55296
#define O_PL 64512
#define O_SC 73728
#define O_AL (O_SC + 64 * 68 * 4)          // 64-float alpha broadcast
#define ATTN_SMEMB (O_AL + 256)            // 91392

// ---------------- prep ------------------------------------------------------
__global__ void prep_k(const void* mask_in, const void* batch_in) {
    __shared__ int flg[2];
    __shared__ int cnt[BBATCH];
    int tid = threadIdx.x;
    if (tid < 2) flg[tid] = 0;
    if (tid < BBATCH) cnt[tid] = 0;
    __syncthreads();
    const unsigned int* bw = (const unsigned int*)batch_in;
    unsigned int o = 0;
    for (int i = tid * 2 + 1; i < NN; i += blockDim.x * 2) o |= bw[i];
    if (o) atomicOr(&flg[0], 1);
    const unsigned char* mb = (const unsigned char*)mask_in;
    int f = 0;
    for (int i = tid; i < BBATCH * SS; i += blockDim.x)
        if ((i & 3) && mb[i]) f = 1;
    if (f) atomicOr(&flg[1], 1);
    __syncthreads();
    int is32 = flg[0], isb = flg[1];
    int lc[BBATCH] = {0, 0, 0, 0};
    for (int i = tid; i < NN; i += blockDim.x) {
        int v = is32 ? ((const int*)batch_in)[i]
                     : (int)((const long long*)batch_in)[i];
        lc[v & 3]++;
    }
    #pragma unroll
    for (int b = 0; b < BBATCH; b++) if (lc[b]) atomicAdd(&cnt[b], lc[b]);
    for (int i = tid; i < BBATCH * SS; i += blockDim.x)
        g_mask[i] = isb ? (mb[i] ? 1 : 0) : (((const int*)mask_in)[i] ? 1 : 0);
    __syncthreads();
    if (tid == 0) {
        int st = 0, t = 0;
        for (int b = 0; b < BBATCH; b++) {
            int e = st + cnt[b];
            for (int s = st; s < e; s += 64) {
                g_tb[t] = b; g_ts[t] = s; g_tc[t] = min(64, e - s); t++;
            }
            st = e;
        }
        g_nt = t;
    }
}

// ---------------- q = x@Wq ; gate = sigmoid(x@Wg + bg) ---------------------
__global__ void __launch_bounds__(256) proj_qg_k(const float* __restrict__ x,
                                                 const float* __restrict__ Wq,
                                                 const float* __restrict__ Wg,
                                                 const float* __restrict__ bg) {
    __shared__ float As[16][68];
    __shared__ float Bs[16][64];
    int tid = threadIdx.x, tx = tid & 15, ty = tid >> 4;
    int m0 = blockIdx.x * 64, n0 = blockIdx.y * 64;
    bool isg = (n0 >= HA);
    const float* W = isg ? Wg : Wq;
    int nc0 = isg ? (n0 - HA) : n0;
    ull acc[4][2] = {};
    int lm = tid >> 2, lk = (tid & 3) * 4;
    int bk = tid >> 4, bn = (tid & 15) * 4;
    for (int k0 = 0; k0 < IFZ; k0 += 16) {
        float4 a = *(const float4*)(x + (size_t)(m0 + lm) * IFZ + k0 + lk);
        As[lk + 0][lm] = a.x; As[lk + 1][lm] = a.y; As[lk + 2][lm] = a.z; As[lk + 3][lm] = a.w;
        *(float4*)&Bs[bk][bn] = *(const float4*)(W + (size_t)(k0 + bk) * HA + nc0 + bn);
        __syncthreads();
        #pragma unroll
        for (int kk = 0; kk < 16; kk++)
            fma8x2(acc, *(float4*)&As[kk][ty * 4], &Bs[kk][tx * 4]);
        __syncthreads();
    }
    if (isg) {
        float4 bgv = *(const float4*)(bg + nc0 + tx * 4);
        #pragma unroll
        for (int i = 0; i < 4; i++) {
            int row = m0 + ty * 4 + i;
            float4 c = row4(acc[i][0], acc[i][1]);
            float4 ov;
            ov.x = 1.0f / (1.0f + __expf(-(c.x + bgv.x)));
            ov.y = 1.0f / (1.0f + __expf(-(c.y + bgv.y)));
            ov.z = 1.0f / (1.0f + __expf(-(c.z + bgv.z)));
            ov.w = 1.0f / (1.0f + __expf(-(c.w + bgv.w)));
            *(float4*)&g_gate[(size_t)row * HA + nc0 + tx * 4] = ov;
        }
    } else {
        #pragma unroll
        for (int i = 0; i < 4; i++) {
            int row = m0 + ty * 4 + i;
            *(float4*)&g_q[(size_t)row * HA + nc0 + tx * 4] = row4(acc[i][0], acc[i][1]);
        }
    }
}

// ---------------- k = emb@Wk ; v = emb@Wv ----------------------------------
__global__ void __launch_bounds__(256) proj_kv_k(const float* __restrict__ emb,
                                                 const float* __restrict__ Wk,
                                                 const float* __restrict__ Wv) {
    __shared__ float As[16][68];
    __shared__ float Bs[16][64];
    int tid = threadIdx.x, tx = tid & 15, ty = tid >> 4;
    int m0 = blockIdx.x * 64, n0 = blockIdx.y * 64;
    bool isv = (n0 >= HA);
    const float* W = isv ? Wv : Wk;
    float* Cout = isv ? g_v : g_k;
    int nc0 = isv ? (n0 - HA) : n0;
    ull acc[4][2] = {};
    int lm = tid >> 2, lk = (tid & 3) * 4;
    int bk = tid >> 4, bn = (tid & 15) * 4;
    for (int k0 = 0; k0 < SFZ; k0 += 16) {
        float4 a = *(const float4*)(emb + (size_t)(m0 + lm) * SFZ + k0 + lk);
        As[lk + 0][lm] = a.x; As[lk + 1][lm] = a.y; As[lk + 2][lm] = a.z; As[lk + 3][lm] = a.w;
        *(float4*)&Bs[bk][bn] = *(const float4*)(W + (size_t)(k0 + bk) * HA + nc0 + bn);
        __syncthreads();
        #pragma unroll
        for (int kk = 0; kk < 16; kk++)
            fma8x2(acc, *(float4*)&As[kk][ty * 4], &Bs[kk][tx * 4]);
        __syncthreads();
    }
    #pragma unroll
    for (int i = 0; i < 4; i++) {
        int row = m0 + ty * 4 + i;
        *(float4*)&Cout[(size_t)row * HA + nc0 + tx * 4] = row4(acc[i][0], acc[i][1]);
    }
}

// ---------------- K -> bf16 hi/lo ------------------------------------------
__global__ void conv_k_k() {
    size_t i = ((size_t)blockIdx.x * 256 + threadIdx.x) * 4;
    float4 v = *(const float4*)&g_k[i];
    u32 h0 = pkbf(v.x, v.y), h1 = pkbf(v.z, v.w);
    float2 f0 = unbf(h0), f1 = unbf(h1);
    u32 l0 = pkbf(v.x - f0.x, v.y - f0.y), l1 = pkbf(v.z - f1.x, v.w - f1.y);
    *(uint2*)&g_kh[i] = make_uint2(h0, h1);
    *(uint2*)&g_kl[i] = make_uint2(l0, l1);
}

// ---------------- V -> transposed [b][h][a][s] bf16 hi/lo ------------------
__global__ void __launch_bounds__(128) conv_v_k() {
    __shared__ float buf[64 * 68];   // pitch 68: 272B rows, float4-aligned
    int b = blockIdx.z, h = blockIdx.y, s0 = blockIdx.x * 64;
    int tid = threadIdx.x;
    #pragma unroll
    for (int p = 0; p < 8; p++) {
        int idx = tid + p * 128, s = idx >> 4, q = idx & 15;
        *(float4*)&buf[s * 68 + q * 4] =
            *(const float4*)&g_v[((size_t)(b << 10) + s0 + s) * HA + h * AA + q * 4];
    }
    __syncthreads();
    int aa = tid >> 1, sh = (tid & 1) * 32;
    u32 hv[16], lv[16];
    #pragma unroll
    for (int p = 0; p < 16; p++) {
        float x0 = buf[(sh + 2 * p) * 68 + aa], x1 = buf[(sh + 2 * p + 1) * 68 + aa];
        hv[p] = pkbf(x0, x1);
        float2 f = unbf(hv[p]);
        lv[p] = pkbf(x0 - f.x, x1 - f.y);
    }
    size_t o = ((size_t)(b * HH + h) * AA + aa) * SS + s0 + sh;
    #pragma unroll
    for (int p = 0; p < 4; p++) {
        *(uint4*)&g_vh[o + p * 8] = make_uint4(hv[4*p], hv[4*p+1], hv[4*p+2], hv[4*p+3]);
        *(uint4*)&g_vl[o + p * 8] = make_uint4(lv[4*p], lv[4*p+1], lv[4*p+2], lv[4*p+3]);
    }
}

// ---------------- attention: mma.sync bf16 3-term, ONE-PASS flash ----------
__global__ void __launch_bounds__(128) attn_mma() {
    extern __shared__ unsigned char sm8[];
    const int t = blockIdx.x;
    if (t >= g_nt) return;
    const int h = blockIdx.y;
    const int b = g_tb[t], n0 = g_ts[t], cnt = g_tc[t];
    const int tid = threadIdx.x, lane = tid & 31, w = tid >> 5;
    const u32 SB = s2u(sm8);
    float* Sc = (float*)(sm8 + O_SC);
    float* Al = (float*)(sm8 + O_AL);

    // stage Q hi/lo (once)
    {
        int i = tid >> 1, ah = (tid & 1) * 32;
        bool val = i < cnt;
        const float* q = &g_q[(size_t)(n0 + i) * HA + h * AA + ah];
        u32 ro = (u32)(i * 72 + ah) * 2;
        #pragma unroll
        for (int u = 0; u < 4; u++) {
            float4 x0 = val ? *(const float4*)(q + u * 8) : make_float4(0, 0, 0, 0);
            float4 x1 = val ? *(const float4*)(q + u * 8 + 4) : make_float4(0, 0, 0, 0);
            u32 h0 = pkbf(x0.x, x0.y), h1 = pkbf(x0.z, x0.w);
            u32 h2 = pkbf(x1.x, x1.y), h3 = pkbf(x1.z, x1.w);
            float2 f0 = unbf(h0), f1 = unbf(h1), f2 = unbf(h2), f3 = unbf(h3);
            u32 l0 = pkbf(x0.x - f0.x, x0.y - f0.y), l1 = pkbf(x0.z - f1.x, x0.w - f1.y);
            u32 l2 = pkbf(x1.x - f2.x, x1.y - f2.y), l3 = pkbf(x1.z - f3.x, x1.w - f3.y);
            *(uint4*)(sm8 + O_QH + ro + u * 16) = make_uint4(h0, h1, h2, h3);
            *(uint4*)(sm8 + O_QL + ro + u * 16) = make_uint4(l0, l1, l2, l3);
        }
    }
    __syncthreads();

    // persistent A fragments for Q
    u32 qhf[4][4], qlf[4][4];
    {
        u32 arow = 16 * w + (lane & 7) + ((lane >> 3) & 1) * 8;
        u32 acol = ((lane >> 4) & 1) * 8;
        #pragma unroll
        for (int k = 0; k < 4; k++) {
            ldmx4(qhf[k], SB + O_QH + (arow * 72 + acol + 16 * k) * 2);
            ldmx4(qlf[k], SB + O_QL + (arow * 72 + acol + 16 * k) * 2);
        }
    }

    const int lr = lane & 15;
    const u32 brow = lr & 7, bc8 = (lr >> 3) * 8;
    const int r0 = 16 * w + (lane >> 2), cc0 = (lane & 3) * 2;
    float m_old = -FLT_MAX, lsum = 0.f;
    float feat[8][4];
    #pragma unroll
    for (int cg = 0; cg < 8; cg++)
        feat[cg][0] = feat[cg][1] = feat[cg][2] = feat[cg][3] = 0.f;

    // ---- one-pass flash: exact 3-term scores, online softmax, PV ----------
    for (int s0 = 0; s0 < SS; s0 += 64) {
        {
            int j = tid >> 1, ah = (tid & 1) * 32;
            size_t kr = ((size_t)(b << 10) + s0 + j) * HA + h * AA + ah;
            size_t vr = ((size_t)(b * HH + h) * AA + j) * SS + s0 + ah;
            u32 ro = (u32)(j * 72 + ah) * 2;
            #pragma unroll
            for (int u = 0; u < 4; u++) {
                *(uint4*)(sm8 + O_KH + ro + u * 16) = *(const uint4*)(&g_kh[kr] + u * 8);
                *(uint4*)(sm8 + O_KL + ro + u * 16) = *(const uint4*)(&g_kl[kr] + u * 8);
                *(uint4*)(sm8 + O_VH + ro + u * 16) = *(const uint4*)(&g_vh[vr] + u * 8);
                *(uint4*)(sm8 + O_VL + ro + u * 16) = *(const uint4*)(&g_vl[vr] + u * 8);
            }
        }
        __syncthreads();
        #pragma unroll
        for (int cg = 0; cg < 8; cg++) {
            float d[4] = {0.f, 0.f, 0.f, 0.f};
            #pragma unroll
            for (int k = 0; k < 4; k++) {
                u32 off = ((cg * 8 + brow) * 72 + 16 * k + bc8) * 2;
                u32 bh[2], bl[2];
                ldmx2(bh, SB + O_KH + off);
                ldmx2(bl, SB + O_KL + off);
                mma16816(d, qhf[k], bh);
                mma16816(d, qhf[k], bl);
                mma16816(d, qlf[k], bh);
            }
            *(float2*)&Sc[r0 * 68 + cg * 8 + cc0] = make_float2(d[0], d[1]);
            *(float2*)&Sc[(r0 + 8) * 68 + cg * 8 + cc0] = make_float2(d[2], d[3]);
        }
        __syncthreads();
        if (tid < 64) {
            float sc[64];
            const float* sr = &Sc[tid * 68];
            #pragma unroll
            for (int x = 0; x < 16; x++) {
                float4 v = *(const float4*)(sr + x * 4);
                sc[x*4] = v.x * 0.125f; sc[x*4+1] = v.y * 0.125f;
                sc[x*4+2] = v.z * 0.125f; sc[x*4+3] = v.w * 0.125f;
            }
            if (h < 2 && tid < cnt) {
                float* dst = (h == 0 ? g_sc0 : g_sc1) + (size_t)(n0 + tid) * SS + s0;
                #pragma unroll
                for (int x = 0; x < 16; x++)
                    *(float4*)(dst + x * 4) =
                        make_float4(sc[x*4], sc[x*4+1], sc[x*4+2], sc[x*4+3]);
            }
            const u32* mp = (const u32*)&g_mask[b * SS + s0];
            u32 mk[64];
            float cm = -FLT_MAX;
            #pragma unroll
            for (int x = 0; x < 16; x++) {
                u32 mw = mp[x];
                mk[x*4] = mw & 255u; mk[x*4+1] = (mw >> 8) & 255u;
                mk[x*4+2] = (mw >> 16) & 255u; mk[x*4+3] = mw >> 24;
                if (mk[x*4])   cm = fmaxf(cm, sc[x*4]);
                if (mk[x*4+1]) cm = fmaxf(cm, sc[x*4+1]);
                if (mk[x*4+2]) cm = fmaxf(cm, sc[x*4+2]);
                if (mk[x*4+3]) cm = fmaxf(cm, sc[x*4+3]);
            }
            float m_new = fmaxf(m_old, cm);
            float alpha = (m_old == m_new) ? 1.f : __expf(m_old - m_new);
            float csum = 0.f;
            #pragma unroll
            for (int x = 0; x < 64; x++) {
                float p = mk[x] ? __expf(sc[x] - m_new) : 0.f;
                sc[x] = p; csum += p;
            }
            lsum = lsum * alpha + csum;
            m_old = m_new;
            Al[tid] = alpha;
            u32 ro = (u32)(tid * 72) * 2;
            #pragma unroll
            for (int u = 0; u < 8; u++) {
                u32 h0 = pkbf(sc[u*8], sc[u*8+1]), h1 = pkbf(sc[u*8+2], sc[u*8+3]);
                u32 h2 = pkbf(sc[u*8+4], sc[u*8+5]), h3 = pkbf(sc[u*8+6], sc[u*8+7]);
                float2 f0 = unbf(h0), f1 = unbf(h1), f2 = unbf(h2), f3 = unbf(h3);
                u32 l0 = pkbf(sc[u*8]-f0.x, sc[u*8+1]-f0.y), l1 = pkbf(sc[u*8+2]-f1.x, sc[u*8+3]-f1.y);
                u32 l2 = pkbf(sc[u*8+4]-f2.x, sc[u*8+5]-f2.y), l3 = pkbf(sc[u*8+6]-f3.x, sc[u*8+7]-f3.y);
                *(uint4*)(sm8 + O_PH + ro + u * 16) = make_uint4(h0, h1, h2, h3);
                *(uint4*)(sm8 + O_PL + ro + u * 16) = make_uint4(l0, l1, l2, l3);
            }
        }
        __syncthreads();
        // rescale running feat frags by per-row alpha, then PV accumulate
        {
            float a0 = Al[r0], a1 = Al[r0 + 8];
            #pragma unroll
            for (int cg = 0; cg < 8; cg++) {
                feat[cg][0] *= a0; feat[cg][1] *= a0;
                feat[cg][2] *= a1; feat[cg][3] *= a1;
            }
            u32 arow = 16 * w + (lane & 7) + ((lane >> 3) & 1) * 8;
            u32 acol = ((lane >> 4) & 1) * 8;
            u32 phf[4][4], plf[4][4];
            #pragma unroll
            for (int k = 0; k < 4; k++) {
                ldmx4(phf[k], SB + O_PH + (arow * 72 + acol + 16 * k) * 2);
                ldmx4(plf[k], SB + O_PL + (arow * 72 + acol + 16 * k) * 2);
            }
            #pragma unroll
            for (int cg = 0; cg < 8; cg++) {
                #pragma unroll
                for (int k = 0; k < 4; k++) {
                    u32 off = ((cg * 8 + brow) * 72 + 16 * k + bc8) * 2;
                    u32 bh[2], bl[2];
                    ldmx2(bh, SB + O_VH + off);
                    ldmx2(bl, SB + O_VL + off);
                    mma16816(feat[cg], phf[k], bh);
                    mma16816(feat[cg], phf[k], bl);
                    mma16816(feat[cg], plf[k], bh);
                }
            }
        }
        __syncthreads();
    }

    // epilogue: frags -> Sc, then row threads gate+store
    #pragma unroll
    for (int cg = 0; cg < 8; cg++) {
        *(float2*)&Sc[r0 * 68 + cg * 8 + cc0] = make_float2(feat[cg][0], feat[cg][1]);
        *(float2*)&Sc[(r0 + 8) * 68 + cg * 8 + cc0] = make_float2(feat[cg][2], feat[cg][3]);
    }
    __syncthreads();
    if (tid < cnt) {
        float inv = 1.f / (lsum + 1e-9f);
        const float* gp = &g_gate[(size_t)(n0 + tid) * HA + h * AA];
        float* fp = &g_feat[(size_t)(n0 + tid) * HA + h * AA];
        const float* sr = &Sc[tid * 68];
        #pragma unroll
        for (int x = 0; x < 16; x++) {
            float4 v = *(const float4*)(sr + x * 4);
            float4 g = *(const float4*)(gp + x * 4);
            *(float4*)(fp + x * 4) =
                make_float4(v.x * inv * g.x, v.y * inv * g.y, v.z * inv * g.z, v.w * inv * g.w);
        }
    }
}

// ---------------- logits = sc0 + sc1 ---------------------------------------
__global__ void addlog_k(float* __restrict__ logits) {
    size_t i = ((size_t)blockIdx.x * 256 + threadIdx.x) * 4;
    float4 a = *(const float4*)&g_sc0[i];
    float4 b4 = *(const float4*)&g_sc1[i];
    *(float4*)&logits[i] = make_float4(a.x + b4.x, a.y + b4.y, a.z + b4.z, a.w + b4.w);
}

// ---------------- y = sqrt(2)*x + gatedfeat @ Wback + bback ----------------
__global__ void __launch_bounds__(256) back_k(const float* __restrict__ x,
                                              const float* __restrict__ Wback,
                                              const float* __restrict__ bback) {
    __shared__ float As[16][68];
    __shared__ float Bs[16][64];
    int tid = threadIdx.x, tx = tid & 15, ty = tid >> 4;
    int m0 = blockIdx.x * 64, n0 = blockIdx.y * 64;
    ull acc[4][2] = {};
    int lm = tid >> 2, lk = (tid & 3) * 4;
    int bk = tid >> 4, bn = (tid & 15) * 4;
    for (int k0 = 0; k0 < HA; k0 += 16) {
        float4 a = *(const float4*)&g_feat[(size_t)(m0 + lm) * HA + k0 + lk];
        As[lk + 0][lm] = a.x; As[lk + 1][lm] = a.y; As[lk + 2][lm] = a.z; As[lk + 3][lm] = a.w;
        *(float4*)&Bs[bk][bn] = *(const float4*)&Wback[(size_t)(k0 + bk) * IFZ + n0 + bn];
        __syncthreads();
        #pragma unroll
        for (int kk = 0; kk < 16; kk++)
            fma8x2(acc, *(float4*)&As[kk][ty * 4], &Bs[kk][tx * 4]);
        __syncthreads();
    }
    const float rt2 = 1.41421356237309515f;
    float4 bb = *(const float4*)&bback[n0 + tx * 4];
    #pragma unroll
    for (int i = 0; i < 4; i++) {
        int row = m0 + ty * 4 + i;
        float4 xv = *(const float4*)&x[(size_t)row * IFZ + n0 + tx * 4];
        float4 cc = row4(acc[i][0], acc[i][1]);
        float4 ov;
        ov.x = rt2 * xv.x + cc.x + bb.x;
        ov.y = rt2 * xv.y + cc.y + bb.y;
        ov.z = rt2 * xv.z + cc.z + bb.z;
        ov.w = rt2 * xv.w + cc.w + bb.w;
        *(float4*)&g_y[(size_t)row * IFZ + n0 + tx * 4] = ov;
    }
}

// ---------------- LayerNorm ------------------------------------------------
__global__ void __launch_bounds__(256) ln_k(const float* __restrict__ gamma,
                                            const float* __restrict__ beta,
                                            float* __restrict__ out) {
    int warp = threadIdx.x >> 5, lane = threadIdx.x & 31;
    int row = blockIdx.x * 8 + warp;
    float4 v0 = *(const float4*)&g_y[(size_t)row * IFZ + lane * 4];
    float4 v1 = *(const float4*)&g_y[(size_t)row * IFZ + 128 + lane * 4];
    float s = v0.x + v0.y + v0.z + v0.w + v1.x + v1.y + v1.z + v1.w;
    #pragma unroll
    for (int d = 16; d; d >>= 1) s += __shfl_xor_sync(0xffffffffu, s, d);
    float mu = s * (1.f / 256.f);
    float q = 0.f;
    q += (v0.x - mu) * (v0.x - mu); q += (v0.y - mu) * (v0.y - mu);
    q += (v0.z - mu) * (v0.z - mu); q += (v0.w - mu) * (v0.w - mu);
    q += (v1.x - mu) * (v1.x - mu); q += (v1.y - mu) * (v1.y - mu);
    q += (v1.z - mu) * (v1.z - mu); q += (v1.w - mu) * (v1.w - mu);
    #pragma unroll
    for (int d = 16; d; d >>= 1) q += __shfl_xor_sync(0xffffffffu, q, d);
    float inv = rsqrtf(q * (1.f / 256.f) + 1e-5f);
    float4 g0 = *(const float4*)&gamma[lane * 4];
    float4 b0 = *(const float4*)&beta[lane * 4];
    float4 g1 = *(const float4*)&gamma[128 + lane * 4];
    float4 b1 = *(const float4*)&beta[128 + lane * 4];
    float4 o0, o1;
    o0.x = (v0.x - mu) * inv * g0.x + b0.x;
    o0.y = (v0.y - mu) * inv * g0.y + b0.y;
    o0.z = (v0.z - mu) * inv * g0.z + b0.z;
    o0.w = (v0.w - mu) * inv * g0.w + b0.w;
    o1.x = (v1.x - mu) * inv * g1.x + b1.x;
    o1.y = (v1.y - mu) * inv * g1.y + b1.y;
    o1.z = (v1.z - mu) * inv * g1.z + b1.z;
    o1.w = (v1.w - mu) * inv * g1.w + b1.w;
    *(float4*)&out[(size_t)row * IFZ + lane * 4] = o0;
    *(float4*)&out[(size_t)row * IFZ + 128 + lane * 4] = o1;
}

// ---------------- launch ---------------------------------------------------
extern "C" void kernel_launch(void* const* d_in, const int* in_sizes, int n_in,
                              void* d_out, int out_size) {
    const float* x     = (const float*)d_in[0];
    const float* emb   = (const float*)d_in[1];
    const void*  mask  = d_in[2];
    const void*  batch = d_in[3];
    const float* Wq    = (const float*)d_in[4];
    const float* Wk    = (const float*)d_in[5];
    const float* Wv    = (const float*)d_in[6];
    const float* Wg    = (const float*)d_in[7];
    const float* bg    = (const float*)d_in[8];
    const float* Wback = (const float*)d_in[9];
    const float* bback = (const float*)d_in[10];
    const float* gamma = (const float*)d_in[11];
    const float* beta  = (const float*)d_in[12];
    float* out    = (float*)d_out;
    float* logits = out + (size_t)NN * IFZ;

    static int smem_set = 0;
    if (!smem_set) {
        cudaFuncSetAttribute(attn_mma, cudaFuncAttributeMaxDynamicSharedMemorySize,
                             ATTN_SMEMB);
        smem_set = 1;
    }

    prep_k<<<1, 256>>>(mask, batch);
    proj_qg_k<<<dim3(32, 16), 256>>>(x, Wq, Wg, bg);
    proj_kv_k<<<dim3(64, 16), 256>>>(emb, Wk, Wv);
    conv_k_k<<<2048, 256>>>();
    conv_v_k<<<dim3(16, HH, BBATCH), 128>>>();
    attn_mma<<<dim3(MAXT, HH), 128, ATTN_SMEMB>>>();
    addlog_k<<<2048, 256>>>(logits);
    back_k<<<dim3(32, 4), 256>>>(x, Wback, bback);
    ln_k<<<256, 256>>>(gamma, beta, out);
}

// round 11
// speedup vs baseline: 1.3397x; 1.0961x over previous
#include <cuda_runtime.h>
#include <cuda_bf16.h>
#include <float.h>
#include <math.h>

#define NN   2048
#define BBATCH 4
#define SS   1024
#define SFZ  384
#define IFZ  256
#define HH   8
#define AA   64
#define HA   512
#define MAXT 36

typedef unsigned long long ull;
typedef unsigned int u32;

__device__ __align__(16) float g_q[NN * HA];
__device__ __align__(16) float g_gate[NN * HA];
__device__ __align__(16) float g_k[BBATCH * SS * HA];
__device__ __align__(16) float g_v[BBATCH * SS * HA];
__device__ __align__(16) float g_feat[NN * HA];
__device__ __align__(16) float g_y[NN * IFZ];
__device__ __align__(16) unsigned char g_mask[BBATCH * SS];
__device__ int g_tb[MAXT], g_ts[MAXT], g_tc[MAXT], g_nt;
__device__ __align__(16) __nv_bfloat16 g_kh[BBATCH * SS * HA];
__device__ __align__(16) __nv_bfloat16 g_kl[BBATCH * SS * HA];
__device__ __align__(16) __nv_bfloat16 g_vh[BBATCH * HH * AA * SS];
__device__ __align__(16) __nv_bfloat16 g_vl[BBATCH * HH * AA * SS];
__device__ __align__(16) float g_sc0[NN * SS];
__device__ __align__(16) float g_sc1[NN * SS];
// emb + transposed-W bf16 hi/lo for proj_kv_mma
__device__ __align__(16) __nv_bfloat16 g_eh[BBATCH * SS * SFZ];
__device__ __align__(16) __nv_bfloat16 g_el[BBATCH * SS * SFZ];
__device__ __align__(16) __nv_bfloat16 g_wht[2 * HA * SFZ];
__device__ __align__(16) __nv_bfloat16 g_wlt[2 * HA * SFZ];

// ---- fp32 packed helpers ----
__device__ __forceinline__ void ffma2(ull &d, ull a, ull b) {
    asm("fma.rn.f32x2 %0, %1, %2, %0;" : "+l"(d) : "l"(a), "l"(b));
}
__device__ __forceinline__ ull pk2(float lo, float hi) {
    ull r; asm("mov.b64 %0, {%1, %2};" : "=l"(r) : "f"(lo), "f"(hi)); return r;
}
__device__ __forceinline__ float2 upk2(ull v) {
    float2 r; asm("mov.b64 {%0, %1}, %2;" : "=f"(r.x), "=f"(r.y) : "l"(v)); return r;
}
__device__ __forceinline__ void fma8x2(ull (&acc)[4][2], float4 a, const float* bp) {
    ull b0 = *(const ull*)bp, b1 = *(const ull*)(bp + 2);
    ull a0 = pk2(a.x, a.x), a1 = pk2(a.y, a.y), a2 = pk2(a.z, a.z), a3 = pk2(a.w, a.w);
    ffma2(acc[0][0], a0, b0); ffma2(acc[0][1], a0, b1);
    ffma2(acc[1][0], a1, b0); ffma2(acc[1][1], a1, b1);
    ffma2(acc[2][0], a2, b0); ffma2(acc[2][1], a2, b1);
    ffma2(acc[3][0], a3, b0); ffma2(acc[3][1], a3, b1);
}
__device__ __forceinline__ float4 row4(ull p0, ull p1) {
    float2 a = upk2(p0), b = upk2(p1);
    return make_float4(a.x, a.y, b.x, b.y);
}

// ---- bf16 split helpers ----
__device__ __forceinline__ u32 pkbf(float a, float b) {
    __nv_bfloat162 t = __float22bfloat162_rn(make_float2(a, b));
    return *(u32*)&t;
}
__device__ __forceinline__ float2 unbf(u32 h) {
    return __bfloat1622float2(*(__nv_bfloat162*)&h);
}

// ---- ldmatrix + mma.sync (baseline PTX, sm_80+) ----
static __device__ __forceinline__ u32 s2u(const void* p) {
    u32 a; asm("{.reg .u64 t; cvta.to.shared.u64 t, %1; cvt.u32.u64 %0, t;}" : "=r"(a) : "l"(p));
    return a;
}
__device__ __forceinline__ void ldmx4(u32* r, u32 a) {
    asm volatile("ldmatrix.sync.aligned.m8n8.x4.shared.b16 {%0,%1,%2,%3},[%4];"
                 : "=r"(r[0]), "=r"(r[1]), "=r"(r[2]), "=r"(r[3]) : "r"(a));
}
__device__ __forceinline__ void ldmx2(u32* r, u32 a) {
    asm volatile("ldmatrix.sync.aligned.m8n8.x2.shared.b16 {%0,%1},[%2];"
                 : "=r"(r[0]), "=r"(r[1]) : "r"(a));
}
__device__ __forceinline__ void mma16816(float* d, const u32* a, const u32* bb) {
    asm volatile("mma.sync.aligned.m16n8k16.row.col.f32.bf16.bf16.f32 "
                 "{%0,%1,%2,%3},{%4,%5,%6,%7},{%8,%9},{%0,%1,%2,%3};"
                 : "+f"(d[0]), "+f"(d[1]), "+f"(d[2]), "+f"(d[3])
                 : "r"(a[0]), "r"(a[1]), "r"(a[2]), "r"(a[3]), "r"(bb[0]), "r"(bb[1]));
}

// attn smem byte offsets
#define O_QH 0
#define O_QL 9216
#define O_KH 18432
#define O_KL 27648
#define O_VH 36864
#define O_VL 46080
#define O_PH 55296
#define O_PL 64512
#define O_SC 73728
#define O_AL (O_SC + 64 * 68 * 4)
#define ATTN_SMEMB (O_AL + 256)

// ---------------- prep ------------------------------------------------------
__global__ void prep_k(const void* mask_in, const void* batch_in) {
    __shared__ int flg[2];
    __shared__ int cnt[BBATCH];
    int tid = threadIdx.x;
    if (tid < 2) flg[tid] = 0;
    if (tid < BBATCH) cnt[tid] = 0;
    __syncthreads();
    const unsigned int* bw = (const unsigned int*)batch_in;
    unsigned int o = 0;
    for (int i = tid * 2 + 1; i < NN; i += blockDim.x * 2) o |= bw[i];
    if (o) atomicOr(&flg[0], 1);
    const unsigned char* mb = (const unsigned char*)mask_in;
    int f = 0;
    for (int i = tid; i < BBATCH * SS; i += blockDim.x)
        if ((i & 3) && mb[i]) f = 1;
    if (f) atomicOr(&flg[1], 1);
    __syncthreads();
    int is32 = flg[0], isb = flg[1];
    int lc[BBATCH] = {0, 0, 0, 0};
    for (int i = tid; i < NN; i += blockDim.x) {
        int v = is32 ? ((const int*)batch_in)[i]
                     : (int)((const long long*)batch_in)[i];
        lc[v & 3]++;
    }
    #pragma unroll
    for (int b = 0; b < BBATCH; b++) if (lc[b]) atomicAdd(&cnt[b], lc[b]);
    for (int i = tid; i < BBATCH * SS; i += blockDim.x)
        g_mask[i] = isb ? (mb[i] ? 1 : 0) : (((const int*)mask_in)[i] ? 1 : 0);
    __syncthreads();
    if (tid == 0) {
        int st = 0, t = 0;
        for (int b = 0; b < BBATCH; b++) {
            int e = st + cnt[b];
            for (int s = st; s < e; s += 64) {
                g_tb[t] = b; g_ts[t] = s; g_tc[t] = min(64, e - s); t++;
            }
            st = e;
        }
        g_nt = t;
    }
}

// ---------------- q = x@Wq ; gate = sigmoid(x@Wg + bg) ---------------------
__global__ void __launch_bounds__(256) proj_qg_k(const float* __restrict__ x,
                                                 const float* __restrict__ Wq,
                                                 const float* __restrict__ Wg,
                                                 const float* __restrict__ bg) {
    __shared__ float As[16][68];
    __shared__ float Bs[16][64];
    int tid = threadIdx.x, tx = tid & 15, ty = tid >> 4;
    int m0 = blockIdx.x * 64, n0 = blockIdx.y * 64;
    bool isg = (n0 >= HA);
    const float* W = isg ? Wg : Wq;
    int nc0 = isg ? (n0 - HA) : n0;
    ull acc[4][2] = {};
    int lm = tid >> 2, lk = (tid & 3) * 4;
    int bk = tid >> 4, bn = (tid & 15) * 4;
    for (int k0 = 0; k0 < IFZ; k0 += 16) {
        float4 a = *(const float4*)(x + (size_t)(m0 + lm) * IFZ + k0 + lk);
        As[lk + 0][lm] = a.x; As[lk + 1][lm] = a.y; As[lk + 2][lm] = a.z; As[lk + 3][lm] = a.w;
        *(float4*)&Bs[bk][bn] = *(const float4*)(W + (size_t)(k0 + bk) * HA + nc0 + bn);
        __syncthreads();
        #pragma unroll
        for (int kk = 0; kk < 16; kk++)
            fma8x2(acc, *(float4*)&As[kk][ty * 4], &Bs[kk][tx * 4]);
        __syncthreads();
    }
    if (isg) {
        float4 bgv = *(const float4*)(bg + nc0 + tx * 4);
        #pragma unroll
        for (int i = 0; i < 4; i++) {
            int row = m0 + ty * 4 + i;
            float4 c = row4(acc[i][0], acc[i][1]);
            float4 ov;
            ov.x = 1.0f / (1.0f + __expf(-(c.x + bgv.x)));
            ov.y = 1.0f / (1.0f + __expf(-(c.y + bgv.y)));
            ov.z = 1.0f / (1.0f + __expf(-(c.z + bgv.z)));
            ov.w = 1.0f / (1.0f + __expf(-(c.w + bgv.w)));
            *(float4*)&g_gate[(size_t)row * HA + nc0 + tx * 4] = ov;
        }
    } else {
        #pragma unroll
        for (int i = 0; i < 4; i++) {
            int row = m0 + ty * 4 + i;
            *(float4*)&g_q[(size_t)row * HA + nc0 + tx * 4] = row4(acc[i][0], acc[i][1]);
        }
    }
}

// ---------------- emb -> bf16 hi/lo ----------------------------------------
__global__ void conv_e_k(const float* __restrict__ emb) {
    size_t i = ((size_t)blockIdx.x * 256 + threadIdx.x) * 4;
    float4 v = *(const float4*)&emb[i];
    u32 h0 = pkbf(v.x, v.y), h1 = pkbf(v.z, v.w);
    float2 f0 = unbf(h0), f1 = unbf(h1);
    u32 l0 = pkbf(v.x - f0.x, v.y - f0.y), l1 = pkbf(v.z - f1.x, v.w - f1.y);
    *(uint2*)&g_eh[i] = make_uint2(h0, h1);
    *(uint2*)&g_el[i] = make_uint2(l0, l1);
}

// ---------------- Wk/Wv -> transposed [n][k] bf16 hi/lo --------------------
__global__ void __launch_bounds__(128) conv_w_k(const float* __restrict__ Wk,
                                                const float* __restrict__ Wv) {
    __shared__ float buf[64 * 68];
    int kc = blockIdx.x * 64;          // k tile (0..5)
    int ng = blockIdx.y * 64;          // global n tile over 1024
    const float* W = (ng < HA) ? Wk : Wv;
    int nb = ng & (HA - 1);
    int tid = threadIdx.x;
    #pragma unroll
    for (int p = 0; p < 8; p++) {
        int idx = tid + p * 128, kk = idx >> 4, nn = (idx & 15) * 4;
        *(float4*)&buf[kk * 68 + nn] =
            *(const float4*)&W[(size_t)(kc + kk) * HA + nb + nn];
    }
    __syncthreads();
    int nn = tid >> 1, kh = (tid & 1) * 32;
    u32 hv[16], lv[16];
    #pragma unroll
    for (int p = 0; p < 16; p++) {
        float x0 = buf[(kh + 2 * p) * 68 + nn], x1 = buf[(kh + 2 * p + 1) * 68 + nn];
        hv[p] = pkbf(x0, x1);
        float2 f = unbf(hv[p]);
        lv[p] = pkbf(x0 - f.x, x1 - f.y);
    }
    size_t o = (size_t)(ng + nn) * SFZ + kc + kh;
    #pragma unroll
    for (int p = 0; p < 4; p++) {
        *(uint4*)&g_wht[o + p * 8] = make_uint4(hv[4*p], hv[4*p+1], hv[4*p+2], hv[4*p+3]);
        *(uint4*)&g_wlt[o + p * 8] = make_uint4(lv[4*p], lv[4*p+1], lv[4*p+2], lv[4*p+3]);
    }
}

// ---------------- k,v = emb @ Wk/Wv : mma.sync bf16 3-term -----------------
__global__ void __launch_bounds__(128) proj_kv_mma() {
    __shared__ __align__(16) unsigned char sm[36864];   // AH AL BH BL, 9216 each
    const u32 SB = s2u(sm);
    int m0 = blockIdx.x * 64, ng = blockIdx.y * 64;
    int tid = threadIdx.x, lane = tid & 31, w = tid >> 5;
    const int lr = lane & 15;
    const u32 brow = lr & 7, bc8 = (lr >> 3) * 8;
    const int r0 = 16 * w + (lane >> 2), cc0 = (lane & 3) * 2;
    u32 arow = 16 * w + (lane & 7) + ((lane >> 3) & 1) * 8;
    u32 acol = ((lane >> 4) & 1) * 8;
    float acc[8][4];
    #pragma unroll
    for (int cg = 0; cg < 8; cg++)
        acc[cg][0] = acc[cg][1] = acc[cg][2] = acc[cg][3] = 0.f;

    int r = tid >> 1, kh2 = (tid & 1) * 32;
    for (int kc = 0; kc < 6; kc++) {
        int k0 = kc * 64;
        {   // stage A (emb rows) and B (W^T rows), hi+lo
            size_t ea = (size_t)(m0 + r) * SFZ + k0 + kh2;
            size_t wa = (size_t)(ng + r) * SFZ + k0 + kh2;
            u32 ro = (u32)(r * 72 + kh2) * 2;
            #pragma unroll
            for (int u = 0; u < 4; u++) {
                *(uint4*)(sm + 0     + ro + u * 16) = *(const uint4*)(&g_eh[ea] + u * 8);
                *(uint4*)(sm + 9216  + ro + u * 16) = *(const uint4*)(&g_el[ea] + u * 8);
                *(uint4*)(sm + 18432 + ro + u * 16) = *(const uint4*)(&g_wht[wa] + u * 8);
                *(uint4*)(sm + 27648 + ro + u * 16) = *(const uint4*)(&g_wlt[wa] + u * 8);
            }
        }
        __syncthreads();
        u32 ahf[4][4], alf[4][4];
        #pragma unroll
        for (int k = 0; k < 4; k++) {
            ldmx4(ahf[k], SB + 0    + (arow * 72 + acol + 16 * k) * 2);
            ldmx4(alf[k], SB + 9216 + (arow * 72 + acol + 16 * k) * 2);
        }
        #pragma unroll
        for (int cg = 0; cg < 8; cg++) {
            #pragma unroll
            for (int k = 0; k < 4; k++) {
                u32 off = ((cg * 8 + brow) * 72 + 16 * k + bc8) * 2;
                u32 bh[2], bl[2];
                ldmx2(bh, SB + 18432 + off);
                ldmx2(bl, SB + 27648 + off);
                mma16816(acc[cg], ahf[k], bh);
                mma16816(acc[cg], ahf[k], bl);
                mma16816(acc[cg], alf[k], bh);
            }
        }
        __syncthreads();
    }
    bool isv = (ng >= HA);
    float* C = isv ? g_v : g_k;
    int nc0 = ng & (HA - 1);
    #pragma unroll
    for (int cg = 0; cg < 8; cg++) {
        *(float2*)&C[(size_t)(m0 + r0) * HA + nc0 + cg * 8 + cc0] =
            make_float2(acc[cg][0], acc[cg][1]);
        *(float2*)&C[(size_t)(m0 + r0 + 8) * HA + nc0 + cg * 8 + cc0] =
            make_float2(acc[cg][2], acc[cg][3]);
    }
}

// ---------------- K -> bf16 hi/lo ------------------------------------------
__global__ void conv_k_k() {
    size_t i = ((size_t)blockIdx.x * 256 + threadIdx.x) * 4;
    float4 v = *(const float4*)&g_k[i];
    u32 h0 = pkbf(v.x, v.y), h1 = pkbf(v.z, v.w);
    float2 f0 = unbf(h0), f1 = unbf(h1);
    u32 l0 = pkbf(v.x - f0.x, v.y - f0.y), l1 = pkbf(v.z - f1.x, v.w - f1.y);
    *(uint2*)&g_kh[i] = make_uint2(h0, h1);
    *(uint2*)&g_kl[i] = make_uint2(l0, l1);
}

// ---------------- V -> transposed [b][h][a][s] bf16 hi/lo ------------------
__global__ void __launch_bounds__(128) conv_v_k() {
    __shared__ float buf[64 * 68];
    int b = blockIdx.z, h = blockIdx.y, s0 = blockIdx.x * 64;
    int tid = threadIdx.x;
    #pragma unroll
    for (int p = 0; p < 8; p++) {
        int idx = tid + p * 128, s = idx >> 4, q = idx & 15;
        *(float4*)&buf[s * 68 + q * 4] =
            *(const float4*)&g_v[((size_t)(b << 10) + s0 + s) * HA + h * AA + q * 4];
    }
    __syncthreads();
    int aa = tid >> 1, sh = (tid & 1) * 32;
    u32 hv[16], lv[16];
    #pragma unroll
    for (int p = 0; p < 16; p++) {
        float x0 = buf[(sh + 2 * p) * 68 + aa], x1 = buf[(sh + 2 * p + 1) * 68 + aa];
        hv[p] = pkbf(x0, x1);
        float2 f = unbf(hv[p]);
        lv[p] = pkbf(x0 - f.x, x1 - f.y);
    }
    size_t o = ((size_t)(b * HH + h) * AA + aa) * SS + s0 + sh;
    #pragma unroll
    for (int p = 0; p < 4; p++) {
        *(uint4*)&g_vh[o + p * 8] = make_uint4(hv[4*p], hv[4*p+1], hv[4*p+2], hv[4*p+3]);
        *(uint4*)&g_vl[o + p * 8] = make_uint4(lv[4*p], lv[4*p+1], lv[4*p+2], lv[4*p+3]);
    }
}

// ---------------- attention: mma.sync bf16 3-term, one-pass flash ----------
__global__ void __launch_bounds__(128) attn_mma() {
    extern __shared__ unsigned char sm8[];
    const int t = blockIdx.x;
    if (t >= g_nt) return;
    const int h = blockIdx.y;
    const int b = g_tb[t], n0 = g_ts[t], cnt = g_tc[t];
    const int tid = threadIdx.x, lane = tid & 31, w = tid >> 5;
    const u32 SB = s2u(sm8);
    float* Sc = (float*)(sm8 + O_SC);
    float* Al = (float*)(sm8 + O_AL);

    {
        int i = tid >> 1, ah = (tid & 1) * 32;
        bool val = i < cnt;
        const float* q = &g_q[(size_t)(n0 + i) * HA + h * AA + ah];
        u32 ro = (u32)(i * 72 + ah) * 2;
        #pragma unroll
        for (int u = 0; u < 4; u++) {
            float4 x0 = val ? *(const float4*)(q + u * 8) : make_float4(0, 0, 0, 0);
            float4 x1 = val ? *(const float4*)(q + u * 8 + 4) : make_float4(0, 0, 0, 0);
            u32 h0 = pkbf(x0.x, x0.y), h1 = pkbf(x0.z, x0.w);
            u32 h2 = pkbf(x1.x, x1.y), h3 = pkbf(x1.z, x1.w);
            float2 f0 = unbf(h0), f1 = unbf(h1), f2 = unbf(h2), f3 = unbf(h3);
            u32 l0 = pkbf(x0.x - f0.x, x0.y - f0.y), l1 = pkbf(x0.z - f1.x, x0.w - f1.y);
            u32 l2 = pkbf(x1.x - f2.x, x1.y - f2.y), l3 = pkbf(x1.z - f3.x, x1.w - f3.y);
            *(uint4*)(sm8 + O_QH + ro + u * 16) = make_uint4(h0, h1, h2, h3);
            *(uint4*)(sm8 + O_QL + ro + u * 16) = make_uint4(l0, l1, l2, l3);
        }
    }
    __syncthreads();

    u32 qhf[4][4], qlf[4][4];
    {
        u32 arow = 16 * w + (lane & 7) + ((lane >> 3) & 1) * 8;
        u32 acol = ((lane >> 4) & 1) * 8;
        #pragma unroll
        for (int k = 0; k < 4; k++) {
            ldmx4(qhf[k], SB + O_QH + (arow * 72 + acol + 16 * k) * 2);
            ldmx4(qlf[k], SB + O_QL + (arow * 72 + acol + 16 * k) * 2);
        }
    }

    const int lr = lane & 15;
    const u32 brow = lr & 7, bc8 = (lr >> 3) * 8;
    const int r0 = 16 * w + (lane >> 2), cc0 = (lane & 3) * 2;
    float m_old = -FLT_MAX, lsum = 0.f;
    float feat[8][4];
    #pragma unroll
    for (int cg = 0; cg < 8; cg++)
        feat[cg][0] = feat[cg][1] = feat[cg][2] = feat[cg][3] = 0.f;

    for (int s0 = 0; s0 < SS; s0 += 64) {
        {
            int j = tid >> 1, ah = (tid & 1) * 32;
            size_t kr = ((size_t)(b << 10) + s0 + j) * HA + h * AA + ah;
            size_t vr = ((size_t)(b * HH + h) * AA + j) * SS + s0 + ah;
            u32 ro = (u32)(j * 72 + ah) * 2;
            #pragma unroll
            for (int u = 0; u < 4; u++) {
                *(uint4*)(sm8 + O_KH + ro + u * 16) = *(const uint4*)(&g_kh[kr] + u * 8);
                *(uint4*)(sm8 + O_KL + ro + u * 16) = *(const uint4*)(&g_kl[kr] + u * 8);
                *(uint4*)(sm8 + O_VH + ro + u * 16) = *(const uint4*)(&g_vh[vr] + u * 8);
                *(uint4*)(sm8 + O_VL + ro + u * 16) = *(const uint4*)(&g_vl[vr] + u * 8);
            }
        }
        __syncthreads();
        #pragma unroll
        for (int cg = 0; cg < 8; cg++) {
            float d[4] = {0.f, 0.f, 0.f, 0.f};
            #pragma unroll
            for (int k = 0; k < 4; k++) {
                u32 off = ((cg * 8 + brow) * 72 + 16 * k + bc8) * 2;
                u32 bh[2], bl[2];
                ldmx2(bh, SB + O_KH + off);
                ldmx2(bl, SB + O_KL + off);
                mma16816(d, qhf[k], bh);
                mma16816(d, qhf[k], bl);
                mma16816(d, qlf[k], bh);
            }
            *(float2*)&Sc[r0 * 68 + cg * 8 + cc0] = make_float2(d[0], d[1]);
            *(float2*)&Sc[(r0 + 8) * 68 + cg * 8 + cc0] = make_float2(d[2], d[3]);
        }
        __syncthreads();
        if (tid < 64) {
            float sc[64];
            const float* sr = &Sc[tid * 68];
            #pragma unroll
            for (int x = 0; x < 16; x++) {
                float4 v = *(const float4*)(sr + x * 4);
                sc[x*4] = v.x * 0.125f; sc[x*4+1] = v.y * 0.125f;
                sc[x*4+2] = v.z * 0.125f; sc[x*4+3] = v.w * 0.125f;
            }
            if (h < 2 && tid < cnt) {
                float* dst = (h == 0 ? g_sc0 : g_sc1) + (size_t)(n0 + tid) * SS + s0;
                #pragma unroll
                for (int x = 0; x < 16; x++)
                    *(float4*)(dst + x * 4) =
                        make_float4(sc[x*4], sc[x*4+1], sc[x*4+2], sc[x*4+3]);
            }
            const u32* mp = (const u32*)&g_mask[b * SS + s0];
            u32 mk[64];
            float cm = -FLT_MAX;
            #pragma unroll
            for (int x = 0; x < 16; x++) {
                u32 mw = mp[x];
                mk[x*4] = mw & 255u; mk[x*4+1] = (mw >> 8) & 255u;
                mk[x*4+2] = (mw >> 16) & 255u; mk[x*4+3] = mw >> 24;
                if (mk[x*4])   cm = fmaxf(cm, sc[x*4]);
                if (mk[x*4+1]) cm = fmaxf(cm, sc[x*4+1]);
                if (mk[x*4+2]) cm = fmaxf(cm, sc[x*4+2]);
                if (mk[x*4+3]) cm = fmaxf(cm, sc[x*4+3]);
            }
            float m_new = fmaxf(m_old, cm);
            float alpha = (m_old == m_new) ? 1.f : __expf(m_old - m_new);
            float csum = 0.f;
            #pragma unroll
            for (int x = 0; x < 64; x++) {
                float p = mk[x] ? __expf(sc[x] - m_new) : 0.f;
                sc[x] = p; csum += p;
            }
            lsum = lsum * alpha + csum;
            m_old = m_new;
            Al[tid] = alpha;
            u32 ro = (u32)(tid * 72) * 2;
            #pragma unroll
            for (int u = 0; u < 8; u++) {
                u32 h0 = pkbf(sc[u*8], sc[u*8+1]), h1 = pkbf(sc[u*8+2], sc[u*8+3]);
                u32 h2 = pkbf(sc[u*8+4], sc[u*8+5]), h3 = pkbf(sc[u*8+6], sc[u*8+7]);
                float2 f0 = unbf(h0), f1 = unbf(h1), f2 = unbf(h2), f3 = unbf(h3);
                u32 l0 = pkbf(sc[u*8]-f0.x, sc[u*8+1]-f0.y), l1 = pkbf(sc[u*8+2]-f1.x, sc[u*8+3]-f1.y);
                u32 l2 = pkbf(sc[u*8+4]-f2.x, sc[u*8+5]-f2.y), l3 = pkbf(sc[u*8+6]-f3.x, sc[u*8+7]-f3.y);
                *(uint4*)(sm8 + O_PH + ro + u * 16) = make_uint4(h0, h1, h2, h3);
                *(uint4*)(sm8 + O_PL + ro + u * 16) = make_uint4(l0, l1, l2, l3);
            }
        }
        __syncthreads();
        {
            float a0 = Al[r0], a1 = Al[r0 + 8];
            #pragma unroll
            for (int cg = 0; cg < 8; cg++) {
                feat[cg][0] *= a0; feat[cg][1] *= a0;
                feat[cg][2] *= a1; feat[cg][3] *= a1;
            }
            u32 arow = 16 * w + (lane & 7) + ((lane >> 3) & 1) * 8;
            u32 acol = ((lane >> 4) & 1) * 8;
            u32 phf[4][4], plf[4][4];
            #pragma unroll
            for (int k = 0; k < 4; k++) {
                ldmx4(phf[k], SB + O_PH + (arow * 72 + acol + 16 * k) * 2);
                ldmx4(plf[k], SB + O_PL + (arow * 72 + acol + 16 * k) * 2);
            }
            #pragma unroll
            for (int cg = 0; cg < 8; cg++) {
                #pragma unroll
                for (int k = 0; k < 4; k++) {
                    u32 off = ((cg * 8 + brow) * 72 + 16 * k + bc8) * 2;
                    u32 bh[2], bl[2];
                    ldmx2(bh, SB + O_VH + off);
                    ldmx2(bl, SB + O_VL + off);
                    mma16816(feat[cg], phf[k], bh);
                    mma16816(feat[cg], phf[k], bl);
                    mma16816(feat[cg], plf[k], bh);
                }
            }
        }
        __syncthreads();
    }

    #pragma unroll
    for (int cg = 0; cg < 8; cg++) {
        *(float2*)&Sc[r0 * 68 + cg * 8 + cc0] = make_float2(feat[cg][0], feat[cg][1]);
        *(float2*)&Sc[(r0 + 8) * 68 + cg * 8 + cc0] = make_float2(feat[cg][2], feat[cg][3]);
    }
    __syncthreads();
    if (tid < cnt) {
        float inv = 1.f / (lsum + 1e-9f);
        const float* gp = &g_gate[(size_t)(n0 + tid) * HA + h * AA];
        float* fp = &g_feat[(size_t)(n0 + tid) * HA + h * AA];
        const float* sr = &Sc[tid * 68];
        #pragma unroll
        for (int x = 0; x < 16; x++) {
            float4 v = *(const float4*)(sr + x * 4);
            float4 g = *(const float4*)(gp + x * 4);
            *(float4*)(fp + x * 4) =
                make_float4(v.x * inv * g.x, v.y * inv * g.y, v.z * inv * g.z, v.w * inv * g.w);
        }
    }
}

// ---------------- logits = sc0 + sc1 ---------------------------------------
__global__ void addlog_k(float* __restrict__ logits) {
    size_t i = ((size_t)blockIdx.x * 256 + threadIdx.x) * 4;
    float4 a = *(const float4*)&g_sc0[i];
    float4 b4 = *(const float4*)&g_sc1[i];
    *(float4*)&logits[i] = make_float4(a.x + b4.x, a.y + b4.y, a.z + b4.z, a.w + b4.w);
}

// ---------------- y = sqrt(2)*x + gatedfeat @ Wback + bback ----------------
__global__ void __launch_bounds__(256) back_k(const float* __restrict__ x,
                                              const float* __restrict__ Wback,
                                              const float* __restrict__ bback) {
    __shared__ float As[16][68];
    __shared__ float Bs[16][64];
    int tid = threadIdx.x, tx = tid & 15, ty = tid >> 4;
    int m0 = blockIdx.x * 64, n0 = blockIdx.y * 64;
    ull acc[4][2] = {};
    int lm = tid >> 2, lk = (tid & 3) * 4;
    int bk = tid >> 4, bn = (tid & 15) * 4;
    for (int k0 = 0; k0 < HA; k0 += 16) {
        float4 a = *(const float4*)&g_feat[(size_t)(m0 + lm) * HA + k0 + lk];
        As[lk + 0][lm] = a.x; As[lk + 1][lm] = a.y; As[lk + 2][lm] = a.z; As[lk + 3][lm] = a.w;
        *(float4*)&Bs[bk][bn] = *(const float4*)&Wback[(size_t)(k0 + bk) * IFZ + n0 + bn];
        __syncthreads();
        #pragma unroll
        for (int kk = 0; kk < 16; kk++)
            fma8x2(acc, *(float4*)&As[kk][ty * 4], &Bs[kk][tx * 4]);
        __syncthreads();
    }
    const float rt2 = 1.41421356237309515f;
    float4 bb = *(const float4*)&bback[n0 + tx * 4];
    #pragma unroll
    for (int i = 0; i < 4; i++) {
        int row = m0 + ty * 4 + i;
        float4 xv = *(const float4*)&x[(size_t)row * IFZ + n0 + tx * 4];
        float4 cc = row4(acc[i][0], acc[i][1]);
        float4 ov;
        ov.x = rt2 * xv.x + cc.x + bb.x;
        ov.y = rt2 * xv.y + cc.y + bb.y;
        ov.z = rt2 * xv.z + cc.z + bb.z;
        ov.w = rt2 * xv.w + cc.w + bb.w;
        *(float4*)&g_y[(size_t)row * IFZ + n0 + tx * 4] = ov;
    }
}

// ---------------- LayerNorm ------------------------------------------------
__global__ void __launch_bounds__(256) ln_k(const float* __restrict__ gamma,
                                            const float* __restrict__ beta,
                                            float* __restrict__ out) {
    int warp = threadIdx.x >> 5, lane = threadIdx.x & 31;
    int row = blockIdx.x * 8 + warp;
    float4 v0 = *(const float4*)&g_y[(size_t)row * IFZ + lane * 4];
    float4 v1 = *(const float4*)&g_y[(size_t)row * IFZ + 128 + lane * 4];
    float s = v0.x + v0.y + v0.z + v0.w + v1.x + v1.y + v1.z + v1.w;
    #pragma unroll
    for (int d = 16; d; d >>= 1) s += __shfl_xor_sync(0xffffffffu, s, d);
    float mu = s * (1.f / 256.f);
    float q = 0.f;
    q += (v0.x - mu) * (v0.x - mu); q += (v0.y - mu) * (v0.y - mu);
    q += (v0.z - mu) * (v0.z - mu); q += (v0.w - mu) * (v0.w - mu);
    q += (v1.x - mu) * (v1.x - mu); q += (v1.y - mu) * (v1.y - mu);
    q += (v1.z - mu) * (v1.z - mu); q += (v1.w - mu) * (v1.w - mu);
    #pragma unroll
    for (int d = 16; d; d >>= 1) q += __shfl_xor_sync(0xffffffffu, q, d);
    float inv = rsqrtf(q * (1.f / 256.f) + 1e-5f);
    float4 g0 = *(const float4*)&gamma[lane * 4];
    float4 b0 = *(const float4*)&beta[lane * 4];
    float4 g1 = *(const float4*)&gamma[128 + lane * 4];
    float4 b1 = *(const float4*)&beta[128 + lane * 4];
    float4 o0, o1;
    o0.x = (v0.x - mu) * inv * g0.x + b0.x;
    o0.y = (v0.y - mu) * inv * g0.y + b0.y;
    o0.z = (v0.z - mu) * inv * g0.z + b0.z;
    o0.w = (v0.w - mu) * inv * g0.w + b0.w;
    o1.x = (v1.x - mu) * inv * g1.x + b1.x;
    o1.y = (v1.y - mu) * inv * g1.y + b1.y;
    o1.z = (v1.z - mu) * inv * g1.z + b1.z;
    o1.w = (v1.w - mu) * inv * g1.w + b1.w;
    *(float4*)&out[(size_t)row * IFZ + lane * 4] = o0;
    *(float4*)&out[(size_t)row * IFZ + 128 + lane * 4] = o1;
}

// ---------------- launch ---------------------------------------------------
extern "C" void kernel_launch(void* const* d_in, const int* in_sizes, int n_in,
                              void* d_out, int out_size) {
    const float* x     = (const float*)d_in[0];
    const float* emb   = (const float*)d_in[1];
    const void*  mask  = d_in[2];
    const void*  batch = d_in[3];
    const float* Wq    = (const float*)d_in[4];
    const float* Wk    = (const float*)d_in[5];
    const float* Wv    = (const float*)d_in[6];
    const float* Wg    = (const float*)d_in[7];
    const float* bg    = (const float*)d_in[8];
    const float* Wback = (const float*)d_in[9];
    const float* bback = (const float*)d_in[10];
    const float* gamma = (const float*)d_in[11];
    const float* beta  = (const float*)d_in[12];
    float* out    = (float*)d_out;
    float* logits = out + (size_t)NN * IFZ;

    static int smem_set = 0;
    if (!smem_set) {
        cudaFuncSetAttribute(attn_mma, cudaFuncAttributeMaxDynamicSharedMemorySize,
                             ATTN_SMEMB);
        smem_set = 1;
    }

    prep_k<<<1, 256>>>(mask, batch);
    conv_e_k<<<1536, 256>>>(emb);
    conv_w_k<<<dim3(6, 16), 128>>>(Wk, Wv);
    proj_qg_k<<<dim3(32, 16), 256>>>(x, Wq, Wg, bg);
    proj_kv_mma<<<dim3(64, 16), 128>>>();
    conv_k_k<<<2048, 256>>>();
    conv_v_k<<<dim3(16, HH, BBATCH), 128>>>();
    attn_mma<<<dim3(MAXT, HH), 128, ATTN_SMEMB>>>();
    addlog_k<<<2048, 256>>>(logits);
    back_k<<<dim3(32, 4), 256>>>(x, Wback, bback);
    ln_k<<<256, 256>>>(gamma, beta, out);
}

// round 12
// speedup vs baseline: 1.3843x; 1.0333x over previous
#include <cuda_runtime.h>
#include <cuda_bf16.h>
#include <float.h>
#include <math.h>

#define NN   2048
#define BBATCH 4
#define SS   1024
#define SFZ  384
#define IFZ  256
#define HH   8
#define AA   64
#define HA   512
#define MAXT 36

typedef unsigned long long ull;
typedef unsigned int u32;

__device__ __align__(16) float g_q[NN * HA];
__device__ __align__(16) float g_gate[NN * HA];
__device__ __align__(16) float g_v[BBATCH * SS * HA];
__device__ __align__(16) float g_feat[NN * HA];
__device__ __align__(16) float g_y[NN * IFZ];
__device__ __align__(16) unsigned char g_mask[BBATCH * SS];
__device__ int g_tb[MAXT], g_ts[MAXT], g_tc[MAXT], g_nt;
__device__ __align__(16) __nv_bfloat16 g_kh[BBATCH * SS * HA];
__device__ __align__(16) __nv_bfloat16 g_kl[BBATCH * SS * HA];
__device__ __align__(16) __nv_bfloat16 g_vh[BBATCH * HH * AA * SS];
__device__ __align__(16) __nv_bfloat16 g_vl[BBATCH * HH * AA * SS];
__device__ __align__(16) float g_sc0[NN * SS];
__device__ __align__(16) float g_sc1[NN * SS];
// bf16 hi/lo operands for mma GEMMs
__device__ __align__(16) __nv_bfloat16 g_eh[BBATCH * SS * SFZ];
__device__ __align__(16) __nv_bfloat16 g_el[BBATCH * SS * SFZ];
__device__ __align__(16) __nv_bfloat16 g_wht[2 * HA * SFZ];
__device__ __align__(16) __nv_bfloat16 g_wlt[2 * HA * SFZ];
__device__ __align__(16) __nv_bfloat16 g_xh[NN * IFZ];
__device__ __align__(16) __nv_bfloat16 g_xl[NN * IFZ];
__device__ __align__(16) __nv_bfloat16 g_qgh[2 * HA * IFZ];
__device__ __align__(16) __nv_bfloat16 g_qgl[2 * HA * IFZ];

// ---- fp32 packed helpers ----
__device__ __forceinline__ void ffma2(ull &d, ull a, ull b) {
    asm("fma.rn.f32x2 %0, %1, %2, %0;" : "+l"(d) : "l"(a), "l"(b));
}
__device__ __forceinline__ ull pk2(float lo, float hi) {
    ull r; asm("mov.b64 %0, {%1, %2};" : "=l"(r) : "f"(lo), "f"(hi)); return r;
}
__device__ __forceinline__ float2 upk2(ull v) {
    float2 r; asm("mov.b64 {%0, %1}, %2;" : "=f"(r.x), "=f"(r.y) : "l"(v)); return r;
}
__device__ __forceinline__ void fma8x2(ull (&acc)[4][2], float4 a, const float* bp) {
    ull b0 = *(const ull*)bp, b1 = *(const ull*)(bp + 2);
    ull a0 = pk2(a.x, a.x), a1 = pk2(a.y, a.y), a2 = pk2(a.z, a.z), a3 = pk2(a.w, a.w);
    ffma2(acc[0][0], a0, b0); ffma2(acc[0][1], a0, b1);
    ffma2(acc[1][0], a1, b0); ffma2(acc[1][1], a1, b1);
    ffma2(acc[2][0], a2, b0); ffma2(acc[2][1], a2, b1);
    ffma2(acc[3][0], a3, b0); ffma2(acc[3][1], a3, b1);
}
__device__ __forceinline__ float4 row4(ull p0, ull p1) {
    float2 a = upk2(p0), b = upk2(p1);
    return make_float4(a.x, a.y, b.x, b.y);
}

// ---- bf16 split helpers ----
__device__ __forceinline__ u32 pkbf(float a, float b) {
    __nv_bfloat162 t = __float22bfloat162_rn(make_float2(a, b));
    return *(u32*)&t;
}
__device__ __forceinline__ float2 unbf(u32 h) {
    return __bfloat1622float2(*(__nv_bfloat162*)&h);
}

// ---- ldmatrix + mma.sync (baseline PTX, sm_80+) ----
static __device__ __forceinline__ u32 s2u(const void* p) {
    u32 a; asm("{.reg .u64 t; cvta.to.shared.u64 t, %1; cvt.u32.u64 %0, t;}" : "=r"(a) : "l"(p));
    return a;
}
__device__ __forceinline__ void ldmx4(u32* r, u32 a) {
    asm volatile("ldmatrix.sync.aligned.m8n8.x4.shared.b16 {%0,%1,%2,%3},[%4];"
                 : "=r"(r[0]), "=r"(r[1]), "=r"(r[2]), "=r"(r[3]) : "r"(a));
}
__device__ __forceinline__ void ldmx2(u32* r, u32 a) {
    asm volatile("ldmatrix.sync.aligned.m8n8.x2.shared.b16 {%0,%1},[%2];"
                 : "=r"(r[0]), "=r"(r[1]) : "r"(a));
}
__device__ __forceinline__ void mma16816(float* d, const u32* a, const u32* bb) {
    asm volatile("mma.sync.aligned.m16n8k16.row.col.f32.bf16.bf16.f32 "
                 "{%0,%1,%2,%3},{%4,%5,%6,%7},{%8,%9},{%0,%1,%2,%3};"
                 : "+f"(d[0]), "+f"(d[1]), "+f"(d[2]), "+f"(d[3])
                 : "r"(a[0]), "r"(a[1]), "r"(a[2]), "r"(a[3]), "r"(bb[0]), "r"(bb[1]));
}

// attn smem byte offsets
#define O_QH 0
#define O_QL 9216
#define O_KH 18432
#define O_KL 27648
#define O_VH 36864
#define O_VL 46080
#define O_PH 55296
#define O_PL 64512
#define O_SC 73728
#define O_AL (O_SC + 64 * 68 * 4)
#define ATTN_SMEMB (O_AL + 256)

// ---------------- prep ------------------------------------------------------
__global__ void prep_k(const void* mask_in, const void* batch_in) {
    __shared__ int flg[2];
    __shared__ int cnt[BBATCH];
    int tid = threadIdx.x;
    if (tid < 2) flg[tid] = 0;
    if (tid < BBATCH) cnt[tid] = 0;
    __syncthreads();
    const unsigned int* bw = (const unsigned int*)batch_in;
    unsigned int o = 0;
    for (int i = tid * 2 + 1; i < NN; i += blockDim.x * 2) o |= bw[i];
    if (o) atomicOr(&flg[0], 1);
    const unsigned char* mb = (const unsigned char*)mask_in;
    int f = 0;
    for (int i = tid; i < BBATCH * SS; i += blockDim.x)
        if ((i & 3) && mb[i]) f = 1;
    if (f) atomicOr(&flg[1], 1);
    __syncthreads();
    int is32 = flg[0], isb = flg[1];
    int lc[BBATCH] = {0, 0, 0, 0};
    for (int i = tid; i < NN; i += blockDim.x) {
        int v = is32 ? ((const int*)batch_in)[i]
                     : (int)((const long long*)batch_in)[i];
        lc[v & 3]++;
    }
    #pragma unroll
    for (int b = 0; b < BBATCH; b++) if (lc[b]) atomicAdd(&cnt[b], lc[b]);
    for (int i = tid; i < BBATCH * SS; i += blockDim.x)
        g_mask[i] = isb ? (mb[i] ? 1 : 0) : (((const int*)mask_in)[i] ? 1 : 0);
    __syncthreads();
    if (tid == 0) {
        int st = 0, t = 0;
        for (int b = 0; b < BBATCH; b++) {
            int e = st + cnt[b];
            for (int s = st; s < e; s += 64) {
                g_tb[t] = b; g_ts[t] = s; g_tc[t] = min(64, e - s); t++;
            }
            st = e;
        }
        g_nt = t;
    }
}

// ---------------- elementwise f32 -> bf16 hi/lo splitters ------------------
__global__ void conv_e_k(const float* __restrict__ emb) {
    size_t i = ((size_t)blockIdx.x * 256 + threadIdx.x) * 4;
    float4 v = *(const float4*)&emb[i];
    u32 h0 = pkbf(v.x, v.y), h1 = pkbf(v.z, v.w);
    float2 f0 = unbf(h0), f1 = unbf(h1);
    u32 l0 = pkbf(v.x - f0.x, v.y - f0.y), l1 = pkbf(v.z - f1.x, v.w - f1.y);
    *(uint2*)&g_eh[i] = make_uint2(h0, h1);
    *(uint2*)&g_el[i] = make_uint2(l0, l1);
}
__global__ void conv_x_k(const float* __restrict__ x) {
    size_t i = ((size_t)blockIdx.x * 256 + threadIdx.x) * 4;
    float4 v = *(const float4*)&x[i];
    u32 h0 = pkbf(v.x, v.y), h1 = pkbf(v.z, v.w);
    float2 f0 = unbf(h0), f1 = unbf(h1);
    u32 l0 = pkbf(v.x - f0.x, v.y - f0.y), l1 = pkbf(v.z - f1.x, v.w - f1.y);
    *(uint2*)&g_xh[i] = make_uint2(h0, h1);
    *(uint2*)&g_xl[i] = make_uint2(l0, l1);
}

// ---------------- weight transposers: W[k][n] -> Wt[n][k] bf16 hi/lo -------
__global__ void __launch_bounds__(128) conv_w_k(const float* __restrict__ Wk,
                                                const float* __restrict__ Wv) {
    __shared__ float buf[64 * 68];
    int kc = blockIdx.x * 64, ng = blockIdx.y * 64;
    const float* W = (ng < HA) ? Wk : Wv;
    int nb = ng & (HA - 1);
    int tid = threadIdx.x;
    #pragma unroll
    for (int p = 0; p < 8; p++) {
        int idx = tid + p * 128, kk = idx >> 4, nn = (idx & 15) * 4;
        *(float4*)&buf[kk * 68 + nn] =
            *(const float4*)&W[(size_t)(kc + kk) * HA + nb + nn];
    }
    __syncthreads();
    int nn = tid >> 1, kh = (tid & 1) * 32;
    u32 hv[16], lv[16];
    #pragma unroll
    for (int p = 0; p < 16; p++) {
        float x0 = buf[(kh + 2 * p) * 68 + nn], x1 = buf[(kh + 2 * p + 1) * 68 + nn];
        hv[p] = pkbf(x0, x1);
        float2 f = unbf(hv[p]);
        lv[p] = pkbf(x0 - f.x, x1 - f.y);
    }
    size_t o = (size_t)(ng + nn) * SFZ + kc + kh;
    #pragma unroll
    for (int p = 0; p < 4; p++) {
        *(uint4*)&g_wht[o + p * 8] = make_uint4(hv[4*p], hv[4*p+1], hv[4*p+2], hv[4*p+3]);
        *(uint4*)&g_wlt[o + p * 8] = make_uint4(lv[4*p], lv[4*p+1], lv[4*p+2], lv[4*p+3]);
    }
}
__global__ void __launch_bounds__(128) conv_wqg_k(const float* __restrict__ Wq,
                                                  const float* __restrict__ Wg) {
    __shared__ float buf[64 * 68];
    int kc = blockIdx.x * 64, ng = blockIdx.y * 64;
    const float* W = (ng < HA) ? Wq : Wg;
    int nb = ng & (HA - 1);
    int tid = threadIdx.x;
    #pragma unroll
    for (int p = 0; p < 8; p++) {
        int idx = tid + p * 128, kk = idx >> 4, nn = (idx & 15) * 4;
        *(float4*)&buf[kk * 68 + nn] =
            *(const float4*)&W[(size_t)(kc + kk) * HA + nb + nn];
    }
    __syncthreads();
    int nn = tid >> 1, kh = (tid & 1) * 32;
    u32 hv[16], lv[16];
    #pragma unroll
    for (int p = 0; p < 16; p++) {
        float x0 = buf[(kh + 2 * p) * 68 + nn], x1 = buf[(kh + 2 * p + 1) * 68 + nn];
        hv[p] = pkbf(x0, x1);
        float2 f = unbf(hv[p]);
        lv[p] = pkbf(x0 - f.x, x1 - f.y);
    }
    size_t o = (size_t)(ng + nn) * IFZ + kc + kh;
    #pragma unroll
    for (int p = 0; p < 4; p++) {
        *(uint4*)&g_qgh[o + p * 8] = make_uint4(hv[4*p], hv[4*p+1], hv[4*p+2], hv[4*p+3]);
        *(uint4*)&g_qgl[o + p * 8] = make_uint4(lv[4*p], lv[4*p+1], lv[4*p+2], lv[4*p+3]);
    }
}

// ---------------- q,gate = x @ Wq/Wg : mma.sync bf16 3-term ----------------
__global__ void __launch_bounds__(128) proj_qg_mma(const float* __restrict__ bg) {
    __shared__ __align__(16) unsigned char sm[36864];
    const u32 SB = s2u(sm);
    int m0 = blockIdx.x * 64, ng = blockIdx.y * 64;
    int tid = threadIdx.x, lane = tid & 31, w = tid >> 5;
    const int lr = lane & 15;
    const u32 brow = lr & 7, bc8 = (lr >> 3) * 8;
    const int r0 = 16 * w + (lane >> 2), cc0 = (lane & 3) * 2;
    u32 arow = 16 * w + (lane & 7) + ((lane >> 3) & 1) * 8;
    u32 acol = ((lane >> 4) & 1) * 8;
    float acc[8][4];
    #pragma unroll
    for (int cg = 0; cg < 8; cg++)
        acc[cg][0] = acc[cg][1] = acc[cg][2] = acc[cg][3] = 0.f;

    int r = tid >> 1, kh2 = (tid & 1) * 32;
    for (int kc = 0; kc < 4; kc++) {
        int k0 = kc * 64;
        {
            size_t xa = (size_t)(m0 + r) * IFZ + k0 + kh2;
            size_t wa = (size_t)(ng + r) * IFZ + k0 + kh2;
            u32 ro = (u32)(r * 72 + kh2) * 2;
            #pragma unroll
            for (int u = 0; u < 4; u++) {
                *(uint4*)(sm + 0     + ro + u * 16) = *(const uint4*)(&g_xh[xa] + u * 8);
                *(uint4*)(sm + 9216  + ro + u * 16) = *(const uint4*)(&g_xl[xa] + u * 8);
                *(uint4*)(sm + 18432 + ro + u * 16) = *(const uint4*)(&g_qgh[wa] + u * 8);
                *(uint4*)(sm + 27648 + ro + u * 16) = *(const uint4*)(&g_qgl[wa] + u * 8);
            }
        }
        __syncthreads();
        u32 ahf[4][4], alf[4][4];
        #pragma unroll
        for (int k = 0; k < 4; k++) {
            ldmx4(ahf[k], SB + 0    + (arow * 72 + acol + 16 * k) * 2);
            ldmx4(alf[k], SB + 9216 + (arow * 72 + acol + 16 * k) * 2);
        }
        #pragma unroll
        for (int cg = 0; cg < 8; cg++) {
            #pragma unroll
            for (int k = 0; k < 4; k++) {
                u32 off = ((cg * 8 + brow) * 72 + 16 * k + bc8) * 2;
                u32 bh[2], bl[2];
                ldmx2(bh, SB + 18432 + off);
                ldmx2(bl, SB + 27648 + off);
                mma16816(acc[cg], ahf[k], bh);
                mma16816(acc[cg], ahf[k], bl);
                mma16816(acc[cg], alf[k], bh);
            }
        }
        __syncthreads();
    }
    bool isg = (ng >= HA);
    int nc0 = ng & (HA - 1);
    if (isg) {
        #pragma unroll
        for (int cg = 0; cg < 8; cg++) {
            int c = nc0 + cg * 8 + cc0;
            float b0 = bg[c], b1 = bg[c + 1];
            float2 o0, o1;
            o0.x = 1.0f / (1.0f + __expf(-(acc[cg][0] + b0)));
            o0.y = 1.0f / (1.0f + __expf(-(acc[cg][1] + b1)));
            o1.x = 1.0f / (1.0f + __expf(-(acc[cg][2] + b0)));
            o1.y = 1.0f / (1.0f + __expf(-(acc[cg][3] + b1)));
            *(float2*)&g_gate[(size_t)(m0 + r0) * HA + c] = o0;
            *(float2*)&g_gate[(size_t)(m0 + r0 + 8) * HA + c] = o1;
        }
    } else {
        #pragma unroll
        for (int cg = 0; cg < 8; cg++) {
            int c = nc0 + cg * 8 + cc0;
            *(float2*)&g_q[(size_t)(m0 + r0) * HA + c] = make_float2(acc[cg][0], acc[cg][1]);
            *(float2*)&g_q[(size_t)(m0 + r0 + 8) * HA + c] = make_float2(acc[cg][2], acc[cg][3]);
        }
    }
}

// ---------------- k,v = emb @ Wk/Wv : mma.sync (K -> bf16 hi/lo fused) -----
__global__ void __launch_bounds__(128) proj_kv_mma() {
    __shared__ __align__(16) unsigned char sm[36864];
    const u32 SB = s2u(sm);
    int m0 = blockIdx.x * 64, ng = blockIdx.y * 64;
    int tid = threadIdx.x, lane = tid & 31, w = tid >> 5;
    const int lr = lane & 15;
    const u32 brow = lr & 7, bc8 = (lr >> 3) * 8;
    const int r0 = 16 * w + (lane >> 2), cc0 = (lane & 3) * 2;
    u32 arow = 16 * w + (lane & 7) + ((lane >> 3) & 1) * 8;
    u32 acol = ((lane >> 4) & 1) * 8;
    float acc[8][4];
    #pragma unroll
    for (int cg = 0; cg < 8; cg++)
        acc[cg][0] = acc[cg][1] = acc[cg][2] = acc[cg][3] = 0.f;

    int r = tid >> 1, kh2 = (tid & 1) * 32;
    for (int kc = 0; kc < 6; kc++) {
        int k0 = kc * 64;
        {
            size_t ea = (size_t)(m0 + r) * SFZ + k0 + kh2;
            size_t wa = (size_t)(ng + r) * SFZ + k0 + kh2;
            u32 ro = (u32)(r * 72 + kh2) * 2;
            #pragma unroll
            for (int u = 0; u < 4; u++) {
                *(uint4*)(sm + 0     + ro + u * 16) = *(const uint4*)(&g_eh[ea] + u * 8);
                *(uint4*)(sm + 9216  + ro + u * 16) = *(const uint4*)(&g_el[ea] + u * 8);
                *(uint4*)(sm + 18432 + ro + u * 16) = *(const uint4*)(&g_wht[wa] + u * 8);
                *(uint4*)(sm + 27648 + ro + u * 16) = *(const uint4*)(&g_wlt[wa] + u * 8);
            }
        }
        __syncthreads();
        u32 ahf[4][4], alf[4][4];
        #pragma unroll
        for (int k = 0; k < 4; k++) {
            ldmx4(ahf[k], SB + 0    + (arow * 72 + acol + 16 * k) * 2);
            ldmx4(alf[k], SB + 9216 + (arow * 72 + acol + 16 * k) * 2);
        }
        #pragma unroll
        for (int cg = 0; cg < 8; cg++) {
            #pragma unroll
            for (int k = 0; k < 4; k++) {
                u32 off = ((cg * 8 + brow) * 72 + 16 * k + bc8) * 2;
                u32 bh[2], bl[2];
                ldmx2(bh, SB + 18432 + off);
                ldmx2(bl, SB + 27648 + off);
                mma16816(acc[cg], ahf[k], bh);
                mma16816(acc[cg], ahf[k], bl);
                mma16816(acc[cg], alf[k], bh);
            }
        }
        __syncthreads();
    }
    bool isv = (ng >= HA);
    int nc0 = ng & (HA - 1);
    if (isv) {
        #pragma unroll
        for (int cg = 0; cg < 8; cg++) {
            int c = nc0 + cg * 8 + cc0;
            *(float2*)&g_v[(size_t)(m0 + r0) * HA + c] = make_float2(acc[cg][0], acc[cg][1]);
            *(float2*)&g_v[(size_t)(m0 + r0 + 8) * HA + c] = make_float2(acc[cg][2], acc[cg][3]);
        }
    } else {
        // fused K -> bf16 hi/lo
        #pragma unroll
        for (int cg = 0; cg < 8; cg++) {
            int c = nc0 + cg * 8 + cc0;
            u32 h0 = pkbf(acc[cg][0], acc[cg][1]);
            u32 h1 = pkbf(acc[cg][2], acc[cg][3]);
            float2 f0 = unbf(h0), f1 = unbf(h1);
            u32 l0 = pkbf(acc[cg][0] - f0.x, acc[cg][1] - f0.y);
            u32 l1 = pkbf(acc[cg][2] - f1.x, acc[cg][3] - f1.y);
            *(u32*)&g_kh[(size_t)(m0 + r0) * HA + c] = h0;
            *(u32*)&g_kl[(size_t)(m0 + r0) * HA + c] = l0;
            *(u32*)&g_kh[(size_t)(m0 + r0 + 8) * HA + c] = h1;
            *(u32*)&g_kl[(size_t)(m0 + r0 + 8) * HA + c] = l1;
        }
    }
}

// ---------------- V -> transposed [b][h][a][s] bf16 hi/lo ------------------
__global__ void __launch_bounds__(128) conv_v_k() {
    __shared__ float buf[64 * 68];
    int b = blockIdx.z, h = blockIdx.y, s0 = blockIdx.x * 64;
    int tid = threadIdx.x;
    #pragma unroll
    for (int p = 0; p < 8; p++) {
        int idx = tid + p * 128, s = idx >> 4, q = idx & 15;
        *(float4*)&buf[s * 68 + q * 4] =
            *(const float4*)&g_v[((size_t)(b << 10) + s0 + s) * HA + h * AA + q * 4];
    }
    __syncthreads();
    int aa = tid >> 1, sh = (tid & 1) * 32;
    u32 hv[16], lv[16];
    #pragma unroll
    for (int p = 0; p < 16; p++) {
        float x0 = buf[(sh + 2 * p) * 68 + aa], x1 = buf[(sh + 2 * p + 1) * 68 + aa];
        hv[p] = pkbf(x0, x1);
        float2 f = unbf(hv[p]);
        lv[p] = pkbf(x0 - f.x, x1 - f.y);
    }
    size_t o = ((size_t)(b * HH + h) * AA + aa) * SS + s0 + sh;
    #pragma unroll
    for (int p = 0; p < 4; p++) {
        *(uint4*)&g_vh[o + p * 8] = make_uint4(hv[4*p], hv[4*p+1], hv[4*p+2], hv[4*p+3]);
        *(uint4*)&g_vl[o + p * 8] = make_uint4(lv[4*p], lv[4*p+1], lv[4*p+2], lv[4*p+3]);
    }
}

// ---------------- attention: mma.sync bf16 3-term, one-pass flash ----------
__global__ void __launch_bounds__(128) attn_mma() {
    extern __shared__ unsigned char sm8[];
    const int t = blockIdx.x;
    if (t >= g_nt) return;
    const int h = blockIdx.y;
    const int b = g_tb[t], n0 = g_ts[t], cnt = g_tc[t];
    const int tid = threadIdx.x, lane = tid & 31, w = tid >> 5;
    const u32 SB = s2u(sm8);
    float* Sc = (float*)(sm8 + O_SC);
    float* Al = (float*)(sm8 + O_AL);

    {
        int i = tid >> 1, ah = (tid & 1) * 32;
        bool val = i < cnt;
        const float* q = &g_q[(size_t)(n0 + i) * HA + h * AA + ah];
        u32 ro = (u32)(i * 72 + ah) * 2;
        #pragma unroll
        for (int u = 0; u < 4; u++) {
            float4 x0 = val ? *(const float4*)(q + u * 8) : make_float4(0, 0, 0, 0);
            float4 x1 = val ? *(const float4*)(q + u * 8 + 4) : make_float4(0, 0, 0, 0);
            u32 h0 = pkbf(x0.x, x0.y), h1 = pkbf(x0.z, x0.w);
            u32 h2 = pkbf(x1.x, x1.y), h3 = pkbf(x1.z, x1.w);
            float2 f0 = unbf(h0), f1 = unbf(h1), f2 = unbf(h2), f3 = unbf(h3);
            u32 l0 = pkbf(x0.x - f0.x, x0.y - f0.y), l1 = pkbf(x0.z - f1.x, x0.w - f1.y);
            u32 l2 = pkbf(x1.x - f2.x, x1.y - f2.y), l3 = pkbf(x1.z - f3.x, x1.w - f3.y);
            *(uint4*)(sm8 + O_QH + ro + u * 16) = make_uint4(h0, h1, h2, h3);
            *(uint4*)(sm8 + O_QL + ro + u * 16) = make_uint4(l0, l1, l2, l3);
        }
    }
    __syncthreads();

    u32 qhf[4][4], qlf[4][4];
    {
        u32 arow = 16 * w + (lane & 7) + ((lane >> 3) & 1) * 8;
        u32 acol = ((lane >> 4) & 1) * 8;
        #pragma unroll
        for (int k = 0; k < 4; k++) {
            ldmx4(qhf[k], SB + O_QH + (arow * 72 + acol + 16 * k) * 2);
            ldmx4(qlf[k], SB + O_QL + (arow * 72 + acol + 16 * k) * 2);
        }
    }

    const int lr = lane & 15;
    const u32 brow = lr & 7, bc8 = (lr >> 3) * 8;
    const int r0 = 16 * w + (lane >> 2), cc0 = (lane & 3) * 2;
    float m_old = -FLT_MAX, lsum = 0.f;
    float feat[8][4];
    #pragma unroll
    for (int cg = 0; cg < 8; cg++)
        feat[cg][0] = feat[cg][1] = feat[cg][2] = feat[cg][3] = 0.f;

    for (int s0 = 0; s0 < SS; s0 += 64) {
        {
            int j = tid >> 1, ah = (tid & 1) * 32;
            size_t kr = ((size_t)(b << 10) + s0 + j) * HA + h * AA + ah;
            size_t vr = ((size_t)(b * HH + h) * AA + j) * SS + s0 + ah;
            u32 ro = (u32)(j * 72 + ah) * 2;
            #pragma unroll
            for (int u = 0; u < 4; u++) {
                *(uint4*)(sm8 + O_KH + ro + u * 16) = *(const uint4*)(&g_kh[kr] + u * 8);
                *(uint4*)(sm8 + O_KL + ro + u * 16) = *(const uint4*)(&g_kl[kr] + u * 8);
                *(uint4*)(sm8 + O_VH + ro + u * 16) = *(const uint4*)(&g_vh[vr] + u * 8);
                *(uint4*)(sm8 + O_VL + ro + u * 16) = *(const uint4*)(&g_vl[vr] + u * 8);
            }
        }
        __syncthreads();
        #pragma unroll
        for (int cg = 0; cg < 8; cg++) {
            float d[4] = {0.f, 0.f, 0.f, 0.f};
            #pragma unroll
            for (int k = 0; k < 4; k++) {
                u32 off = ((cg * 8 + brow) * 72 + 16 * k + bc8) * 2;
                u32 bh[2], bl[2];
                ldmx2(bh, SB + O_KH + off);
                ldmx2(bl, SB + O_KL + off);
                mma16816(d, qhf[k], bh);
                mma16816(d, qhf[k], bl);
                mma16816(d, qlf[k], bh);
            }
            *(float2*)&Sc[r0 * 68 + cg * 8 + cc0] = make_float2(d[0], d[1]);
            *(float2*)&Sc[(r0 + 8) * 68 + cg * 8 + cc0] = make_float2(d[2], d[3]);
        }
        __syncthreads();
        if (tid < 64) {
            float sc[64];
            const float* sr = &Sc[tid * 68];
            #pragma unroll
            for (int x = 0; x < 16; x++) {
                float4 v = *(const float4*)(sr + x * 4);
                sc[x*4] = v.x * 0.125f; sc[x*4+1] = v.y * 0.125f;
                sc[x*4+2] = v.z * 0.125f; sc[x*4+3] = v.w * 0.125f;
            }
            if (h < 2 && tid < cnt) {
                float* dst = (h == 0 ? g_sc0 : g_sc1) + (size_t)(n0 + tid) * SS + s0;
                #pragma unroll
                for (int x = 0; x < 16; x++)
                    *(float4*)(dst + x * 4) =
                        make_float4(sc[x*4], sc[x*4+1], sc[x*4+2], sc[x*4+3]);
            }
            const u32* mp = (const u32*)&g_mask[b * SS + s0];
            u32 mk[64];
            float cm = -FLT_MAX;
            #pragma unroll
            for (int x = 0; x < 16; x++) {
                u32 mw = mp[x];
                mk[x*4] = mw & 255u; mk[x*4+1] = (mw >> 8) & 255u;
                mk[x*4+2] = (mw >> 16) & 255u; mk[x*4+3] = mw >> 24;
                if (mk[x*4])   cm = fmaxf(cm, sc[x*4]);
                if (mk[x*4+1]) cm = fmaxf(cm, sc[x*4+1]);
                if (mk[x*4+2]) cm = fmaxf(cm, sc[x*4+2]);
                if (mk[x*4+3]) cm = fmaxf(cm, sc[x*4+3]);
            }
            float m_new = fmaxf(m_old, cm);
            float alpha = (m_old == m_new) ? 1.f : __expf(m_old - m_new);
            float csum = 0.f;
            #pragma unroll
            for (int x = 0; x < 64; x++) {
                float p = mk[x] ? __expf(sc[x] - m_new) : 0.f;
                sc[x] = p; csum += p;
            }
            lsum = lsum * alpha + csum;
            m_old = m_new;
            Al[tid] = alpha;
            u32 ro = (u32)(tid * 72) * 2;
            #pragma unroll
            for (int u = 0; u < 8; u++) {
                u32 h0 = pkbf(sc[u*8], sc[u*8+1]), h1 = pkbf(sc[u*8+2], sc[u*8+3]);
                u32 h2 = pkbf(sc[u*8+4], sc[u*8+5]), h3 = pkbf(sc[u*8+6], sc[u*8+7]);
                float2 f0 = unbf(h0), f1 = unbf(h1), f2 = unbf(h2), f3 = unbf(h3);
                u32 l0 = pkbf(sc[u*8]-f0.x, sc[u*8+1]-f0.y), l1 = pkbf(sc[u*8+2]-f1.x, sc[u*8+3]-f1.y);
                u32 l2 = pkbf(sc[u*8+4]-f2.x, sc[u*8+5]-f2.y), l3 = pkbf(sc[u*8+6]-f3.x, sc[u*8+7]-f3.y);
                *(uint4*)(sm8 + O_PH + ro + u * 16) = make_uint4(h0, h1, h2, h3);
                *(uint4*)(sm8 + O_PL + ro + u * 16) = make_uint4(l0, l1, l2, l3);
            }
        }
        __syncthreads();
        {
            float a0 = Al[r0], a1 = Al[r0 + 8];
            #pragma unroll
            for (int cg = 0; cg < 8; cg++) {
                feat[cg][0] *= a0; feat[cg][1] *= a0;
                feat[cg][2] *= a1; feat[cg][3] *= a1;
            }
            u32 arow = 16 * w + (lane & 7) + ((lane >> 3) & 1) * 8;
            u32 acol = ((lane >> 4) & 1) * 8;
            u32 phf[4][4], plf[4][4];
            #pragma unroll
            for (int k = 0; k < 4; k++) {
                ldmx4(phf[k], SB + O_PH + (arow * 72 + acol + 16 * k) * 2);
                ldmx4(plf[k], SB + O_PL + (arow * 72 + acol + 16 * k) * 2);
            }
            #pragma unroll
            for (int cg = 0; cg < 8; cg++) {
                #pragma unroll
                for (int k = 0; k < 4; k++) {
                    u32 off = ((cg * 8 + brow) * 72 + 16 * k + bc8) * 2;
                    u32 bh[2], bl[2];
                    ldmx2(bh, SB + O_VH + off);
                    ldmx2(bl, SB + O_VL + off);
                    mma16816(feat[cg], phf[k], bh);
                    mma16816(feat[cg], phf[k], bl);
                    mma16816(feat[cg], plf[k], bh);
                }
            }
        }
        __syncthreads();
    }

    #pragma unroll
    for (int cg = 0; cg < 8; cg++) {
        *(float2*)&Sc[r0 * 68 + cg * 8 + cc0] = make_float2(feat[cg][0], feat[cg][1]);
        *(float2*)&Sc[(r0 + 8) * 68 + cg * 8 + cc0] = make_float2(feat[cg][2], feat[cg][3]);
    }
    __syncthreads();
    if (tid < cnt) {
        float inv = 1.f / (lsum + 1e-9f);
        const float* gp = &g_gate[(size_t)(n0 + tid) * HA + h * AA];
        float* fp = &g_feat[(size_t)(n0 + tid) * HA + h * AA];
        const float* sr = &Sc[tid * 68];
        #pragma unroll
        for (int x = 0; x < 16; x++) {
            float4 v = *(const float4*)(sr + x * 4);
            float4 g = *(const float4*)(gp + x * 4);
            *(float4*)(fp + x * 4) =
                make_float4(v.x * inv * g.x, v.y * inv * g.y, v.z * inv * g.z, v.w * inv * g.w);
        }
    }
}

// ---------------- logits = sc0 + sc1 ---------------------------------------
__global__ void addlog_k(float* __restrict__ logits) {
    size_t i = ((size_t)blockIdx.x * 256 + threadIdx.x) * 4;
    float4 a = *(const float4*)&g_sc0[i];
    float4 b4 = *(const float4*)&g_sc1[i];
    *(float4*)&logits[i] = make_float4(a.x + b4.x, a.y + b4.y, a.z + b4.z, a.w + b4.w);
}

// ---------------- y = sqrt(2)*x + gatedfeat @ Wback + bback ----------------
__global__ void __launch_bounds__(256) back_k(const float* __restrict__ x,
                                              const float* __restrict__ Wback,
                                              const float* __restrict__ bback) {
    __shared__ float As[16][68];
    __shared__ float Bs[16][64];
    int tid = threadIdx.x, tx = tid & 15, ty = tid >> 4;
    int m0 = blockIdx.x * 64, n0 = blockIdx.y * 64;
    ull acc[4][2] = {};
    int lm = tid >> 2, lk = (tid & 3) * 4;
    int bk = tid >> 4, bn = (tid & 15) * 4;
    for (int k0 = 0; k0 < HA; k0 += 16) {
        float4 a = *(const float4*)&g_feat[(size_t)(m0 + lm) * HA + k0 + lk];
        As[lk + 0][lm] = a.x; As[lk + 1][lm] = a.y; As[lk + 2][lm] = a.z; As[lk + 3][lm] = a.w;
        *(float4*)&Bs[bk][bn] = *(const float4*)&Wback[(size_t)(k0 + bk) * IFZ + n0 + bn];
        __syncthreads();
        #pragma unroll
        for (int kk = 0; kk < 16; kk++)
            fma8x2(acc, *(float4*)&As[kk][ty * 4], &Bs[kk][tx * 4]);
        __syncthreads();
    }
    const float rt2 = 1.41421356237309515f;
    float4 bb = *(const float4*)&bback[n0 + tx * 4];
    #pragma unroll
    for (int i = 0; i < 4; i++) {
        int row = m0 + ty * 4 + i;
        float4 xv = *(const float4*)&x[(size_t)row * IFZ + n0 + tx * 4];
        float4 cc = row4(acc[i][0], acc[i][1]);
        float4 ov;
        ov.x = rt2 * xv.x + cc.x + bb.x;
        ov.y = rt2 * xv.y + cc.y + bb.y;
        ov.z = rt2 * xv.z + cc.z + bb.z;
        ov.w = rt2 * xv.w + cc.w + bb.w;
        *(float4*)&g_y[(size_t)row * IFZ + n0 + tx * 4] = ov;
    }
}

// ---------------- LayerNorm ------------------------------------------------
__global__ void __launch_bounds__(256) ln_k(const float* __restrict__ gamma,
                                            const float* __restrict__ beta,
                                            float* __restrict__ out) {
    int warp = threadIdx.x >> 5, lane = threadIdx.x & 31;
    int row = blockIdx.x * 8 + warp;
    float4 v0 = *(const float4*)&g_y[(size_t)row * IFZ + lane * 4];
    float4 v1 = *(const float4*)&g_y[(size_t)row * IFZ + 128 + lane * 4];
    float s = v0.x + v0.y + v0.z + v0.w + v1.x + v1.y + v1.z + v1.w;
    #pragma unroll
    for (int d = 16; d; d >>= 1) s += __shfl_xor_sync(0xffffffffu, s, d);
    float mu = s * (1.f / 256.f);
    float q = 0.f;
    q += (v0.x - mu) * (v0.x - mu); q += (v0.y - mu) * (v0.y - mu);
    q += (v0.z - mu) * (v0.z - mu); q += (v0.w - mu) * (v0.w - mu);
    q += (v1.x - mu) * (v1.x - mu); q += (v1.y - mu) * (v1.y - mu);
    q += (v1.z - mu) * (v1.z - mu); q += (v1.w - mu) * (v1.w - mu);
    #pragma unroll
    for (int d = 16; d; d >>= 1) q += __shfl_xor_sync(0xffffffffu, q, d);
    float inv = rsqrtf(q * (1.f / 256.f) + 1e-5f);
    float4 g0 = *(const float4*)&gamma[lane * 4];
    float4 b0 = *(const float4*)&beta[lane * 4];
    float4 g1 = *(const float4*)&gamma[128 + lane * 4];
    float4 b1 = *(const float4*)&beta[128 + lane * 4];
    float4 o0, o1;
    o0.x = (v0.x - mu) * inv * g0.x + b0.x;
    o0.y = (v0.y - mu) * inv * g0.y + b0.y;
    o0.z = (v0.z - mu) * inv * g0.z + b0.z;
    o0.w = (v0.w - mu) * inv * g0.w + b0.w;
    o1.x = (v1.x - mu) * inv * g1.x + b1.x;
    o1.y = (v1.y - mu) * inv * g1.y + b1.y;
    o1.z = (v1.z - mu) * inv * g1.z + b1.z;
    o1.w = (v1.w - mu) * inv * g1.w + b1.w;
    *(float4*)&out[(size_t)row * IFZ + lane * 4] = o0;
    *(float4*)&out[(size_t)row * IFZ + 128 + lane * 4] = o1;
}

// ---------------- launch ---------------------------------------------------
extern "C" void kernel_launch(void* const* d_in, const int* in_sizes, int n_in,
                              void* d_out, int out_size) {
    const float* x     = (const float*)d_in[0];
    const float* emb   = (const float*)d_in[1];
    const void*  mask  = d_in[2];
    const void*  batch = d_in[3];
    const float* Wq    = (const float*)d_in[4];
    const float* Wk    = (const float*)d_in[5];
    const float* Wv    = (const float*)d_in[6];
    const float* Wg    = (const float*)d_in[7];
    const float* bg    = (const float*)d_in[8];
    const float* Wback = (const float*)d_in[9];
    const float* bback = (const float*)d_in[10];
    const float* gamma = (const float*)d_in[11];
    const float* beta  = (const float*)d_in[12];
    float* out    = (float*)d_out;
    float* logits = out + (size_t)NN * IFZ;

    static int smem_set = 0;
    if (!smem_set) {
        cudaFuncSetAttribute(attn_mma, cudaFuncAttributeMaxDynamicSharedMemorySize,
                             ATTN_SMEMB);
        smem_set = 1;
    }

    prep_k<<<1, 256>>>(mask, batch);
    conv_e_k<<<1536, 256>>>(emb);
    conv_x_k<<<512, 256>>>(x);
    conv_w_k<<<dim3(6, 16), 128>>>(Wk, Wv);
    conv_wqg_k<<<dim3(4, 16), 128>>>(Wq, Wg);
    proj_qg_mma<<<dim3(32, 16), 128>>>(bg);
    proj_kv_mma<<<dim3(64, 16), 128>>>();
    conv_v_k<<<dim3(16, HH, BBATCH), 128>>>();
    attn_mma<<<dim3(MAXT, HH), 128, ATTN_SMEMB>>>();
    addlog_k<<<2048, 256>>>(logits);
    back_k<<<dim3(32, 4), 256>>>(x, Wback, bback);
    ln_k<<<256, 256>>>(gamma, beta, out);
}

// round 13
// speedup vs baseline: 1.4886x; 1.0753x over previous
#include <cuda_runtime.h>
#include <cuda_bf16.h>
#include <float.h>
#include <math.h>

#define NN   2048
#define BBATCH 4
#define SS   1024
#define SFZ  384
#define IFZ  256
#define HH   8
#define AA   64
#define HA   512
#define MAXT 36

typedef unsigned long long ull;
typedef unsigned int u32;

__device__ __align__(16) float g_q[NN * HA];
__device__ __align__(16) float g_gate[NN * HA];
__device__ __align__(16) float g_v[BBATCH * SS * HA];
__device__ __align__(16) float g_feat[NN * HA];
__device__ __align__(16) float g_y[NN * IFZ];
__device__ __align__(16) unsigned char g_mask[BBATCH * SS];
__device__ int g_tb[MAXT], g_ts[MAXT], g_tc[MAXT], g_nt;
__device__ __align__(16) __nv_bfloat16 g_kh[BBATCH * SS * HA];
__device__ __align__(16) __nv_bfloat16 g_kl[BBATCH * SS * HA];
__device__ __align__(16) __nv_bfloat16 g_vh[BBATCH * HH * AA * SS];
__device__ __align__(16) __nv_bfloat16 g_vl[BBATCH * HH * AA * SS];
__device__ __align__(16) float g_sc0[NN * SS];
__device__ __align__(16) float g_sc1[NN * SS];
__device__ __align__(16) __nv_bfloat16 g_eh[BBATCH * SS * SFZ];
__device__ __align__(16) __nv_bfloat16 g_el[BBATCH * SS * SFZ];
__device__ __align__(16) __nv_bfloat16 g_wht[2 * HA * SFZ];
__device__ __align__(16) __nv_bfloat16 g_wlt[2 * HA * SFZ];
__device__ __align__(16) __nv_bfloat16 g_xh[NN * IFZ];
__device__ __align__(16) __nv_bfloat16 g_xl[NN * IFZ];
__device__ __align__(16) __nv_bfloat16 g_qgh[2 * HA * IFZ];
__device__ __align__(16) __nv_bfloat16 g_qgl[2 * HA * IFZ];

// ---- fp32 packed helpers ----
__device__ __forceinline__ void ffma2(ull &d, ull a, ull b) {
    asm("fma.rn.f32x2 %0, %1, %2, %0;" : "+l"(d) : "l"(a), "l"(b));
}
__device__ __forceinline__ ull pk2(float lo, float hi) {
    ull r; asm("mov.b64 %0, {%1, %2};" : "=l"(r) : "f"(lo), "f"(hi)); return r;
}
__device__ __forceinline__ float2 upk2(ull v) {
    float2 r; asm("mov.b64 {%0, %1}, %2;" : "=f"(r.x), "=f"(r.y) : "l"(v)); return r;
}
__device__ __forceinline__ void fma8x2(ull (&acc)[4][2], float4 a, const float* bp) {
    ull b0 = *(const ull*)bp, b1 = *(const ull*)(bp + 2);
    ull a0 = pk2(a.x, a.x), a1 = pk2(a.y, a.y), a2 = pk2(a.z, a.z), a3 = pk2(a.w, a.w);
    ffma2(acc[0][0], a0, b0); ffma2(acc[0][1], a0, b1);
    ffma2(acc[1][0], a1, b0); ffma2(acc[1][1], a1, b1);
    ffma2(acc[2][0], a2, b0); ffma2(acc[2][1], a2, b1);
    ffma2(acc[3][0], a3, b0); ffma2(acc[3][1], a3, b1);
}
__device__ __forceinline__ float4 row4(ull p0, ull p1) {
    float2 a = upk2(p0), b = upk2(p1);
    return make_float4(a.x, a.y, b.x, b.y);
}

// ---- bf16 split helpers ----
__device__ __forceinline__ u32 pkbf(float a, float b) {
    __nv_bfloat162 t = __float22bfloat162_rn(make_float2(a, b));
    return *(u32*)&t;
}
__device__ __forceinline__ float2 unbf(u32 h) {
    return __bfloat1622float2(*(__nv_bfloat162*)&h);
}

// ---- ldmatrix + mma.sync (baseline PTX, sm_80+) ----
static __device__ __forceinline__ u32 s2u(const void* p) {
    u32 a; asm("{.reg .u64 t; cvta.to.shared.u64 t, %1; cvt.u32.u64 %0, t;}" : "=r"(a) : "l"(p));
    return a;
}
__device__ __forceinline__ void ldmx4(u32* r, u32 a) {
    asm volatile("ldmatrix.sync.aligned.m8n8.x4.shared.b16 {%0,%1,%2,%3},[%4];"
                 : "=r"(r[0]), "=r"(r[1]), "=r"(r[2]), "=r"(r[3]) : "r"(a));
}
__device__ __forceinline__ void ldmx2(u32* r, u32 a) {
    asm volatile("ldmatrix.sync.aligned.m8n8.x2.shared.b16 {%0,%1},[%2];"
                 : "=r"(r[0]), "=r"(r[1]) : "r"(a));
}
__device__ __forceinline__ void mma16816(float* d, const u32* a, const u32* bb) {
    asm volatile("mma.sync.aligned.m16n8k16.row.col.f32.bf16.bf16.f32 "
                 "{%0,%1,%2,%3},{%4,%5,%6,%7},{%8,%9},{%0,%1,%2,%3};"
                 : "+f"(d[0]), "+f"(d[1]), "+f"(d[2]), "+f"(d[3])
                 : "r"(a[0]), "r"(a[1]), "r"(a[2]), "r"(a[3]), "r"(bb[0]), "r"(bb[1]));
}

// attn smem byte offsets
#define O_QH 0
#define O_QL 9216
#define O_KH 18432
#define O_KL 27648
#define O_VH 36864
#define O_VL 46080
#define O_PH 55296
#define O_PL 64512
#define O_SC 73728
#define O_AL (O_SC + 64 * 68 * 4)
#define ATTN_SMEMB (O_AL + 256)

// ---------------- prep ------------------------------------------------------
__global__ void prep_k(const void* mask_in, const void* batch_in) {
    __shared__ int flg[2];
    __shared__ int cnt[BBATCH];
    int tid = threadIdx.x;
    if (tid < 2) flg[tid] = 0;
    if (tid < BBATCH) cnt[tid] = 0;
    __syncthreads();
    const unsigned int* bw = (const unsigned int*)batch_in;
    unsigned int o = 0;
    for (int i = tid * 2 + 1; i < NN; i += blockDim.x * 2) o |= bw[i];
    if (o) atomicOr(&flg[0], 1);
    const unsigned char* mb = (const unsigned char*)mask_in;
    int f = 0;
    for (int i = tid; i < BBATCH * SS; i += blockDim.x)
        if ((i & 3) && mb[i]) f = 1;
    if (f) atomicOr(&flg[1], 1);
    __syncthreads();
    int is32 = flg[0], isb = flg[1];
    int lc[BBATCH] = {0, 0, 0, 0};
    for (int i = tid; i < NN; i += blockDim.x) {
        int v = is32 ? ((const int*)batch_in)[i]
                     : (int)((const long long*)batch_in)[i];
        lc[v & 3]++;
    }
    #pragma unroll
    for (int b = 0; b < BBATCH; b++) if (lc[b]) atomicAdd(&cnt[b], lc[b]);
    for (int i = tid; i < BBATCH * SS; i += blockDim.x)
        g_mask[i] = isb ? (mb[i] ? 1 : 0) : (((const int*)mask_in)[i] ? 1 : 0);
    __syncthreads();
    if (tid == 0) {
        int st = 0, t = 0;
        for (int b = 0; b < BBATCH; b++) {
            int e = st + cnt[b];
            for (int s = st; s < e; s += 64) {
                g_tb[t] = b; g_ts[t] = s; g_tc[t] = min(64, e - s); t++;
            }
            st = e;
        }
        g_nt = t;
    }
}

// ---------------- elementwise f32 -> bf16 hi/lo splitters ------------------
__global__ void conv_e_k(const float* __restrict__ emb) {
    size_t i = ((size_t)blockIdx.x * 256 + threadIdx.x) * 4;
    float4 v = *(const float4*)&emb[i];
    u32 h0 = pkbf(v.x, v.y), h1 = pkbf(v.z, v.w);
    float2 f0 = unbf(h0), f1 = unbf(h1);
    u32 l0 = pkbf(v.x - f0.x, v.y - f0.y), l1 = pkbf(v.z - f1.x, v.w - f1.y);
    *(uint2*)&g_eh[i] = make_uint2(h0, h1);
    *(uint2*)&g_el[i] = make_uint2(l0, l1);
}
__global__ void conv_x_k(const float* __restrict__ x) {
    size_t i = ((size_t)blockIdx.x * 256 + threadIdx.x) * 4;
    float4 v = *(const float4*)&x[i];
    u32 h0 = pkbf(v.x, v.y), h1 = pkbf(v.z, v.w);
    float2 f0 = unbf(h0), f1 = unbf(h1);
    u32 l0 = pkbf(v.x - f0.x, v.y - f0.y), l1 = pkbf(v.z - f1.x, v.w - f1.y);
    *(uint2*)&g_xh[i] = make_uint2(h0, h1);
    *(uint2*)&g_xl[i] = make_uint2(l0, l1);
}

// ---------------- weight transposers: W[k][n] -> Wt[n][k] bf16 hi/lo -------
__global__ void __launch_bounds__(128) conv_w_k(const float* __restrict__ Wk,
                                                const float* __restrict__ Wv) {
    __shared__ float buf[64 * 68];
    int kc = blockIdx.x * 64, ng = blockIdx.y * 64;
    const float* W = (ng < HA) ? Wk : Wv;
    int nb = ng & (HA - 1);
    int tid = threadIdx.x;
    #pragma unroll
    for (int p = 0; p < 8; p++) {
        int idx = tid + p * 128, kk = idx >> 4, nn = (idx & 15) * 4;
        *(float4*)&buf[kk * 68 + nn] =
            *(const float4*)&W[(size_t)(kc + kk) * HA + nb + nn];
    }
    __syncthreads();
    int nn = tid >> 1, kh = (tid & 1) * 32;
    u32 hv[16], lv[16];
    #pragma unroll
    for (int p = 0; p < 16; p++) {
        float x0 = buf[(kh + 2 * p) * 68 + nn], x1 = buf[(kh + 2 * p + 1) * 68 + nn];
        hv[p] = pkbf(x0, x1);
        float2 f = unbf(hv[p]);
        lv[p] = pkbf(x0 - f.x, x1 - f.y);
    }
    size_t o = (size_t)(ng + nn) * SFZ + kc + kh;
    #pragma unroll
    for (int p = 0; p < 4; p++) {
        *(uint4*)&g_wht[o + p * 8] = make_uint4(hv[4*p], hv[4*p+1], hv[4*p+2], hv[4*p+3]);
        *(uint4*)&g_wlt[o + p * 8] = make_uint4(lv[4*p], lv[4*p+1], lv[4*p+2], lv[4*p+3]);
    }
}
__global__ void __launch_bounds__(128) conv_wqg_k(const float* __restrict__ Wq,
                                                  const float* __restrict__ Wg) {
    __shared__ float buf[64 * 68];
    int kc = blockIdx.x * 64, ng = blockIdx.y * 64;
    const float* W = (ng < HA) ? Wq : Wg;
    int nb = ng & (HA - 1);
    int tid = threadIdx.x;
    #pragma unroll
    for (int p = 0; p < 8; p++) {
        int idx = tid + p * 128, kk = idx >> 4, nn = (idx & 15) * 4;
        *(float4*)&buf[kk * 68 + nn] =
            *(const float4*)&W[(size_t)(kc + kk) * HA + nb + nn];
    }
    __syncthreads();
    int nn = tid >> 1, kh = (tid & 1) * 32;
    u32 hv[16], lv[16];
    #pragma unroll
    for (int p = 0; p < 16; p++) {
        float x0 = buf[(kh + 2 * p) * 68 + nn], x1 = buf[(kh + 2 * p + 1) * 68 + nn];
        hv[p] = pkbf(x0, x1);
        float2 f = unbf(hv[p]);
        lv[p] = pkbf(x0 - f.x, x1 - f.y);
    }
    size_t o = (size_t)(ng + nn) * IFZ + kc + kh;
    #pragma unroll
    for (int p = 0; p < 4; p++) {
        *(uint4*)&g_qgh[o + p * 8] = make_uint4(hv[4*p], hv[4*p+1], hv[4*p+2], hv[4*p+3]);
        *(uint4*)&g_qgl[o + p * 8] = make_uint4(lv[4*p], lv[4*p+1], lv[4*p+2], lv[4*p+3]);
    }
}

// ---------------- q,gate = x @ Wq/Wg : mma.sync bf16 3-term ----------------
__global__ void __launch_bounds__(128) proj_qg_mma(const float* __restrict__ bg) {
    __shared__ __align__(16) unsigned char sm[36864];
    const u32 SB = s2u(sm);
    int m0 = blockIdx.x * 64, ng = blockIdx.y * 64;
    int tid = threadIdx.x, lane = tid & 31, w = tid >> 5;
    const int lr = lane & 15;
    const u32 brow = lr & 7, bc8 = (lr >> 3) * 8;
    const int r0 = 16 * w + (lane >> 2), cc0 = (lane & 3) * 2;
    u32 arow = 16 * w + (lane & 7) + ((lane >> 3) & 1) * 8;
    u32 acol = ((lane >> 4) & 1) * 8;
    float acc[8][4];
    #pragma unroll
    for (int cg = 0; cg < 8; cg++)
        acc[cg][0] = acc[cg][1] = acc[cg][2] = acc[cg][3] = 0.f;

    int r = tid >> 1, kh2 = (tid & 1) * 32;
    for (int kc = 0; kc < 4; kc++) {
        int k0 = kc * 64;
        {
            size_t xa = (size_t)(m0 + r) * IFZ + k0 + kh2;
            size_t wa = (size_t)(ng + r) * IFZ + k0 + kh2;
            u32 ro = (u32)(r * 72 + kh2) * 2;
            #pragma unroll
            for (int u = 0; u < 4; u++) {
                *(uint4*)(sm + 0     + ro + u * 16) = *(const uint4*)(&g_xh[xa] + u * 8);
                *(uint4*)(sm + 9216  + ro + u * 16) = *(const uint4*)(&g_xl[xa] + u * 8);
                *(uint4*)(sm + 18432 + ro + u * 16) = *(const uint4*)(&g_qgh[wa] + u * 8);
                *(uint4*)(sm + 27648 + ro + u * 16) = *(const uint4*)(&g_qgl[wa] + u * 8);
            }
        }
        __syncthreads();
        u32 ahf[4][4], alf[4][4];
        #pragma unroll
        for (int k = 0; k < 4; k++) {
            ldmx4(ahf[k], SB + 0    + (arow * 72 + acol + 16 * k) * 2);
            ldmx4(alf[k], SB + 9216 + (arow * 72 + acol + 16 * k) * 2);
        }
        #pragma unroll
        for (int cg = 0; cg < 8; cg++) {
            #pragma unroll
            for (int k = 0; k < 4; k++) {
                u32 off = ((cg * 8 + brow) * 72 + 16 * k + bc8) * 2;
                u32 bh[2], bl[2];
                ldmx2(bh, SB + 18432 + off);
                ldmx2(bl, SB + 27648 + off);
                mma16816(acc[cg], ahf[k], bh);
                mma16816(acc[cg], ahf[k], bl);
                mma16816(acc[cg], alf[k], bh);
            }
        }
        __syncthreads();
    }
    bool isg = (ng >= HA);
    int nc0 = ng & (HA - 1);
    if (isg) {
        #pragma unroll
        for (int cg = 0; cg < 8; cg++) {
            int c = nc0 + cg * 8 + cc0;
            float b0 = bg[c], b1 = bg[c + 1];
            float2 o0, o1;
            o0.x = 1.0f / (1.0f + __expf(-(acc[cg][0] + b0)));
            o0.y = 1.0f / (1.0f + __expf(-(acc[cg][1] + b1)));
            o1.x = 1.0f / (1.0f + __expf(-(acc[cg][2] + b0)));
            o1.y = 1.0f / (1.0f + __expf(-(acc[cg][3] + b1)));
            *(float2*)&g_gate[(size_t)(m0 + r0) * HA + c] = o0;
            *(float2*)&g_gate[(size_t)(m0 + r0 + 8) * HA + c] = o1;
        }
    } else {
        #pragma unroll
        for (int cg = 0; cg < 8; cg++) {
            int c = nc0 + cg * 8 + cc0;
            *(float2*)&g_q[(size_t)(m0 + r0) * HA + c] = make_float2(acc[cg][0], acc[cg][1]);
            *(float2*)&g_q[(size_t)(m0 + r0 + 8) * HA + c] = make_float2(acc[cg][2], acc[cg][3]);
        }
    }
}

// ---------------- k,v = emb @ Wk/Wv : mma.sync (K -> bf16 hi/lo fused) -----
__global__ void __launch_bounds__(128) proj_kv_mma() {
    __shared__ __align__(16) unsigned char sm[36864];
    const u32 SB = s2u(sm);
    int m0 = blockIdx.x * 64, ng = blockIdx.y * 64;
    int tid = threadIdx.x, lane = tid & 31, w = tid >> 5;
    const int lr = lane & 15;
    const u32 brow = lr & 7, bc8 = (lr >> 3) * 8;
    const int r0 = 16 * w + (lane >> 2), cc0 = (lane & 3) * 2;
    u32 arow = 16 * w + (lane & 7) + ((lane >> 3) & 1) * 8;
    u32 acol = ((lane >> 4) & 1) * 8;
    float acc[8][4];
    #pragma unroll
    for (int cg = 0; cg < 8; cg++)
        acc[cg][0] = acc[cg][1] = acc[cg][2] = acc[cg][3] = 0.f;

    int r = tid >> 1, kh2 = (tid & 1) * 32;
    for (int kc = 0; kc < 6; kc++) {
        int k0 = kc * 64;
        {
            size_t ea = (size_t)(m0 + r) * SFZ + k0 + kh2;
            size_t wa = (size_t)(ng + r) * SFZ + k0 + kh2;
            u32 ro = (u32)(r * 72 + kh2) * 2;
            #pragma unroll
            for (int u = 0; u < 4; u++) {
                *(uint4*)(sm + 0     + ro + u * 16) = *(const uint4*)(&g_eh[ea] + u * 8);
                *(uint4*)(sm + 9216  + ro + u * 16) = *(const uint4*)(&g_el[ea] + u * 8);
                *(uint4*)(sm + 18432 + ro + u * 16) = *(const uint4*)(&g_wht[wa] + u * 8);
                *(uint4*)(sm + 27648 + ro + u * 16) = *(const uint4*)(&g_wlt[wa] + u * 8);
            }
        }
        __syncthreads();
        u32 ahf[4][4], alf[4][4];
        #pragma unroll
        for (int k = 0; k < 4; k++) {
            ldmx4(ahf[k], SB + 0    + (arow * 72 + acol + 16 * k) * 2);
            ldmx4(alf[k], SB + 9216 + (arow * 72 + acol + 16 * k) * 2);
        }
        #pragma unroll
        for (int cg = 0; cg < 8; cg++) {
            #pragma unroll
            for (int k = 0; k < 4; k++) {
                u32 off = ((cg * 8 + brow) * 72 + 16 * k + bc8) * 2;
                u32 bh[2], bl[2];
                ldmx2(bh, SB + 18432 + off);
                ldmx2(bl, SB + 27648 + off);
                mma16816(acc[cg], ahf[k], bh);
                mma16816(acc[cg], ahf[k], bl);
                mma16816(acc[cg], alf[k], bh);
            }
        }
        __syncthreads();
    }
    bool isv = (ng >= HA);
    int nc0 = ng & (HA - 1);
    if (isv) {
        #pragma unroll
        for (int cg = 0; cg < 8; cg++) {
            int c = nc0 + cg * 8 + cc0;
            *(float2*)&g_v[(size_t)(m0 + r0) * HA + c] = make_float2(acc[cg][0], acc[cg][1]);
            *(float2*)&g_v[(size_t)(m0 + r0 + 8) * HA + c] = make_float2(acc[cg][2], acc[cg][3]);
        }
    } else {
        #pragma unroll
        for (int cg = 0; cg < 8; cg++) {
            int c = nc0 + cg * 8 + cc0;
            u32 h0 = pkbf(acc[cg][0], acc[cg][1]);
            u32 h1 = pkbf(acc[cg][2], acc[cg][3]);
            float2 f0 = unbf(h0), f1 = unbf(h1);
            u32 l0 = pkbf(acc[cg][0] - f0.x, acc[cg][1] - f0.y);
            u32 l1 = pkbf(acc[cg][2] - f1.x, acc[cg][3] - f1.y);
            *(u32*)&g_kh[(size_t)(m0 + r0) * HA + c] = h0;
            *(u32*)&g_kl[(size_t)(m0 + r0) * HA + c] = l0;
            *(u32*)&g_kh[(size_t)(m0 + r0 + 8) * HA + c] = h1;
            *(u32*)&g_kl[(size_t)(m0 + r0 + 8) * HA + c] = l1;
        }
    }
}

// ---------------- V -> transposed [b][h][a][s] bf16 hi/lo ------------------
__global__ void __launch_bounds__(128) conv_v_k() {
    __shared__ float buf[64 * 68];
    int b = blockIdx.z, h = blockIdx.y, s0 = blockIdx.x * 64;
    int tid = threadIdx.x;
    #pragma unroll
    for (int p = 0; p < 8; p++) {
        int idx = tid + p * 128, s = idx >> 4, q = idx & 15;
        *(float4*)&buf[s * 68 + q * 4] =
            *(const float4*)&g_v[((size_t)(b << 10) + s0 + s) * HA + h * AA + q * 4];
    }
    __syncthreads();
    int aa = tid >> 1, sh = (tid & 1) * 32;
    u32 hv[16], lv[16];
    #pragma unroll
    for (int p = 0; p < 16; p++) {
        float x0 = buf[(sh + 2 * p) * 68 + aa], x1 = buf[(sh + 2 * p + 1) * 68 + aa];
        hv[p] = pkbf(x0, x1);
        float2 f = unbf(hv[p]);
        lv[p] = pkbf(x0 - f.x, x1 - f.y);
    }
    size_t o = ((size_t)(b * HH + h) * AA + aa) * SS + s0 + sh;
    #pragma unroll
    for (int p = 0; p < 4; p++) {
        *(uint4*)&g_vh[o + p * 8] = make_uint4(hv[4*p], hv[4*p+1], hv[4*p+2], hv[4*p+3]);
        *(uint4*)&g_vl[o + p * 8] = make_uint4(lv[4*p], lv[4*p+1], lv[4*p+2], lv[4*p+3]);
    }
}

// ---------------- attention: mma.sync bf16 3-term, flash, full-width smax --
__global__ void __launch_bounds__(128) attn_mma() {
    extern __shared__ unsigned char sm8[];
    const int t = blockIdx.x;
    if (t >= g_nt) return;
    const int h = blockIdx.y;
    const int b = g_tb[t], n0 = g_ts[t], cnt = g_tc[t];
    const int tid = threadIdx.x, lane = tid & 31, w = tid >> 5;
    const u32 SB = s2u(sm8);
    float* Sc = (float*)(sm8 + O_SC);
    float* Al = (float*)(sm8 + O_AL);
    const int jr = tid >> 1, half = (tid & 1) * 32;   // pair (2j,2j+1) owns row jr

    // stage Q hi/lo (once)
    {
        bool val = jr < cnt;
        const float* q = &g_q[(size_t)(n0 + jr) * HA + h * AA + half];
        u32 ro = (u32)(jr * 72 + half) * 2;
        #pragma unroll
        for (int u = 0; u < 4; u++) {
            float4 x0 = val ? *(const float4*)(q + u * 8) : make_float4(0, 0, 0, 0);
            float4 x1 = val ? *(const float4*)(q + u * 8 + 4) : make_float4(0, 0, 0, 0);
            u32 h0 = pkbf(x0.x, x0.y), h1 = pkbf(x0.z, x0.w);
            u32 h2 = pkbf(x1.x, x1.y), h3 = pkbf(x1.z, x1.w);
            float2 f0 = unbf(h0), f1 = unbf(h1), f2 = unbf(h2), f3 = unbf(h3);
            u32 l0 = pkbf(x0.x - f0.x, x0.y - f0.y), l1 = pkbf(x0.z - f1.x, x0.w - f1.y);
            u32 l2 = pkbf(x1.x - f2.x, x1.y - f2.y), l3 = pkbf(x1.z - f3.x, x1.w - f3.y);
            *(uint4*)(sm8 + O_QH + ro + u * 16) = make_uint4(h0, h1, h2, h3);
            *(uint4*)(sm8 + O_QL + ro + u * 16) = make_uint4(l0, l1, l2, l3);
        }
    }
    __syncthreads();

    u32 qhf[4][4], qlf[4][4];
    {
        u32 arow = 16 * w + (lane & 7) + ((lane >> 3) & 1) * 8;
        u32 acol = ((lane >> 4) & 1) * 8;
        #pragma unroll
        for (int k = 0; k < 4; k++) {
            ldmx4(qhf[k], SB + O_QH + (arow * 72 + acol + 16 * k) * 2);
            ldmx4(qlf[k], SB + O_QL + (arow * 72 + acol + 16 * k) * 2);
        }
    }

    const int lr = lane & 15;
    const u32 brow = lr & 7, bc8 = (lr >> 3) * 8;
    const int r0 = 16 * w + (lane >> 2), cc0 = (lane & 3) * 2;
    float m_old = -FLT_MAX, lsum = 0.f;    // lsum = this thread's half-row sum
    float feat[8][4];
    #pragma unroll
    for (int cg = 0; cg < 8; cg++)
        feat[cg][0] = feat[cg][1] = feat[cg][2] = feat[cg][3] = 0.f;

    for (int s0 = 0; s0 < SS; s0 += 64) {
        {   // stage K/V hi/lo
            size_t kr = ((size_t)(b << 10) + s0 + jr) * HA + h * AA + half;
            size_t vr = ((size_t)(b * HH + h) * AA + jr) * SS + s0 + half;
            u32 ro = (u32)(jr * 72 + half) * 2;
            #pragma unroll
            for (int u = 0; u < 4; u++) {
                *(uint4*)(sm8 + O_KH + ro + u * 16) = *(const uint4*)(&g_kh[kr] + u * 8);
                *(uint4*)(sm8 + O_KL + ro + u * 16) = *(const uint4*)(&g_kl[kr] + u * 8);
                *(uint4*)(sm8 + O_VH + ro + u * 16) = *(const uint4*)(&g_vh[vr] + u * 8);
                *(uint4*)(sm8 + O_VL + ro + u * 16) = *(const uint4*)(&g_vl[vr] + u * 8);
            }
        }
        __syncthreads();
        #pragma unroll
        for (int cg = 0; cg < 8; cg++) {
            float d[4] = {0.f, 0.f, 0.f, 0.f};
            #pragma unroll
            for (int k = 0; k < 4; k++) {
                u32 off = ((cg * 8 + brow) * 72 + 16 * k + bc8) * 2;
                u32 bh[2], bl[2];
                ldmx2(bh, SB + O_KH + off);
                ldmx2(bl, SB + O_KL + off);
                mma16816(d, qhf[k], bh);
                mma16816(d, qhf[k], bl);
                mma16816(d, qlf[k], bh);
            }
            *(float2*)&Sc[r0 * 68 + cg * 8 + cc0] = make_float2(d[0], d[1]);
            *(float2*)&Sc[(r0 + 8) * 68 + cg * 8 + cc0] = make_float2(d[2], d[3]);
        }
        __syncthreads();
        {   // softmax: all 128 threads; thread owns 32 cols of row jr
            float sc[32];
            const float* sr = &Sc[jr * 68 + half];
            #pragma unroll
            for (int x = 0; x < 8; x++) {
                float4 v = *(const float4*)(sr + x * 4);
                sc[x*4] = v.x * 0.125f; sc[x*4+1] = v.y * 0.125f;
                sc[x*4+2] = v.z * 0.125f; sc[x*4+3] = v.w * 0.125f;
            }
            if (h < 2 && jr < cnt) {
                float* dst = (h == 0 ? g_sc0 : g_sc1) + (size_t)(n0 + jr) * SS + s0 + half;
                #pragma unroll
                for (int x = 0; x < 8; x++)
                    *(float4*)(dst + x * 4) =
                        make_float4(sc[x*4], sc[x*4+1], sc[x*4+2], sc[x*4+3]);
            }
            const u32* mp = (const u32*)&g_mask[b * SS + s0 + half];
            u32 mk[32];
            float cm = -FLT_MAX;
            #pragma unroll
            for (int x = 0; x < 8; x++) {
                u32 mw = mp[x];
                mk[x*4] = mw & 255u; mk[x*4+1] = (mw >> 8) & 255u;
                mk[x*4+2] = (mw >> 16) & 255u; mk[x*4+3] = mw >> 24;
                if (mk[x*4])   cm = fmaxf(cm, sc[x*4]);
                if (mk[x*4+1]) cm = fmaxf(cm, sc[x*4+1]);
                if (mk[x*4+2]) cm = fmaxf(cm, sc[x*4+2]);
                if (mk[x*4+3]) cm = fmaxf(cm, sc[x*4+3]);
            }
            cm = fmaxf(cm, __shfl_xor_sync(0xffffffffu, cm, 1));
            float m_new = fmaxf(m_old, cm);
            float alpha = (m_old == m_new) ? 1.f : __expf(m_old - m_new);
            float csum = 0.f;
            #pragma unroll
            for (int x = 0; x < 32; x++) {
                float p = mk[x] ? __expf(sc[x] - m_new) : 0.f;
                sc[x] = p; csum += p;
            }
            lsum = lsum * alpha + csum;
            m_old = m_new;
            if ((tid & 1) == 0) Al[jr] = alpha;
            u32 ro = (u32)(jr * 72 + half) * 2;
            #pragma unroll
            for (int u = 0; u < 4; u++) {
                u32 h0 = pkbf(sc[u*8], sc[u*8+1]), h1 = pkbf(sc[u*8+2], sc[u*8+3]);
                u32 h2 = pkbf(sc[u*8+4], sc[u*8+5]), h3 = pkbf(sc[u*8+6], sc[u*8+7]);
                float2 f0 = unbf(h0), f1 = unbf(h1), f2 = unbf(h2), f3 = unbf(h3);
                u32 l0 = pkbf(sc[u*8]-f0.x, sc[u*8+1]-f0.y), l1 = pkbf(sc[u*8+2]-f1.x, sc[u*8+3]-f1.y);
                u32 l2 = pkbf(sc[u*8+4]-f2.x, sc[u*8+5]-f2.y), l3 = pkbf(sc[u*8+6]-f3.x, sc[u*8+7]-f3.y);
                *(uint4*)(sm8 + O_PH + ro + u * 16) = make_uint4(h0, h1, h2, h3);
                *(uint4*)(sm8 + O_PL + ro + u * 16) = make_uint4(l0, l1, l2, l3);
            }
        }
        __syncthreads();
        {
            float a0 = Al[r0], a1 = Al[r0 + 8];
            #pragma unroll
            for (int cg = 0; cg < 8; cg++) {
                feat[cg][0] *= a0; feat[cg][1] *= a0;
                feat[cg][2] *= a1; feat[cg][3] *= a1;
            }
            u32 arow = 16 * w + (lane & 7) + ((lane >> 3) & 1) * 8;
            u32 acol = ((lane >> 4) & 1) * 8;
            u32 phf[4][4], plf[4][4];
            #pragma unroll
            for (int k = 0; k < 4; k++) {
                ldmx4(phf[k], SB + O_PH + (arow * 72 + acol + 16 * k) * 2);
                ldmx4(plf[k], SB + O_PL + (arow * 72 + acol + 16 * k) * 2);
            }
            #pragma unroll
            for (int cg = 0; cg < 8; cg++) {
                #pragma unroll
                for (int k = 0; k < 4; k++) {
                    u32 off = ((cg * 8 + brow) * 72 + 16 * k + bc8) * 2;
                    u32 bh[2], bl[2];
                    ldmx2(bh, SB + O_VH + off);
                    ldmx2(bl, SB + O_VL + off);
                    mma16816(feat[cg], phf[k], bh);
                    mma16816(feat[cg], phf[k], bl);
                    mma16816(feat[cg], plf[k], bh);
                }
            }
        }
        __syncthreads();
    }

    // pair-sum the half-row lsums; broadcast inverse per row
    float lfull = lsum + __shfl_xor_sync(0xffffffffu, lsum, 1);
    #pragma unroll
    for (int cg = 0; cg < 8; cg++) {
        *(float2*)&Sc[r0 * 68 + cg * 8 + cc0] = make_float2(feat[cg][0], feat[cg][1]);
        *(float2*)&Sc[(r0 + 8) * 68 + cg * 8 + cc0] = make_float2(feat[cg][2], feat[cg][3]);
    }
    if ((tid & 1) == 0) Al[jr] = 1.f / (lfull + 1e-9f);
    __syncthreads();
    if (tid < cnt) {
        float inv = Al[tid];
        const float* gp = &g_gate[(size_t)(n0 + tid) * HA + h * AA];
        float* fp = &g_feat[(size_t)(n0 + tid) * HA + h * AA];
        const float* sr = &Sc[tid * 68];
        #pragma unroll
        for (int x = 0; x < 16; x++) {
            float4 v = *(const float4*)(sr + x * 4);
            float4 g = *(const float4*)(gp + x * 4);
            *(float4*)(fp + x * 4) =
                make_float4(v.x * inv * g.x, v.y * inv * g.y, v.z * inv * g.z, v.w * inv * g.w);
        }
    }
}

// ---------------- logits = sc0 + sc1 ---------------------------------------
__global__ void addlog_k(float* __restrict__ logits) {
    size_t i = ((size_t)blockIdx.x * 256 + threadIdx.x) * 4;
    float4 a = *(const float4*)&g_sc0[i];
    float4 b4 = *(const float4*)&g_sc1[i];
    *(float4*)&logits[i] = make_float4(a.x + b4.x, a.y + b4.y, a.z + b4.z, a.w + b4.w);
}

// ---------------- y = sqrt(2)*x + gatedfeat @ Wback + bback ----------------
__global__ void __launch_bounds__(256) back_k(const float* __restrict__ x,
                                              const float* __restrict__ Wback,
                                              const float* __restrict__ bback) {
    __shared__ float As[16][68];
    __shared__ float Bs[16][64];
    int tid = threadIdx.x, tx = tid & 15, ty = tid >> 4;
    int m0 = blockIdx.x * 64, n0 = blockIdx.y * 64;
    ull acc[4][2] = {};
    int lm = tid >> 2, lk = (tid & 3) * 4;
    int bk = tid >> 4, bn = (tid & 15) * 4;
    for (int k0 = 0; k0 < HA; k0 += 16) {
        float4 a = *(const float4*)&g_feat[(size_t)(m0 + lm) * HA + k0 + lk];
        As[lk + 0][lm] = a.x; As[lk + 1][lm] = a.y; As[lk + 2][lm] = a.z; As[lk + 3][lm] = a.w;
        *(float4*)&Bs[bk][bn] = *(const float4*)&Wback[(size_t)(k0 + bk) * IFZ + n0 + bn];
        __syncthreads();
        #pragma unroll
        for (int kk = 0; kk < 16; kk++)
            fma8x2(acc, *(float4*)&As[kk][ty * 4], &Bs[kk][tx * 4]);
        __syncthreads();
    }
    const float rt2 = 1.41421356237309515f;
    float4 bb = *(const float4*)&bback[n0 + tx * 4];
    #pragma unroll
    for (int i = 0; i < 4; i++) {
        int row = m0 + ty * 4 + i;
        float4 xv = *(const float4*)&x[(size_t)row * IFZ + n0 + tx * 4];
        float4 cc = row4(acc[i][0], acc[i][1]);
        float4 ov;
        ov.x = rt2 * xv.x + cc.x + bb.x;
        ov.y = rt2 * xv.y + cc.y + bb.y;
        ov.z = rt2 * xv.z + cc.z + bb.z;
        ov.w = rt2 * xv.w + cc.w + bb.w;
        *(float4*)&g_y[(size_t)row * IFZ + n0 + tx * 4] = ov;
    }
}

// ---------------- LayerNorm ------------------------------------------------
__global__ void __launch_bounds__(256) ln_k(const float* __restrict__ gamma,
                                            const float* __restrict__ beta,
                                            float* __restrict__ out) {
    int warp = threadIdx.x >> 5, lane = threadIdx.x & 31;
    int row = blockIdx.x * 8 + warp;
    float4 v0 = *(const float4*)&g_y[(size_t)row * IFZ + lane * 4];
    float4 v1 = *(const float4*)&g_y[(size_t)row * IFZ + 128 + lane * 4];
    float s = v0.x + v0.y + v0.z + v0.w + v1.x + v1.y + v1.z + v1.w;
    #pragma unroll
    for (int d = 16; d; d >>= 1) s += __shfl_xor_sync(0xffffffffu, s, d);
    float mu = s * (1.f / 256.f);
    float q = 0.f;
    q += (v0.x - mu) * (v0.x - mu); q += (v0.y - mu) * (v0.y - mu);
    q += (v0.z - mu) * (v0.z - mu); q += (v0.w - mu) * (v0.w - mu);
    q += (v1.x - mu) * (v1.x - mu); q += (v1.y - mu) * (v1.y - mu);
    q += (v1.z - mu) * (v1.z - mu); q += (v1.w - mu) * (v1.w - mu);
    #pragma unroll
    for (int d = 16; d; d >>= 1) q += __shfl_xor_sync(0xffffffffu, q, d);
    float inv = rsqrtf(q * (1.f / 256.f) + 1e-5f);
    float4 g0 = *(const float4*)&gamma[lane * 4];
    float4 b0 = *(const float4*)&beta[lane * 4];
    float4 g1 = *(const float4*)&gamma[128 + lane * 4];
    float4 b1 = *(const float4*)&beta[128 + lane * 4];
    float4 o0, o1;
    o0.x = (v0.x - mu) * inv * g0.x + b0.x;
    o0.y = (v0.y - mu) * inv * g0.y + b0.y;
    o0.z = (v0.z - mu) * inv * g0.z + b0.z;
    o0.w = (v0.w - mu) * inv * g0.w + b0.w;
    o1.x = (v1.x - mu) * inv * g1.x + b1.x;
    o1.y = (v1.y - mu) * inv * g1.y + b1.y;
    o1.z = (v1.z - mu) * inv * g1.z + b1.z;
    o1.w = (v1.w - mu) * inv * g1.w + b1.w;
    *(float4*)&out[(size_t)row * IFZ + lane * 4] = o0;
    *(float4*)&out[(size_t)row * IFZ + 128 + lane * 4] = o1;
}

// ---------------- launch ---------------------------------------------------
extern "C" void kernel_launch(void* const* d_in, const int* in_sizes, int n_in,
                              void* d_out, int out_size) {
    const float* x     = (const float*)d_in[0];
    const float* emb   = (const float*)d_in[1];
    const void*  mask  = d_in[2];
    const void*  batch = d_in[3];
    const float* Wq    = (const float*)d_in[4];
    const float* Wk    = (const float*)d_in[5];
    const float* Wv    = (const float*)d_in[6];
    const float* Wg    = (const float*)d_in[7];
    const float* bg    = (const float*)d_in[8];
    const float* Wback = (const float*)d_in[9];
    const float* bback = (const float*)d_in[10];
    const float* gamma = (const float*)d_in[11];
    const float* beta  = (const float*)d_in[12];
    float* out    = (float*)d_out;
    float* logits = out + (size_t)NN * IFZ;

    static int smem_set = 0;
    if (!smem_set) {
        cudaFuncSetAttribute(attn_mma, cudaFuncAttributeMaxDynamicSharedMemorySize,
                             ATTN_SMEMB);
        smem_set = 1;
    }

    prep_k<<<1, 256>>>(mask, batch);
    conv_e_k<<<1536, 256>>>(emb);
    conv_x_k<<<512, 256>>>(x);
    conv_w_k<<<dim3(6, 16), 128>>>(Wk, Wv);
    conv_wqg_k<<<dim3(4, 16), 128>>>(Wq, Wg);
    proj_qg_mma<<<dim3(32, 16), 128>>>(bg);
    proj_kv_mma<<<dim3(64, 16), 128>>>();
    conv_v_k<<<dim3(16, HH, BBATCH), 128>>>();
    attn_mma<<<dim3(MAXT, HH), 128, ATTN_SMEMB>>>();
    addlog_k<<<2048, 256>>>(logits);
    back_k<<<dim3(32, 4), 256>>>(x, Wback, bback);
    ln_k<<<256, 256>>>(gamma, beta, out);
}

// round 14
// speedup vs baseline: 1.6359x; 1.0989x over previous
#include <cuda_runtime.h>
#include <cuda_bf16.h>
#include <float.h>
#include <math.h>

#define NN   2048
#define BBATCH 4
#define SS   1024
#define SFZ  384
#define IFZ  256
#define HH   8
#define AA   64
#define HA   512
#define MAXT 36

typedef unsigned long long ull;
typedef unsigned int u32;
typedef unsigned short u16;

__device__ __align__(16) float g_q[NN * HA];
__device__ __align__(16) float g_gate[NN * HA];
__device__ __align__(16) float g_v[BBATCH * SS * HA];
__device__ __align__(16) float g_feat[NN * HA];
__device__ __align__(16) float g_y[NN * IFZ];
__device__ __align__(16) unsigned char g_mask[BBATCH * SS];
__device__ int g_tb[MAXT], g_ts[MAXT], g_tc[MAXT], g_nt;
__device__ __align__(16) __nv_bfloat16 g_kh[BBATCH * SS * HA];
__device__ __align__(16) __nv_bfloat16 g_kl[BBATCH * SS * HA];
__device__ __align__(16) __nv_bfloat16 g_vh[BBATCH * HH * AA * SS];
__device__ __align__(16) __nv_bfloat16 g_vl[BBATCH * HH * AA * SS];
__device__ __align__(16) float g_sc0[NN * SS];
__device__ __align__(16) float g_sc1[NN * SS];
__device__ __align__(16) __nv_bfloat16 g_eh[BBATCH * SS * SFZ];
__device__ __align__(16) __nv_bfloat16 g_el[BBATCH * SS * SFZ];
__device__ __align__(16) __nv_bfloat16 g_wht[2 * HA * SFZ];
__device__ __align__(16) __nv_bfloat16 g_wlt[2 * HA * SFZ];
__device__ __align__(16) __nv_bfloat16 g_xh[NN * IFZ];
__device__ __align__(16) __nv_bfloat16 g_xl[NN * IFZ];
__device__ __align__(16) __nv_bfloat16 g_qgh[2 * HA * IFZ];
__device__ __align__(16) __nv_bfloat16 g_qgl[2 * HA * IFZ];

// ---- fp32 packed helpers ----
__device__ __forceinline__ void ffma2(ull &d, ull a, ull b) {
    asm("fma.rn.f32x2 %0, %1, %2, %0;" : "+l"(d) : "l"(a), "l"(b));
}
__device__ __forceinline__ ull pk2(float lo, float hi) {
    ull r; asm("mov.b64 %0, {%1, %2};" : "=l"(r) : "f"(lo), "f"(hi)); return r;
}
__device__ __forceinline__ float2 upk2(ull v) {
    float2 r; asm("mov.b64 {%0, %1}, %2;" : "=f"(r.x), "=f"(r.y) : "l"(v)); return r;
}
__device__ __forceinline__ void fma8x2(ull (&acc)[4][2], float4 a, const float* bp) {
    ull b0 = *(const ull*)bp, b1 = *(const ull*)(bp + 2);
    ull a0 = pk2(a.x, a.x), a1 = pk2(a.y, a.y), a2 = pk2(a.z, a.z), a3 = pk2(a.w, a.w);
    ffma2(acc[0][0], a0, b0); ffma2(acc[0][1], a0, b1);
    ffma2(acc[1][0], a1, b0); ffma2(acc[1][1], a1, b1);
    ffma2(acc[2][0], a2, b0); ffma2(acc[2][1], a2, b1);
    ffma2(acc[3][0], a3, b0); ffma2(acc[3][1], a3, b1);
}
__device__ __forceinline__ float4 row4(ull p0, ull p1) {
    float2 a = upk2(p0), b = upk2(p1);
    return make_float4(a.x, a.y, b.x, b.y);
}

// ---- bf16 split helpers ----
__device__ __forceinline__ u32 pkbf(float a, float b) {
    __nv_bfloat162 t = __float22bfloat162_rn(make_float2(a, b));
    return *(u32*)&t;
}
__device__ __forceinline__ float2 unbf(u32 h) {
    return __bfloat1622float2(*(__nv_bfloat162*)&h);
}

// ---- ldmatrix + mma.sync (baseline PTX, sm_80+) ----
static __device__ __forceinline__ u32 s2u(const void* p) {
    u32 a; asm("{.reg .u64 t; cvta.to.shared.u64 t, %1; cvt.u32.u64 %0, t;}" : "=r"(a) : "l"(p));
    return a;
}
__device__ __forceinline__ void ldmx4(u32* r, u32 a) {
    asm volatile("ldmatrix.sync.aligned.m8n8.x4.shared.b16 {%0,%1,%2,%3},[%4];"
                 : "=r"(r[0]), "=r"(r[1]), "=r"(r[2]), "=r"(r[3]) : "r"(a));
}
__device__ __forceinline__ void ldmx2(u32* r, u32 a) {
    asm volatile("ldmatrix.sync.aligned.m8n8.x2.shared.b16 {%0,%1},[%2];"
                 : "=r"(r[0]), "=r"(r[1]) : "r"(a));
}
__device__ __forceinline__ void mma16816(float* d, const u32* a, const u32* bb) {
    asm volatile("mma.sync.aligned.m16n8k16.row.col.f32.bf16.bf16.f32 "
                 "{%0,%1,%2,%3},{%4,%5,%6,%7},{%8,%9},{%0,%1,%2,%3};"
                 : "+f"(d[0]), "+f"(d[1]), "+f"(d[2]), "+f"(d[3])
                 : "r"(a[0]), "r"(a[1]), "r"(a[2]), "r"(a[3]), "r"(bb[0]), "r"(bb[1]));
}

// attn smem byte offsets (P/Sc round-trip removed; Sc only for epilogue)
#define O_QH 0
#define O_QL 9216
#define O_KH 18432
#define O_KL 27648
#define O_VH 36864
#define O_VL 46080
#define O_SC 55296
#define O_AL (O_SC + 64 * 68 * 4)
#define ATTN_SMEMB (O_AL + 256)   // 72960

// ---------------- prep ------------------------------------------------------
__global__ void prep_k(const void* mask_in, const void* batch_in) {
    __shared__ int flg[2];
    __shared__ int cnt[BBATCH];
    int tid = threadIdx.x;
    if (tid < 2) flg[tid] = 0;
    if (tid < BBATCH) cnt[tid] = 0;
    __syncthreads();
    const unsigned int* bw = (const unsigned int*)batch_in;
    unsigned int o = 0;
    for (int i = tid * 2 + 1; i < NN; i += blockDim.x * 2) o |= bw[i];
    if (o) atomicOr(&flg[0], 1);
    const unsigned char* mb = (const unsigned char*)mask_in;
    int f = 0;
    for (int i = tid; i < BBATCH * SS; i += blockDim.x)
        if ((i & 3) && mb[i]) f = 1;
    if (f) atomicOr(&flg[1], 1);
    __syncthreads();
    int is32 = flg[0], isb = flg[1];
    int lc[BBATCH] = {0, 0, 0, 0};
    for (int i = tid; i < NN; i += blockDim.x) {
        int v = is32 ? ((const int*)batch_in)[i]
                     : (int)((const long long*)batch_in)[i];
        lc[v & 3]++;
    }
    #pragma unroll
    for (int b = 0; b < BBATCH; b++) if (lc[b]) atomicAdd(&cnt[b], lc[b]);
    for (int i = tid; i < BBATCH * SS; i += blockDim.x)
        g_mask[i] = isb ? (mb[i] ? 1 : 0) : (((const int*)mask_in)[i] ? 1 : 0);
    __syncthreads();
    if (tid == 0) {
        int st = 0, t = 0;
        for (int b = 0; b < BBATCH; b++) {
            int e = st + cnt[b];
            for (int s = st; s < e; s += 64) {
                g_tb[t] = b; g_ts[t] = s; g_tc[t] = min(64, e - s); t++;
            }
            st = e;
        }
        g_nt = t;
    }
}

// ---------------- elementwise f32 -> bf16 hi/lo splitters ------------------
__global__ void conv_e_k(const float* __restrict__ emb) {
    size_t i = ((size_t)blockIdx.x * 256 + threadIdx.x) * 4;
    float4 v = *(const float4*)&emb[i];
    u32 h0 = pkbf(v.x, v.y), h1 = pkbf(v.z, v.w);
    float2 f0 = unbf(h0), f1 = unbf(h1);
    u32 l0 = pkbf(v.x - f0.x, v.y - f0.y), l1 = pkbf(v.z - f1.x, v.w - f1.y);
    *(uint2*)&g_eh[i] = make_uint2(h0, h1);
    *(uint2*)&g_el[i] = make_uint2(l0, l1);
}
__global__ void conv_x_k(const float* __restrict__ x) {
    size_t i = ((size_t)blockIdx.x * 256 + threadIdx.x) * 4;
    float4 v = *(const float4*)&x[i];
    u32 h0 = pkbf(v.x, v.y), h1 = pkbf(v.z, v.w);
    float2 f0 = unbf(h0), f1 = unbf(h1);
    u32 l0 = pkbf(v.x - f0.x, v.y - f0.y), l1 = pkbf(v.z - f1.x, v.w - f1.y);
    *(uint2*)&g_xh[i] = make_uint2(h0, h1);
    *(uint2*)&g_xl[i] = make_uint2(l0, l1);
}

// ---------------- weight transposers: W[k][n] -> Wt[n][k] bf16 hi/lo -------
__global__ void __launch_bounds__(128) conv_w_k(const float* __restrict__ Wk,
                                                const float* __restrict__ Wv) {
    __shared__ float buf[64 * 68];
    int kc = blockIdx.x * 64, ng = blockIdx.y * 64;
    const float* W = (ng < HA) ? Wk : Wv;
    int nb = ng & (HA - 1);
    int tid = threadIdx.x;
    #pragma unroll
    for (int p = 0; p < 8; p++) {
        int idx = tid + p * 128, kk = idx >> 4, nn = (idx & 15) * 4;
        *(float4*)&buf[kk * 68 + nn] =
            *(const float4*)&W[(size_t)(kc + kk) * HA + nb + nn];
    }
    __syncthreads();
    int nn = tid >> 1, kh = (tid & 1) * 32;
    u32 hv[16], lv[16];
    #pragma unroll
    for (int p = 0; p < 16; p++) {
        float x0 = buf[(kh + 2 * p) * 68 + nn], x1 = buf[(kh + 2 * p + 1) * 68 + nn];
        hv[p] = pkbf(x0, x1);
        float2 f = unbf(hv[p]);
        lv[p] = pkbf(x0 - f.x, x1 - f.y);
    }
    size_t o = (size_t)(ng + nn) * SFZ + kc + kh;
    #pragma unroll
    for (int p = 0; p < 4; p++) {
        *(uint4*)&g_wht[o + p * 8] = make_uint4(hv[4*p], hv[4*p+1], hv[4*p+2], hv[4*p+3]);
        *(uint4*)&g_wlt[o + p * 8] = make_uint4(lv[4*p], lv[4*p+1], lv[4*p+2], lv[4*p+3]);
    }
}
__global__ void __launch_bounds__(128) conv_wqg_k(const float* __restrict__ Wq,
                                                  const float* __restrict__ Wg) {
    __shared__ float buf[64 * 68];
    int kc = blockIdx.x * 64, ng = blockIdx.y * 64;
    const float* W = (ng < HA) ? Wq : Wg;
    int nb = ng & (HA - 1);
    int tid = threadIdx.x;
    #pragma unroll
    for (int p = 0; p < 8; p++) {
        int idx = tid + p * 128, kk = idx >> 4, nn = (idx & 15) * 4;
        *(float4*)&buf[kk * 68 + nn] =
            *(const float4*)&W[(size_t)(kc + kk) * HA + nb + nn];
    }
    __syncthreads();
    int nn = tid >> 1, kh = (tid & 1) * 32;
    u32 hv[16], lv[16];
    #pragma unroll
    for (int p = 0; p < 16; p++) {
        float x0 = buf[(kh + 2 * p) * 68 + nn], x1 = buf[(kh + 2 * p + 1) * 68 + nn];
        hv[p] = pkbf(x0, x1);
        float2 f = unbf(hv[p]);
        lv[p] = pkbf(x0 - f.x, x1 - f.y);
    }
    size_t o = (size_t)(ng + nn) * IFZ + kc + kh;
    #pragma unroll
    for (int p = 0; p < 4; p++) {
        *(uint4*)&g_qgh[o + p * 8] = make_uint4(hv[4*p], hv[4*p+1], hv[4*p+2], hv[4*p+3]);
        *(uint4*)&g_qgl[o + p * 8] = make_uint4(lv[4*p], lv[4*p+1], lv[4*p+2], lv[4*p+3]);
    }
}

// ---------------- q,gate = x @ Wq/Wg : mma.sync bf16 3-term ----------------
__global__ void __launch_bounds__(128) proj_qg_mma(const float* __restrict__ bg) {
    __shared__ __align__(16) unsigned char sm[36864];
    const u32 SB = s2u(sm);
    int m0 = blockIdx.x * 64, ng = blockIdx.y * 64;
    int tid = threadIdx.x, lane = tid & 31, w = tid >> 5;
    const int lr = lane & 15;
    const u32 brow = lr & 7, bc8 = (lr >> 3) * 8;
    const int r0 = 16 * w + (lane >> 2), cc0 = (lane & 3) * 2;
    u32 arow = 16 * w + (lane & 7) + ((lane >> 3) & 1) * 8;
    u32 acol = ((lane >> 4) & 1) * 8;
    float acc[8][4];
    #pragma unroll
    for (int cg = 0; cg < 8; cg++)
        acc[cg][0] = acc[cg][1] = acc[cg][2] = acc[cg][3] = 0.f;

    int r = tid >> 1, kh2 = (tid & 1) * 32;
    for (int kc = 0; kc < 4; kc++) {
        int k0 = kc * 64;
        {
            size_t xa = (size_t)(m0 + r) * IFZ + k0 + kh2;
            size_t wa = (size_t)(ng + r) * IFZ + k0 + kh2;
            u32 ro = (u32)(r * 72 + kh2) * 2;
            #pragma unroll
            for (int u = 0; u < 4; u++) {
                *(uint4*)(sm + 0     + ro + u * 16) = *(const uint4*)(&g_xh[xa] + u * 8);
                *(uint4*)(sm + 9216  + ro + u * 16) = *(const uint4*)(&g_xl[xa] + u * 8);
                *(uint4*)(sm + 18432 + ro + u * 16) = *(const uint4*)(&g_qgh[wa] + u * 8);
                *(uint4*)(sm + 27648 + ro + u * 16) = *(const uint4*)(&g_qgl[wa] + u * 8);
            }
        }
        __syncthreads();
        u32 ahf[4][4], alf[4][4];
        #pragma unroll
        for (int k = 0; k < 4; k++) {
            ldmx4(ahf[k], SB + 0    + (arow * 72 + acol + 16 * k) * 2);
            ldmx4(alf[k], SB + 9216 + (arow * 72 + acol + 16 * k) * 2);
        }
        #pragma unroll
        for (int cg = 0; cg < 8; cg++) {
            #pragma unroll
            for (int k = 0; k < 4; k++) {
                u32 off = ((cg * 8 + brow) * 72 + 16 * k + bc8) * 2;
                u32 bh[2], bl[2];
                ldmx2(bh, SB + 18432 + off);
                ldmx2(bl, SB + 27648 + off);
                mma16816(acc[cg], ahf[k], bh);
                mma16816(acc[cg], ahf[k], bl);
                mma16816(acc[cg], alf[k], bh);
            }
        }
        __syncthreads();
    }
    bool isg = (ng >= HA);
    int nc0 = ng & (HA - 1);
    if (isg) {
        #pragma unroll
        for (int cg = 0; cg < 8; cg++) {
            int c = nc0 + cg * 8 + cc0;
            float b0 = bg[c], b1 = bg[c + 1];
            float2 o0, o1;
            o0.x = 1.0f / (1.0f + __expf(-(acc[cg][0] + b0)));
            o0.y = 1.0f / (1.0f + __expf(-(acc[cg][1] + b1)));
            o1.x = 1.0f / (1.0f + __expf(-(acc[cg][2] + b0)));
            o1.y = 1.0f / (1.0f + __expf(-(acc[cg][3] + b1)));
            *(float2*)&g_gate[(size_t)(m0 + r0) * HA + c] = o0;
            *(float2*)&g_gate[(size_t)(m0 + r0 + 8) * HA + c] = o1;
        }
    } else {
        #pragma unroll
        for (int cg = 0; cg < 8; cg++) {
            int c = nc0 + cg * 8 + cc0;
            *(float2*)&g_q[(size_t)(m0 + r0) * HA + c] = make_float2(acc[cg][0], acc[cg][1]);
            *(float2*)&g_q[(size_t)(m0 + r0 + 8) * HA + c] = make_float2(acc[cg][2], acc[cg][3]);
        }
    }
}

// ---------------- k,v = emb @ Wk/Wv : mma.sync (K -> bf16 hi/lo fused) -----
__global__ void __launch_bounds__(128) proj_kv_mma() {
    __shared__ __align__(16) unsigned char sm[36864];
    const u32 SB = s2u(sm);
    int m0 = blockIdx.x * 64, ng = blockIdx.y * 64;
    int tid = threadIdx.x, lane = tid & 31, w = tid >> 5;
    const int lr = lane & 15;
    const u32 brow = lr & 7, bc8 = (lr >> 3) * 8;
    const int r0 = 16 * w + (lane >> 2), cc0 = (lane & 3) * 2;
    u32 arow = 16 * w + (lane & 7) + ((lane >> 3) & 1) * 8;
    u32 acol = ((lane >> 4) & 1) * 8;
    float acc[8][4];
    #pragma unroll
    for (int cg = 0; cg < 8; cg++)
        acc[cg][0] = acc[cg][1] = acc[cg][2] = acc[cg][3] = 0.f;

    int r = tid >> 1, kh2 = (tid & 1) * 32;
    for (int kc = 0; kc < 6; kc++) {
        int k0 = kc * 64;
        {
            size_t ea = (size_t)(m0 + r) * SFZ + k0 + kh2;
            size_t wa = (size_t)(ng + r) * SFZ + k0 + kh2;
            u32 ro = (u32)(r * 72 + kh2) * 2;
            #pragma unroll
            for (int u = 0; u < 4; u++) {
                *(uint4*)(sm + 0     + ro + u * 16) = *(const uint4*)(&g_eh[ea] + u * 8);
                *(uint4*)(sm + 9216  + ro + u * 16) = *(const uint4*)(&g_el[ea] + u * 8);
                *(uint4*)(sm + 18432 + ro + u * 16) = *(const uint4*)(&g_wht[wa] + u * 8);
                *(uint4*)(sm + 27648 + ro + u * 16) = *(const uint4*)(&g_wlt[wa] + u * 8);
            }
        }
        __syncthreads();
        u32 ahf[4][4], alf[4][4];
        #pragma unroll
        for (int k = 0; k < 4; k++) {
            ldmx4(ahf[k], SB + 0    + (arow * 72 + acol + 16 * k) * 2);
            ldmx4(alf[k], SB + 9216 + (arow * 72 + acol + 16 * k) * 2);
        }
        #pragma unroll
        for (int cg = 0; cg < 8; cg++) {
            #pragma unroll
            for (int k = 0; k < 4; k++) {
                u32 off = ((cg * 8 + brow) * 72 + 16 * k + bc8) * 2;
                u32 bh[2], bl[2];
                ldmx2(bh, SB + 18432 + off);
                ldmx2(bl, SB + 27648 + off);
                mma16816(acc[cg], ahf[k], bh);
                mma16816(acc[cg], ahf[k], bl);
                mma16816(acc[cg], alf[k], bh);
            }
        }
        __syncthreads();
    }
    bool isv = (ng >= HA);
    int nc0 = ng & (HA - 1);
    if (isv) {
        #pragma unroll
        for (int cg = 0; cg < 8; cg++) {
            int c = nc0 + cg * 8 + cc0;
            *(float2*)&g_v[(size_t)(m0 + r0) * HA + c] = make_float2(acc[cg][0], acc[cg][1]);
            *(float2*)&g_v[(size_t)(m0 + r0 + 8) * HA + c] = make_float2(acc[cg][2], acc[cg][3]);
        }
    } else {
        #pragma unroll
        for (int cg = 0; cg < 8; cg++) {
            int c = nc0 + cg * 8 + cc0;
            u32 h0 = pkbf(acc[cg][0], acc[cg][1]);
            u32 h1 = pkbf(acc[cg][2], acc[cg][3]);
            float2 f0 = unbf(h0), f1 = unbf(h1);
            u32 l0 = pkbf(acc[cg][0] - f0.x, acc[cg][1] - f0.y);
            u32 l1 = pkbf(acc[cg][2] - f1.x, acc[cg][3] - f1.y);
            *(u32*)&g_kh[(size_t)(m0 + r0) * HA + c] = h0;
            *(u32*)&g_kl[(size_t)(m0 + r0) * HA + c] = l0;
            *(u32*)&g_kh[(size_t)(m0 + r0 + 8) * HA + c] = h1;
            *(u32*)&g_kl[(size_t)(m0 + r0 + 8) * HA + c] = l1;
        }
    }
}

// ---------------- V -> transposed [b][h][a][s] bf16 hi/lo ------------------
__global__ void __launch_bounds__(128) conv_v_k() {
    __shared__ float buf[64 * 68];
    int b = blockIdx.z, h = blockIdx.y, s0 = blockIdx.x * 64;
    int tid = threadIdx.x;
    #pragma unroll
    for (int p = 0; p < 8; p++) {
        int idx = tid + p * 128, s = idx >> 4, q = idx & 15;
        *(float4*)&buf[s * 68 + q * 4] =
            *(const float4*)&g_v[((size_t)(b << 10) + s0 + s) * HA + h * AA + q * 4];
    }
    __syncthreads();
    int aa = tid >> 1, sh = (tid & 1) * 32;
    u32 hv[16], lv[16];
    #pragma unroll
    for (int p = 0; p < 16; p++) {
        float x0 = buf[(sh + 2 * p) * 68 + aa], x1 = buf[(sh + 2 * p + 1) * 68 + aa];
        hv[p] = pkbf(x0, x1);
        float2 f = unbf(hv[p]);
        lv[p] = pkbf(x0 - f.x, x1 - f.y);
    }
    size_t o = ((size_t)(b * HH + h) * AA + aa) * SS + s0 + sh;
    #pragma unroll
    for (int p = 0; p < 4; p++) {
        *(uint4*)&g_vh[o + p * 8] = make_uint4(hv[4*p], hv[4*p+1], hv[4*p+2], hv[4*p+3]);
        *(uint4*)&g_vl[o + p * 8] = make_uint4(lv[4*p], lv[4*p+1], lv[4*p+2], lv[4*p+3]);
    }
}

// ---------------- attention: register-resident flash softmax ---------------
__global__ void __launch_bounds__(128) attn_mma() {
    extern __shared__ unsigned char sm8[];
    const int t = blockIdx.x;
    if (t >= g_nt) return;
    const int h = blockIdx.y;
    const int b = g_tb[t], n0 = g_ts[t], cnt = g_tc[t];
    const int tid = threadIdx.x, lane = tid & 31, w = tid >> 5;
    const u32 SB = s2u(sm8);
    float* Sc = (float*)(sm8 + O_SC);
    float* Al = (float*)(sm8 + O_AL);
    const int jr = tid >> 1, half = (tid & 1) * 32;

    // stage Q hi/lo (once)
    {
        bool val = jr < cnt;
        const float* q = &g_q[(size_t)(n0 + jr) * HA + h * AA + half];
        u32 ro = (u32)(jr * 72 + half) * 2;
        #pragma unroll
        for (int u = 0; u < 4; u++) {
            float4 x0 = val ? *(const float4*)(q + u * 8) : make_float4(0, 0, 0, 0);
            float4 x1 = val ? *(const float4*)(q + u * 8 + 4) : make_float4(0, 0, 0, 0);
            u32 h0 = pkbf(x0.x, x0.y), h1 = pkbf(x0.z, x0.w);
            u32 h2 = pkbf(x1.x, x1.y), h3 = pkbf(x1.z, x1.w);
            float2 f0 = unbf(h0), f1 = unbf(h1), f2 = unbf(h2), f3 = unbf(h3);
            u32 l0 = pkbf(x0.x - f0.x, x0.y - f0.y), l1 = pkbf(x0.z - f1.x, x0.w - f1.y);
            u32 l2 = pkbf(x1.x - f2.x, x1.y - f2.y), l3 = pkbf(x1.z - f3.x, x1.w - f3.y);
            *(uint4*)(sm8 + O_QH + ro + u * 16) = make_uint4(h0, h1, h2, h3);
            *(uint4*)(sm8 + O_QL + ro + u * 16) = make_uint4(l0, l1, l2, l3);
        }
    }
    __syncthreads();

    u32 qhf[4][4], qlf[4][4];
    {
        u32 arow = 16 * w + (lane & 7) + ((lane >> 3) & 1) * 8;
        u32 acol = ((lane >> 4) & 1) * 8;
        #pragma unroll
        for (int k = 0; k < 4; k++) {
            ldmx4(qhf[k], SB + O_QH + (arow * 72 + acol + 16 * k) * 2);
            ldmx4(qlf[k], SB + O_QL + (arow * 72 + acol + 16 * k) * 2);
        }
    }

    const int lr = lane & 15;
    const u32 brow = lr & 7, bc8 = (lr >> 3) * 8;
    const int r0 = 16 * w + (lane >> 2), cc0 = (lane & 3) * 2;
    float mo0 = -FLT_MAX, mo1 = -FLT_MAX, ls0 = 0.f, ls1 = 0.f;
    float feat[8][4];
    #pragma unroll
    for (int cg = 0; cg < 8; cg++)
        feat[cg][0] = feat[cg][1] = feat[cg][2] = feat[cg][3] = 0.f;

    for (int s0 = 0; s0 < SS; s0 += 64) {
        {   // stage K/V hi/lo
            size_t kr = ((size_t)(b << 10) + s0 + jr) * HA + h * AA + half;
            size_t vr = ((size_t)(b * HH + h) * AA + jr) * SS + s0 + half;
            u32 ro = (u32)(jr * 72 + half) * 2;
            #pragma unroll
            for (int u = 0; u < 4; u++) {
                *(uint4*)(sm8 + O_KH + ro + u * 16) = *(const uint4*)(&g_kh[kr] + u * 8);
                *(uint4*)(sm8 + O_KL + ro + u * 16) = *(const uint4*)(&g_kl[kr] + u * 8);
                *(uint4*)(sm8 + O_VH + ro + u * 16) = *(const uint4*)(&g_vh[vr] + u * 8);
                *(uint4*)(sm8 + O_VL + ro + u * 16) = *(const uint4*)(&g_vl[vr] + u * 8);
            }
        }
        __syncthreads();
        // QK scores (fragments stay in registers)
        float d[8][4];
        #pragma unroll
        for (int cg = 0; cg < 8; cg++) {
            d[cg][0] = d[cg][1] = d[cg][2] = d[cg][3] = 0.f;
            #pragma unroll
            for (int k = 0; k < 4; k++) {
                u32 off = ((cg * 8 + brow) * 72 + 16 * k + bc8) * 2;
                u32 bh[2], bl[2];
                ldmx2(bh, SB + O_KH + off);
                ldmx2(bl, SB + O_KL + off);
                mma16816(d[cg], qhf[k], bh);
                mma16816(d[cg], qhf[k], bl);
                mma16816(d[cg], qlf[k], bh);
            }
            d[cg][0] *= 0.125f; d[cg][1] *= 0.125f;
            d[cg][2] *= 0.125f; d[cg][3] *= 0.125f;
        }
        // logits (raw scores) for heads 0,1
        if (h < 2) {
            float* base = (h == 0 ? g_sc0 : g_sc1);
            #pragma unroll
            for (int cg = 0; cg < 8; cg++) {
                int c = s0 + cg * 8 + cc0;
                if (r0 < cnt)
                    *(float2*)&base[(size_t)(n0 + r0) * SS + c] = make_float2(d[cg][0], d[cg][1]);
                if (r0 + 8 < cnt)
                    *(float2*)&base[(size_t)(n0 + r0 + 8) * SS + c] = make_float2(d[cg][2], d[cg][3]);
            }
        }
        // mask (2 bytes per cg)
        u16 mw[8];
        #pragma unroll
        for (int cg = 0; cg < 8; cg++)
            mw[cg] = *(const u16*)&g_mask[b * SS + s0 + cg * 8 + cc0];
        // row max (quad = lanes sharing rows)
        float cm0 = -FLT_MAX, cm1 = -FLT_MAX;
        #pragma unroll
        for (int cg = 0; cg < 8; cg++) {
            if (mw[cg] & 0xff) { cm0 = fmaxf(cm0, d[cg][0]); cm1 = fmaxf(cm1, d[cg][2]); }
            if (mw[cg] >> 8)   { cm0 = fmaxf(cm0, d[cg][1]); cm1 = fmaxf(cm1, d[cg][3]); }
        }
        cm0 = fmaxf(cm0, __shfl_xor_sync(0xffffffffu, cm0, 1));
        cm0 = fmaxf(cm0, __shfl_xor_sync(0xffffffffu, cm0, 2));
        cm1 = fmaxf(cm1, __shfl_xor_sync(0xffffffffu, cm1, 1));
        cm1 = fmaxf(cm1, __shfl_xor_sync(0xffffffffu, cm1, 2));
        float mn0 = fmaxf(mo0, cm0), mn1 = fmaxf(mo1, cm1);
        float a0 = (mo0 == mn0) ? 1.f : __expf(mo0 - mn0);
        float a1 = (mo1 == mn1) ? 1.f : __expf(mo1 - mn1);
        float cs0 = 0.f, cs1 = 0.f;
        u32 phf[4][4], plf[4][4];
        #pragma unroll
        for (int cg = 0; cg < 8; cg++) {
            float p0 = (mw[cg] & 0xff) ? __expf(d[cg][0] - mn0) : 0.f;
            float p1 = (mw[cg] >> 8)   ? __expf(d[cg][1] - mn0) : 0.f;
            float p2 = (mw[cg] & 0xff) ? __expf(d[cg][2] - mn1) : 0.f;
            float p3 = (mw[cg] >> 8)   ? __expf(d[cg][3] - mn1) : 0.f;
            cs0 += p0 + p1; cs1 += p2 + p3;
            // pack into A-fragments: kchunk = cg>>1, slot = (cg&1)*2
            u32 hA = pkbf(p0, p1), hB = pkbf(p2, p3);
            float2 fA = unbf(hA), fB = unbf(hB);
            u32 lA = pkbf(p0 - fA.x, p1 - fA.y), lB = pkbf(p2 - fB.x, p3 - fB.y);
            phf[cg >> 1][(cg & 1) * 2]     = hA;
            phf[cg >> 1][(cg & 1) * 2 + 1] = hB;
            plf[cg >> 1][(cg & 1) * 2]     = lA;
            plf[cg >> 1][(cg & 1) * 2 + 1] = lB;
        }
        ls0 = ls0 * a0 + cs0;  ls1 = ls1 * a1 + cs1;
        mo0 = mn0;  mo1 = mn1;
        // rescale running feat and PV accumulate
        #pragma unroll
        for (int cg = 0; cg < 8; cg++) {
            feat[cg][0] *= a0; feat[cg][1] *= a0;
            feat[cg][2] *= a1; feat[cg][3] *= a1;
            #pragma unroll
            for (int k = 0; k < 4; k++) {
                u32 off = ((cg * 8 + brow) * 72 + 16 * k + bc8) * 2;
                u32 bh[2], bl[2];
                ldmx2(bh, SB + O_VH + off);
                ldmx2(bl, SB + O_VL + off);
                mma16816(feat[cg], phf[k], bh);
                mma16816(feat[cg], phf[k], bl);
                mma16816(feat[cg], plf[k], bh);
            }
        }
        __syncthreads();
    }

    // final row sums (quad reduce), dump feat to Sc, epilogue
    ls0 += __shfl_xor_sync(0xffffffffu, ls0, 1);
    ls0 += __shfl_xor_sync(0xffffffffu, ls0, 2);
    ls1 += __shfl_xor_sync(0xffffffffu, ls1, 1);
    ls1 += __shfl_xor_sync(0xffffffffu, ls1, 2);
    #pragma unroll
    for (int cg = 0; cg < 8; cg++) {
        *(float2*)&Sc[r0 * 68 + cg * 8 + cc0] = make_float2(feat[cg][0], feat[cg][1]);
        *(float2*)&Sc[(r0 + 8) * 68 + cg * 8 + cc0] = make_float2(feat[cg][2], feat[cg][3]);
    }
    if ((lane & 3) == 0) {
        Al[r0] = 1.f / (ls0 + 1e-9f);
        Al[r0 + 8] = 1.f / (ls1 + 1e-9f);
    }
    __syncthreads();
    if (tid < cnt) {
        float inv = Al[tid];
        const float* gp = &g_gate[(size_t)(n0 + tid) * HA + h * AA];
        float* fp = &g_feat[(size_t)(n0 + tid) * HA + h * AA];
        const float* sr = &Sc[tid * 68];
        #pragma unroll
        for (int x = 0; x < 16; x++) {
            float4 v = *(const float4*)(sr + x * 4);
            float4 g = *(const float4*)(gp + x * 4);
            *(float4*)(fp + x * 4) =
                make_float4(v.x * inv * g.x, v.y * inv * g.y, v.z * inv * g.z, v.w * inv * g.w);
        }
    }
}

// ---------------- logits = sc0 + sc1 ---------------------------------------
__global__ void addlog_k(float* __restrict__ logits) {
    size_t i = ((size_t)blockIdx.x * 256 + threadIdx.x) * 4;
    float4 a = *(const float4*)&g_sc0[i];
    float4 b4 = *(const float4*)&g_sc1[i];
    *(float4*)&logits[i] = make_float4(a.x + b4.x, a.y + b4.y, a.z + b4.z, a.w + b4.w);
}

// ---------------- y = sqrt(2)*x + gatedfeat @ Wback + bback ----------------
__global__ void __launch_bounds__(256) back_k(const float* __restrict__ x,
                                              const float* __restrict__ Wback,
                                              const float* __restrict__ bback) {
    __shared__ float As[16][68];
    __shared__ float Bs[16][64];
    int tid = threadIdx.x, tx = tid & 15, ty = tid >> 4;
    int m0 = blockIdx.x * 64, n0 = blockIdx.y * 64;
    ull acc[4][2] = {};
    int lm = tid >> 2, lk = (tid & 3) * 4;
    int bk = tid >> 4, bn = (tid & 15) * 4;
    for (int k0 = 0; k0 < HA; k0 += 16) {
        float4 a = *(const float4*)&g_feat[(size_t)(m0 + lm) * HA + k0 + lk];
        As[lk + 0][lm] = a.x; As[lk + 1][lm] = a.y; As[lk + 2][lm] = a.z; As[lk + 3][lm] = a.w;
        *(float4*)&Bs[bk][bn] = *(const float4*)&Wback[(size_t)(k0 + bk) * IFZ + n0 + bn];
        __syncthreads();
        #pragma unroll
        for (int kk = 0; kk < 16; kk++)
            fma8x2(acc, *(float4*)&As[kk][ty * 4], &Bs[kk][tx * 4]);
        __syncthreads();
    }
    const float rt2 = 1.41421356237309515f;
    float4 bb = *(const float4*)&bback[n0 + tx * 4];
    #pragma unroll
    for (int i = 0; i < 4; i++) {
        int row = m0 + ty * 4 + i;
        float4 xv = *(const float4*)&x[(size_t)row * IFZ + n0 + tx * 4];
        float4 cc = row4(acc[i][0], acc[i][1]);
        float4 ov;
        ov.x = rt2 * xv.x + cc.x + bb.x;
        ov.y = rt2 * xv.y + cc.y + bb.y;
        ov.z = rt2 * xv.z + cc.z + bb.z;
        ov.w = rt2 * xv.w + cc.w + bb.w;
        *(float4*)&g_y[(size_t)row * IFZ + n0 + tx * 4] = ov;
    }
}

// ---------------- LayerNorm ------------------------------------------------
__global__ void __launch_bounds__(256) ln_k(const float* __restrict__ gamma,
                                            const float* __restrict__ beta,
                                            float* __restrict__ out) {
    int warp = threadIdx.x >> 5, lane = threadIdx.x & 31;
    int row = blockIdx.x * 8 + warp;
    float4 v0 = *(const float4*)&g_y[(size_t)row * IFZ + lane * 4];
    float4 v1 = *(const float4*)&g_y[(size_t)row * IFZ + 128 + lane * 4];
    float s = v0.x + v0.y + v0.z + v0.w + v1.x + v1.y + v1.z + v1.w;
    #pragma unroll
    for (int d = 16; d; d >>= 1) s += __shfl_xor_sync(0xffffffffu, s, d);
    float mu = s * (1.f / 256.f);
    float q = 0.f;
    q += (v0.x - mu) * (v0.x - mu); q += (v0.y - mu) * (v0.y - mu);
    q += (v0.z - mu) * (v0.z - mu); q += (v0.w - mu) * (v0.w - mu);
    q += (v1.x - mu) * (v1.x - mu); q += (v1.y - mu) * (v1.y - mu);
    q += (v1.z - mu) * (v1.z - mu); q += (v1.w - mu) * (v1.w - mu);
    #pragma unroll
    for (int d = 16; d; d >>= 1) q += __shfl_xor_sync(0xffffffffu, q, d);
    float inv = rsqrtf(q * (1.f / 256.f) + 1e-5f);
    float4 g0 = *(const float4*)&gamma[lane * 4];
    float4 b0 = *(const float4*)&beta[lane * 4];
    float4 g1 = *(const float4*)&gamma[128 + lane * 4];
    float4 b1 = *(const float4*)&beta[128 + lane * 4];
    float4 o0, o1;
    o0.x = (v0.x - mu) * inv * g0.x + b0.x;
    o0.y = (v0.y - mu) * inv * g0.y + b0.y;
    o0.z = (v0.z - mu) * inv * g0.z + b0.z;
    o0.w = (v0.w - mu) * inv * g0.w + b0.w;
    o1.x = (v1.x - mu) * inv * g1.x + b1.x;
    o1.y = (v1.y - mu) * inv * g1.y + b1.y;
    o1.z = (v1.z - mu) * inv * g1.z + b1.z;
    o1.w = (v1.w - mu) * inv * g1.w + b1.w;
    *(float4*)&out[(size_t)row * IFZ + lane * 4] = o0;
    *(float4*)&out[(size_t)row * IFZ + 128 + lane * 4] = o1;
}

// ---------------- launch ---------------------------------------------------
extern "C" void kernel_launch(void* const* d_in, const int* in_sizes, int n_in,
                              void* d_out, int out_size) {
    const float* x     = (const float*)d_in[0];
    const float* emb   = (const float*)d_in[1];
    const void*  mask  = d_in[2];
    const void*  batch = d_in[3];
    const float* Wq    = (const float*)d_in[4];
    const float* Wk    = (const float*)d_in[5];
    const float* Wv    = (const float*)d_in[6];
    const float* Wg    = (const float*)d_in[7];
    const float* bg    = (const float*)d_in[8];
    const float* Wback = (const float*)d_in[9];
    const float* bback = (const float*)d_in[10];
    const float* gamma = (const float*)d_in[11];
    const float* beta  = (const float*)d_in[12];
    float* out    = (float*)d_out;
    float* logits = out + (size_t)NN * IFZ;

    static int smem_set = 0;
    if (!smem_set) {
        cudaFuncSetAttribute(attn_mma, cudaFuncAttributeMaxDynamicSharedMemorySize,
                             ATTN_SMEMB);
        smem_set = 1;
    }

    prep_k<<<1, 256>>>(mask, batch);
    conv_e_k<<<1536, 256>>>(emb);
    conv_x_k<<<512, 256>>>(x);
    conv_w_k<<<dim3(6, 16), 128>>>(Wk, Wv);
    conv_wqg_k<<<dim3(4, 16), 128>>>(Wq, Wg);
    proj_qg_mma<<<dim3(32, 16), 128>>>(bg);
    proj_kv_mma<<<dim3(64, 16), 128>>>();
    conv_v_k<<<dim3(16, HH, BBATCH), 128>>>();
    attn_mma<<<dim3(MAXT, HH), 128, ATTN_SMEMB>>>();
    addlog_k<<<2048, 256>>>(logits);
    back_k<<<dim3(32, 4), 256>>>(x, Wback, bback);
    ln_k<<<256, 256>>>(gamma, beta, out);
}

// round 15
// speedup vs baseline: 1.7320x; 1.0588x over previous
#include <cuda_runtime.h>
#include <cuda_bf16.h>
#include <float.h>
#include <math.h>

#define NN   2048
#define BBATCH 4
#define SS   1024
#define SFZ  384
#define IFZ  256
#define HH   8
#define AA   64
#define HA   512
#define MAXT 36

typedef unsigned long long ull;
typedef unsigned int u32;
typedef unsigned short u16;

__device__ __align__(16) float g_q[NN * HA];
__device__ __align__(16) float g_gate[NN * HA];
__device__ __align__(16) float g_v[BBATCH * SS * HA];
__device__ __align__(16) float g_y[NN * IFZ];
__device__ __align__(16) unsigned char g_mask[BBATCH * SS];
__device__ int g_tb[MAXT], g_ts[MAXT], g_tc[MAXT], g_nt;
__device__ __align__(16) __nv_bfloat16 g_kh[BBATCH * SS * HA];
__device__ __align__(16) __nv_bfloat16 g_kl[BBATCH * SS * HA];
__device__ __align__(16) __nv_bfloat16 g_vh[BBATCH * HH * AA * SS];
__device__ __align__(16) __nv_bfloat16 g_vl[BBATCH * HH * AA * SS];
__device__ __align__(16) float g_sc0[NN * SS];
__device__ __align__(16) float g_sc1[NN * SS];
__device__ __align__(16) __nv_bfloat16 g_eh[BBATCH * SS * SFZ];
__device__ __align__(16) __nv_bfloat16 g_el[BBATCH * SS * SFZ];
__device__ __align__(16) __nv_bfloat16 g_wht[2 * HA * SFZ];
__device__ __align__(16) __nv_bfloat16 g_wlt[2 * HA * SFZ];
__device__ __align__(16) __nv_bfloat16 g_xh[NN * IFZ];
__device__ __align__(16) __nv_bfloat16 g_xl[NN * IFZ];
__device__ __align__(16) __nv_bfloat16 g_qgh[2 * HA * IFZ];
__device__ __align__(16) __nv_bfloat16 g_qgl[2 * HA * IFZ];
__device__ __align__(16) __nv_bfloat16 g_fh[NN * HA];
__device__ __align__(16) __nv_bfloat16 g_fl[NN * HA];
__device__ __align__(16) __nv_bfloat16 g_wbh[IFZ * HA];
__device__ __align__(16) __nv_bfloat16 g_wbl[IFZ * HA];

// ---- bf16 split helpers ----
__device__ __forceinline__ u32 pkbf(float a, float b) {
    __nv_bfloat162 t = __float22bfloat162_rn(make_float2(a, b));
    return *(u32*)&t;
}
__device__ __forceinline__ float2 unbf(u32 h) {
    return __bfloat1622float2(*(__nv_bfloat162*)&h);
}

// ---- ldmatrix + mma.sync (baseline PTX, sm_80+) ----
static __device__ __forceinline__ u32 s2u(const void* p) {
    u32 a; asm("{.reg .u64 t; cvta.to.shared.u64 t, %1; cvt.u32.u64 %0, t;}" : "=r"(a) : "l"(p));
    return a;
}
__device__ __forceinline__ void ldmx4(u32* r, u32 a) {
    asm volatile("ldmatrix.sync.aligned.m8n8.x4.shared.b16 {%0,%1,%2,%3},[%4];"
                 : "=r"(r[0]), "=r"(r[1]), "=r"(r[2]), "=r"(r[3]) : "r"(a));
}
__device__ __forceinline__ void ldmx2(u32* r, u32 a) {
    asm volatile("ldmatrix.sync.aligned.m8n8.x2.shared.b16 {%0,%1},[%2];"
                 : "=r"(r[0]), "=r"(r[1]) : "r"(a));
}
__device__ __forceinline__ void mma16816(float* d, const u32* a, const u32* bb) {
    asm volatile("mma.sync.aligned.m16n8k16.row.col.f32.bf16.bf16.f32 "
                 "{%0,%1,%2,%3},{%4,%5,%6,%7},{%8,%9},{%0,%1,%2,%3};"
                 : "+f"(d[0]), "+f"(d[1]), "+f"(d[2]), "+f"(d[3])
                 : "r"(a[0]), "r"(a[1]), "r"(a[2]), "r"(a[3]), "r"(bb[0]), "r"(bb[1]));
}

// attn smem layout: Q (fragments loaded once) aliased by Sc/Al; double K/V bufs
#define O_QH 0
#define O_QL 9216
#define O_SC 0
#define O_AL 17408
#define O_B0 18432
#define O_B1 55296
#define ATTN_SMEMB 92160

// ---------------- prep ------------------------------------------------------
__global__ void prep_k(const void* mask_in, const void* batch_in) {
    __shared__ int flg[2];
    __shared__ int cnt[BBATCH];
    int tid = threadIdx.x;
    if (tid < 2) flg[tid] = 0;
    if (tid < BBATCH) cnt[tid] = 0;
    __syncthreads();
    const unsigned int* bw = (const unsigned int*)batch_in;
    unsigned int o = 0;
    for (int i = tid * 2 + 1; i < NN; i += blockDim.x * 2) o |= bw[i];
    if (o) atomicOr(&flg[0], 1);
    const unsigned char* mb = (const unsigned char*)mask_in;
    int f = 0;
    for (int i = tid; i < BBATCH * SS; i += blockDim.x)
        if ((i & 3) && mb[i]) f = 1;
    if (f) atomicOr(&flg[1], 1);
    __syncthreads();
    int is32 = flg[0], isb = flg[1];
    int lc[BBATCH] = {0, 0, 0, 0};
    for (int i = tid; i < NN; i += blockDim.x) {
        int v = is32 ? ((const int*)batch_in)[i]
                     : (int)((const long long*)batch_in)[i];
        lc[v & 3]++;
    }
    #pragma unroll
    for (int b = 0; b < BBATCH; b++) if (lc[b]) atomicAdd(&cnt[b], lc[b]);
    for (int i = tid; i < BBATCH * SS; i += blockDim.x)
        g_mask[i] = isb ? (mb[i] ? 1 : 0) : (((const int*)mask_in)[i] ? 1 : 0);
    __syncthreads();
    if (tid == 0) {
        int st = 0, t = 0;
        for (int b = 0; b < BBATCH; b++) {
            int e = st + cnt[b];
            for (int s = st; s < e; s += 64) {
                g_tb[t] = b; g_ts[t] = s; g_tc[t] = min(64, e - s); t++;
            }
            st = e;
        }
        g_nt = t;
    }
}

// ---------------- elementwise f32 -> bf16 hi/lo splitters ------------------
__global__ void conv_e_k(const float* __restrict__ emb) {
    size_t i = ((size_t)blockIdx.x * 256 + threadIdx.x) * 4;
    float4 v = *(const float4*)&emb[i];
    u32 h0 = pkbf(v.x, v.y), h1 = pkbf(v.z, v.w);
    float2 f0 = unbf(h0), f1 = unbf(h1);
    u32 l0 = pkbf(v.x - f0.x, v.y - f0.y), l1 = pkbf(v.z - f1.x, v.w - f1.y);
    *(uint2*)&g_eh[i] = make_uint2(h0, h1);
    *(uint2*)&g_el[i] = make_uint2(l0, l1);
}
__global__ void conv_x_k(const float* __restrict__ x) {
    size_t i = ((size_t)blockIdx.x * 256 + threadIdx.x) * 4;
    float4 v = *(const float4*)&x[i];
    u32 h0 = pkbf(v.x, v.y), h1 = pkbf(v.z, v.w);
    float2 f0 = unbf(h0), f1 = unbf(h1);
    u32 l0 = pkbf(v.x - f0.x, v.y - f0.y), l1 = pkbf(v.z - f1.x, v.w - f1.y);
    *(uint2*)&g_xh[i] = make_uint2(h0, h1);
    *(uint2*)&g_xl[i] = make_uint2(l0, l1);
}

// ---------------- weight transposers: W[k][n] -> Wt[n][k] bf16 hi/lo -------
__global__ void __launch_bounds__(128) conv_w_k(const float* __restrict__ Wk,
                                                const float* __restrict__ Wv) {
    __shared__ float buf[64 * 68];
    int kc = blockIdx.x * 64, ng = blockIdx.y * 64;
    const float* W = (ng < HA) ? Wk : Wv;
    int nb = ng & (HA - 1);
    int tid = threadIdx.x;
    #pragma unroll
    for (int p = 0; p < 8; p++) {
        int idx = tid + p * 128, kk = idx >> 4, nn = (idx & 15) * 4;
        *(float4*)&buf[kk * 68 + nn] =
            *(const float4*)&W[(size_t)(kc + kk) * HA + nb + nn];
    }
    __syncthreads();
    int nn = tid >> 1, kh = (tid & 1) * 32;
    u32 hv[16], lv[16];
    #pragma unroll
    for (int p = 0; p < 16; p++) {
        float x0 = buf[(kh + 2 * p) * 68 + nn], x1 = buf[(kh + 2 * p + 1) * 68 + nn];
        hv[p] = pkbf(x0, x1);
        float2 f = unbf(hv[p]);
        lv[p] = pkbf(x0 - f.x, x1 - f.y);
    }
    size_t o = (size_t)(ng + nn) * SFZ + kc + kh;
    #pragma unroll
    for (int p = 0; p < 4; p++) {
        *(uint4*)&g_wht[o + p * 8] = make_uint4(hv[4*p], hv[4*p+1], hv[4*p+2], hv[4*p+3]);
        *(uint4*)&g_wlt[o + p * 8] = make_uint4(lv[4*p], lv[4*p+1], lv[4*p+2], lv[4*p+3]);
    }
}
__global__ void __launch_bounds__(128) conv_wqg_k(const float* __restrict__ Wq,
                                                  const float* __restrict__ Wg) {
    __shared__ float buf[64 * 68];
    int kc = blockIdx.x * 64, ng = blockIdx.y * 64;
    const float* W = (ng < HA) ? Wq : Wg;
    int nb = ng & (HA - 1);
    int tid = threadIdx.x;
    #pragma unroll
    for (int p = 0; p < 8; p++) {
        int idx = tid + p * 128, kk = idx >> 4, nn = (idx & 15) * 4;
        *(float4*)&buf[kk * 68 + nn] =
            *(const float4*)&W[(size_t)(kc + kk) * HA + nb + nn];
    }
    __syncthreads();
    int nn = tid >> 1, kh = (tid & 1) * 32;
    u32 hv[16], lv[16];
    #pragma unroll
    for (int p = 0; p < 16; p++) {
        float x0 = buf[(kh + 2 * p) * 68 + nn], x1 = buf[(kh + 2 * p + 1) * 68 + nn];
        hv[p] = pkbf(x0, x1);
        float2 f = unbf(hv[p]);
        lv[p] = pkbf(x0 - f.x, x1 - f.y);
    }
    size_t o = (size_t)(ng + nn) * IFZ + kc + kh;
    #pragma unroll
    for (int p = 0; p < 4; p++) {
        *(uint4*)&g_qgh[o + p * 8] = make_uint4(hv[4*p], hv[4*p+1], hv[4*p+2], hv[4*p+3]);
        *(uint4*)&g_qgl[o + p * 8] = make_uint4(lv[4*p], lv[4*p+1], lv[4*p+2], lv[4*p+3]);
    }
}
__global__ void __launch_bounds__(128) conv_wb_k(const float* __restrict__ Wb) {
    __shared__ float buf[64 * 68];
    int kc = blockIdx.x * 64, ng = blockIdx.y * 64;
    int tid = threadIdx.x;
    #pragma unroll
    for (int p = 0; p < 8; p++) {
        int idx = tid + p * 128, kk = idx >> 4, nn = (idx & 15) * 4;
        *(float4*)&buf[kk * 68 + nn] =
            *(const float4*)&Wb[(size_t)(kc + kk) * IFZ + ng + nn];
    }
    __syncthreads();
    int nn = tid >> 1, kh = (tid & 1) * 32;
    u32 hv[16], lv[16];
    #pragma unroll
    for (int p = 0; p < 16; p++) {
        float x0 = buf[(kh + 2 * p) * 68 + nn], x1 = buf[(kh + 2 * p + 1) * 68 + nn];
        hv[p] = pkbf(x0, x1);
        float2 f = unbf(hv[p]);
        lv[p] = pkbf(x0 - f.x, x1 - f.y);
    }
    size_t o = (size_t)(ng + nn) * HA + kc + kh;
    #pragma unroll
    for (int p = 0; p < 4; p++) {
        *(uint4*)&g_wbh[o + p * 8] = make_uint4(hv[4*p], hv[4*p+1], hv[4*p+2], hv[4*p+3]);
        *(uint4*)&g_wbl[o + p * 8] = make_uint4(lv[4*p], lv[4*p+1], lv[4*p+2], lv[4*p+3]);
    }
}

// ---------------- q,gate = x @ Wq/Wg : mma.sync bf16 3-term ----------------
__global__ void __launch_bounds__(128) proj_qg_mma(const float* __restrict__ bg) {
    __shared__ __align__(16) unsigned char sm[36864];
    const u32 SB = s2u(sm);
    int m0 = blockIdx.x * 64, ng = blockIdx.y * 64;
    int tid = threadIdx.x, lane = tid & 31, w = tid >> 5;
    const int lr = lane & 15;
    const u32 brow = lr & 7, bc8 = (lr >> 3) * 8;
    const int r0 = 16 * w + (lane >> 2), cc0 = (lane & 3) * 2;
    u32 arow = 16 * w + (lane & 7) + ((lane >> 3) & 1) * 8;
    u32 acol = ((lane >> 4) & 1) * 8;
    float acc[8][4];
    #pragma unroll
    for (int cg = 0; cg < 8; cg++)
        acc[cg][0] = acc[cg][1] = acc[cg][2] = acc[cg][3] = 0.f;
    int r = tid >> 1, kh2 = (tid & 1) * 32;
    for (int kc = 0; kc < 4; kc++) {
        int k0 = kc * 64;
        {
            size_t xa = (size_t)(m0 + r) * IFZ + k0 + kh2;
            size_t wa = (size_t)(ng + r) * IFZ + k0 + kh2;
            u32 ro = (u32)(r * 72 + kh2) * 2;
            #pragma unroll
            for (int u = 0; u < 4; u++) {
                *(uint4*)(sm + 0     + ro + u * 16) = *(const uint4*)(&g_xh[xa] + u * 8);
                *(uint4*)(sm + 9216  + ro + u * 16) = *(const uint4*)(&g_xl[xa] + u * 8);
                *(uint4*)(sm + 18432 + ro + u * 16) = *(const uint4*)(&g_qgh[wa] + u * 8);
                *(uint4*)(sm + 27648 + ro + u * 16) = *(const uint4*)(&g_qgl[wa] + u * 8);
            }
        }
        __syncthreads();
        u32 ahf[4][4], alf[4][4];
        #pragma unroll
        for (int k = 0; k < 4; k++) {
            ldmx4(ahf[k], SB + 0    + (arow * 72 + acol + 16 * k) * 2);
            ldmx4(alf[k], SB + 9216 + (arow * 72 + acol + 16 * k) * 2);
        }
        #pragma unroll
        for (int cg = 0; cg < 8; cg++) {
            #pragma unroll
            for (int k = 0; k < 4; k++) {
                u32 off = ((cg * 8 + brow) * 72 + 16 * k + bc8) * 2;
                u32 bh[2], bl[2];
                ldmx2(bh, SB + 18432 + off);
                ldmx2(bl, SB + 27648 + off);
                mma16816(acc[cg], ahf[k], bh);
                mma16816(acc[cg], ahf[k], bl);
                mma16816(acc[cg], alf[k], bh);
            }
        }
        __syncthreads();
    }
    bool isg = (ng >= HA);
    int nc0 = ng & (HA - 1);
    if (isg) {
        #pragma unroll
        for (int cg = 0; cg < 8; cg++) {
            int c = nc0 + cg * 8 + cc0;
            float b0 = bg[c], b1 = bg[c + 1];
            float2 o0, o1;
            o0.x = 1.0f / (1.0f + __expf(-(acc[cg][0] + b0)));
            o0.y = 1.0f / (1.0f + __expf(-(acc[cg][1] + b1)));
            o1.x = 1.0f / (1.0f + __expf(-(acc[cg][2] + b0)));
            o1.y = 1.0f / (1.0f + __expf(-(acc[cg][3] + b1)));
            *(float2*)&g_gate[(size_t)(m0 + r0) * HA + c] = o0;
            *(float2*)&g_gate[(size_t)(m0 + r0 + 8) * HA + c] = o1;
        }
    } else {
        #pragma unroll
        for (int cg = 0; cg < 8; cg++) {
            int c = nc0 + cg * 8 + cc0;
            *(float2*)&g_q[(size_t)(m0 + r0) * HA + c] = make_float2(acc[cg][0], acc[cg][1]);
            *(float2*)&g_q[(size_t)(m0 + r0 + 8) * HA + c] = make_float2(acc[cg][2], acc[cg][3]);
        }
    }
}

// ---------------- k,v = emb @ Wk/Wv : mma.sync (K -> bf16 hi/lo fused) -----
__global__ void __launch_bounds__(128) proj_kv_mma() {
    __shared__ __align__(16) unsigned char sm[36864];
    const u32 SB = s2u(sm);
    int m0 = blockIdx.x * 64, ng = blockIdx.y * 64;
    int tid = threadIdx.x, lane = tid & 31, w = tid >> 5;
    const int lr = lane & 15;
    const u32 brow = lr & 7, bc8 = (lr >> 3) * 8;
    const int r0 = 16 * w + (lane >> 2), cc0 = (lane & 3) * 2;
    u32 arow = 16 * w + (lane & 7) + ((lane >> 3) & 1) * 8;
    u32 acol = ((lane >> 4) & 1) * 8;
    float acc[8][4];
    #pragma unroll
    for (int cg = 0; cg < 8; cg++)
        acc[cg][0] = acc[cg][1] = acc[cg][2] = acc[cg][3] = 0.f;
    int r = tid >> 1, kh2 = (tid & 1) * 32;
    for (int kc = 0; kc < 6; kc++) {
        int k0 = kc * 64;
        {
            size_t ea = (size_t)(m0 + r) * SFZ + k0 + kh2;
            size_t wa = (size_t)(ng + r) * SFZ + k0 + kh2;
            u32 ro = (u32)(r * 72 + kh2) * 2;
            #pragma unroll
            for (int u = 0; u < 4; u++) {
                *(uint4*)(sm + 0     + ro + u * 16) = *(const uint4*)(&g_eh[ea] + u * 8);
                *(uint4*)(sm + 9216  + ro + u * 16) = *(const uint4*)(&g_el[ea] + u * 8);
                *(uint4*)(sm + 18432 + ro + u * 16) = *(const uint4*)(&g_wht[wa] + u * 8);
                *(uint4*)(sm + 27648 + ro + u * 16) = *(const uint4*)(&g_wlt[wa] + u * 8);
            }
        }
        __syncthreads();
        u32 ahf[4][4], alf[4][4];
        #pragma unroll
        for (int k = 0; k < 4; k++) {
            ldmx4(ahf[k], SB + 0    + (arow * 72 + acol + 16 * k) * 2);
            ldmx4(alf[k], SB + 9216 + (arow * 72 + acol + 16 * k) * 2);
        }
        #pragma unroll
        for (int cg = 0; cg < 8; cg++) {
            #pragma unroll
            for (int k = 0; k < 4; k++) {
                u32 off = ((cg * 8 + brow) * 72 + 16 * k + bc8) * 2;
                u32 bh[2], bl[2];
                ldmx2(bh, SB + 18432 + off);
                ldmx2(bl, SB + 27648 + off);
                mma16816(acc[cg], ahf[k], bh);
                mma16816(acc[cg], ahf[k], bl);
                mma16816(acc[cg], alf[k], bh);
            }
        }
        __syncthreads();
    }
    bool isv = (ng >= HA);
    int nc0 = ng & (HA - 1);
    if (isv) {
        #pragma unroll
        for (int cg = 0; cg < 8; cg++) {
            int c = nc0 + cg * 8 + cc0;
            *(float2*)&g_v[(size_t)(m0 + r0) * HA + c] = make_float2(acc[cg][0], acc[cg][1]);
            *(float2*)&g_v[(size_t)(m0 + r0 + 8) * HA + c] = make_float2(acc[cg][2], acc[cg][3]);
        }
    } else {
        #pragma unroll
        for (int cg = 0; cg < 8; cg++) {
            int c = nc0 + cg * 8 + cc0;
            u32 h0 = pkbf(acc[cg][0], acc[cg][1]);
            u32 h1 = pkbf(acc[cg][2], acc[cg][3]);
            float2 f0 = unbf(h0), f1 = unbf(h1);
            u32 l0 = pkbf(acc[cg][0] - f0.x, acc[cg][1] - f0.y);
            u32 l1 = pkbf(acc[cg][2] - f1.x, acc[cg][3] - f1.y);
            *(u32*)&g_kh[(size_t)(m0 + r0) * HA + c] = h0;
            *(u32*)&g_kl[(size_t)(m0 + r0) * HA + c] = l0;
            *(u32*)&g_kh[(size_t)(m0 + r0 + 8) * HA + c] = h1;
            *(u32*)&g_kl[(size_t)(m0 + r0 + 8) * HA + c] = l1;
        }
    }
}

// ---------------- V -> transposed [b][h][a][s] bf16 hi/lo ------------------
__global__ void __launch_bounds__(128) conv_v_k() {
    __shared__ float buf[64 * 68];
    int b = blockIdx.z, h = blockIdx.y, s0 = blockIdx.x * 64;
    int tid = threadIdx.x;
    #pragma unroll
    for (int p = 0; p < 8; p++) {
        int idx = tid + p * 128, s = idx >> 4, q = idx & 15;
        *(float4*)&buf[s * 68 + q * 4] =
            *(const float4*)&g_v[((size_t)(b << 10) + s0 + s) * HA + h * AA + q * 4];
    }
    __syncthreads();
    int aa = tid >> 1, sh = (tid & 1) * 32;
    u32 hv[16], lv[16];
    #pragma unroll
    for (int p = 0; p < 16; p++) {
        float x0 = buf[(sh + 2 * p) * 68 + aa], x1 = buf[(sh + 2 * p + 1) * 68 + aa];
        hv[p] = pkbf(x0, x1);
        float2 f = unbf(hv[p]);
        lv[p] = pkbf(x0 - f.x, x1 - f.y);
    }
    size_t o = ((size_t)(b * HH + h) * AA + aa) * SS + s0 + sh;
    #pragma unroll
    for (int p = 0; p < 4; p++) {
        *(uint4*)&g_vh[o + p * 8] = make_uint4(hv[4*p], hv[4*p+1], hv[4*p+2], hv[4*p+3]);
        *(uint4*)&g_vl[o + p * 8] = make_uint4(lv[4*p], lv[4*p+1], lv[4*p+2], lv[4*p+3]);
    }
}

// ---------------- attention: reg-resident flash + double-buffered staging --
__global__ void __launch_bounds__(128) attn_mma() {
    extern __shared__ unsigned char sm8[];
    const int t = blockIdx.x;
    if (t >= g_nt) return;
    const int h = blockIdx.y;
    const int b = g_tb[t], n0 = g_ts[t], cnt = g_tc[t];
    const int tid = threadIdx.x, lane = tid & 31, w = tid >> 5;
    const u32 SB = s2u(sm8);
    float* Sc = (float*)(sm8 + O_SC);
    float* Al = (float*)(sm8 + O_AL);
    const int jr = tid >> 1, half = (tid & 1) * 32;
    const u32 ro = (u32)(jr * 72 + half) * 2;
    const size_t krb = ((size_t)(b << 10) + jr) * HA + h * AA + half;
    const size_t vrb = ((size_t)(b * HH + h) * AA + jr) * SS + half;

    // stage Q hi/lo (once)
    {
        bool val = jr < cnt;
        const float* q = &g_q[(size_t)(n0 + jr) * HA + h * AA + half];
        #pragma unroll
        for (int u = 0; u < 4; u++) {
            float4 x0 = val ? *(const float4*)(q + u * 8) : make_float4(0, 0, 0, 0);
            float4 x1 = val ? *(const float4*)(q + u * 8 + 4) : make_float4(0, 0, 0, 0);
            u32 h0 = pkbf(x0.x, x0.y), h1 = pkbf(x0.z, x0.w);
            u32 h2 = pkbf(x1.x, x1.y), h3 = pkbf(x1.z, x1.w);
            float2 f0 = unbf(h0), f1 = unbf(h1), f2 = unbf(h2), f3 = unbf(h3);
            u32 l0 = pkbf(x0.x - f0.x, x0.y - f0.y), l1 = pkbf(x0.z - f1.x, x0.w - f1.y);
            u32 l2 = pkbf(x1.x - f2.x, x1.y - f2.y), l3 = pkbf(x1.z - f3.x, x1.w - f3.y);
            *(uint4*)(sm8 + O_QH + ro + u * 16) = make_uint4(h0, h1, h2, h3);
            *(uint4*)(sm8 + O_QL + ro + u * 16) = make_uint4(l0, l1, l2, l3);
        }
    }
    __syncthreads();
    u32 qhf[4][4], qlf[4][4];
    {
        u32 arow = 16 * w + (lane & 7) + ((lane >> 3) & 1) * 8;
        u32 acol = ((lane >> 4) & 1) * 8;
        #pragma unroll
        for (int k = 0; k < 4; k++) {
            ldmx4(qhf[k], SB + O_QH + (arow * 72 + acol + 16 * k) * 2);
            ldmx4(qlf[k], SB + O_QL + (arow * 72 + acol + 16 * k) * 2);
        }
    }
    __syncthreads();   // Q region free; staging buffers are elsewhere anyway

    // prologue: stage chunk 0 into buf0
    #pragma unroll
    for (int u = 0; u < 4; u++) {
        *(uint4*)(sm8 + O_B0 + 0     + ro + u * 16) = *(const uint4*)(&g_kh[krb] + u * 8);
        *(uint4*)(sm8 + O_B0 + 9216  + ro + u * 16) = *(const uint4*)(&g_kl[krb] + u * 8);
        *(uint4*)(sm8 + O_B0 + 18432 + ro + u * 16) = *(const uint4*)(&g_vh[vrb] + u * 8);
        *(uint4*)(sm8 + O_B0 + 27648 + ro + u * 16) = *(const uint4*)(&g_vl[vrb] + u * 8);
    }
    __syncthreads();

    const int lr = lane & 15;
    const u32 brow = lr & 7, bc8 = (lr >> 3) * 8;
    const int r0 = 16 * w + (lane >> 2), cc0 = (lane & 3) * 2;
    float mo0 = -FLT_MAX, mo1 = -FLT_MAX, ls0 = 0.f, ls1 = 0.f;
    float feat[8][4];
    #pragma unroll
    for (int cg = 0; cg < 8; cg++)
        feat[cg][0] = feat[cg][1] = feat[cg][2] = feat[cg][3] = 0.f;

    for (int c = 0; c < 16; c++) {
        int s0 = c * 64;
        u32 bb = (c & 1) ? O_B1 : O_B0;
        u32 bn = (c & 1) ? O_B0 : O_B1;
        // prefetch next chunk into registers (overlaps compute below)
        uint4 pf[16];
        if (c < 15) {
            size_t kr = krb + (size_t)(s0 + 64) * HA;
            size_t vr = vrb + s0 + 64;
            #pragma unroll
            for (int u = 0; u < 4; u++) {
                pf[u]      = *(const uint4*)(&g_kh[kr] + u * 8);
                pf[u + 4]  = *(const uint4*)(&g_kl[kr] + u * 8);
                pf[u + 8]  = *(const uint4*)(&g_vh[vr] + u * 8);
                pf[u + 12] = *(const uint4*)(&g_vl[vr] + u * 8);
            }
        }
        // QK scores
        float d[8][4];
        #pragma unroll
        for (int cg = 0; cg < 8; cg++) {
            d[cg][0] = d[cg][1] = d[cg][2] = d[cg][3] = 0.f;
            #pragma unroll
            for (int k = 0; k < 4; k++) {
                u32 off = ((cg * 8 + brow) * 72 + 16 * k + bc8) * 2;
                u32 bh[2], bl[2];
                ldmx2(bh, SB + bb + 0 + off);
                ldmx2(bl, SB + bb + 9216 + off);
                mma16816(d[cg], qhf[k], bh);
                mma16816(d[cg], qhf[k], bl);
                mma16816(d[cg], qlf[k], bh);
            }
            d[cg][0] *= 0.125f; d[cg][1] *= 0.125f;
            d[cg][2] *= 0.125f; d[cg][3] *= 0.125f;
        }
        if (h < 2) {
            float* base = (h == 0 ? g_sc0 : g_sc1);
            #pragma unroll
            for (int cg = 0; cg < 8; cg++) {
                int cc = s0 + cg * 8 + cc0;
                if (r0 < cnt)
                    *(float2*)&base[(size_t)(n0 + r0) * SS + cc] = make_float2(d[cg][0], d[cg][1]);
                if (r0 + 8 < cnt)
                    *(float2*)&base[(size_t)(n0 + r0 + 8) * SS + cc] = make_float2(d[cg][2], d[cg][3]);
            }
        }
        u16 mw[8];
        #pragma unroll
        for (int cg = 0; cg < 8; cg++)
            mw[cg] = *(const u16*)&g_mask[b * SS + s0 + cg * 8 + cc0];
        float cm0 = -FLT_MAX, cm1 = -FLT_MAX;
        #pragma unroll
        for (int cg = 0; cg < 8; cg++) {
            if (mw[cg] & 0xff) { cm0 = fmaxf(cm0, d[cg][0]); cm1 = fmaxf(cm1, d[cg][2]); }
            if (mw[cg] >> 8)   { cm0 = fmaxf(cm0, d[cg][1]); cm1 = fmaxf(cm1, d[cg][3]); }
        }
        cm0 = fmaxf(cm0, __shfl_xor_sync(0xffffffffu, cm0, 1));
        cm0 = fmaxf(cm0, __shfl_xor_sync(0xffffffffu, cm0, 2));
        cm1 = fmaxf(cm1, __shfl_xor_sync(0xffffffffu, cm1, 1));
        cm1 = fmaxf(cm1, __shfl_xor_sync(0xffffffffu, cm1, 2));
        float mn0 = fmaxf(mo0, cm0), mn1 = fmaxf(mo1, cm1);
        float a0 = (mo0 == mn0) ? 1.f : __expf(mo0 - mn0);
        float a1 = (mo1 == mn1) ? 1.f : __expf(mo1 - mn1);
        float cs0 = 0.f, cs1 = 0.f;
        u32 phf[4][4], plf[4][4];
        #pragma unroll
        for (int cg = 0; cg < 8; cg++) {
            float p0 = (mw[cg] & 0xff) ? __expf(d[cg][0] - mn0) : 0.f;
            float p1 = (mw[cg] >> 8)   ? __expf(d[cg][1] - mn0) : 0.f;
            float p2 = (mw[cg] & 0xff) ? __expf(d[cg][2] - mn1) : 0.f;
            float p3 = (mw[cg] >> 8)   ? __expf(d[cg][3] - mn1) : 0.f;
            cs0 += p0 + p1; cs1 += p2 + p3;
            u32 hA = pkbf(p0, p1), hB = pkbf(p2, p3);
            float2 fA = unbf(hA), fB = unbf(hB);
            u32 lA = pkbf(p0 - fA.x, p1 - fA.y), lB = pkbf(p2 - fB.x, p3 - fB.y);
            phf[cg >> 1][(cg & 1) * 2]     = hA;
            phf[cg >> 1][(cg & 1) * 2 + 1] = hB;
            plf[cg >> 1][(cg & 1) * 2]     = lA;
            plf[cg >> 1][(cg & 1) * 2 + 1] = lB;
        }
        ls0 = ls0 * a0 + cs0;  ls1 = ls1 * a1 + cs1;
        mo0 = mn0;  mo1 = mn1;
        #pragma unroll
        for (int cg = 0; cg < 8; cg++) {
            feat[cg][0] *= a0; feat[cg][1] *= a0;
            feat[cg][2] *= a1; feat[cg][3] *= a1;
            #pragma unroll
            for (int k = 0; k < 4; k++) {
                u32 off = ((cg * 8 + brow) * 72 + 16 * k + bc8) * 2;
                u32 bh[2], bl[2];
                ldmx2(bh, SB + bb + 18432 + off);
                ldmx2(bl, SB + bb + 27648 + off);
                mma16816(feat[cg], phf[k], bh);
                mma16816(feat[cg], phf[k], bl);
                mma16816(feat[cg], plf[k], bh);
            }
        }
        // store prefetched chunk into the other buffer
        if (c < 15) {
            #pragma unroll
            for (int u = 0; u < 4; u++) {
                *(uint4*)(sm8 + bn + 0     + ro + u * 16) = pf[u];
                *(uint4*)(sm8 + bn + 9216  + ro + u * 16) = pf[u + 4];
                *(uint4*)(sm8 + bn + 18432 + ro + u * 16) = pf[u + 8];
                *(uint4*)(sm8 + bn + 27648 + ro + u * 16) = pf[u + 12];
            }
        }
        __syncthreads();
    }

    ls0 += __shfl_xor_sync(0xffffffffu, ls0, 1);
    ls0 += __shfl_xor_sync(0xffffffffu, ls0, 2);
    ls1 += __shfl_xor_sync(0xffffffffu, ls1, 1);
    ls1 += __shfl_xor_sync(0xffffffffu, ls1, 2);
    #pragma unroll
    for (int cg = 0; cg < 8; cg++) {
        *(float2*)&Sc[r0 * 68 + cg * 8 + cc0] = make_float2(feat[cg][0], feat[cg][1]);
        *(float2*)&Sc[(r0 + 8) * 68 + cg * 8 + cc0] = make_float2(feat[cg][2], feat[cg][3]);
    }
    if ((lane & 3) == 0) {
        Al[r0] = 1.f / (ls0 + 1e-9f);
        Al[r0 + 8] = 1.f / (ls1 + 1e-9f);
    }
    __syncthreads();
    // epilogue: gate, split to bf16 hi/lo feat
    if (tid < cnt) {
        float inv = Al[tid];
        const float* gp = &g_gate[(size_t)(n0 + tid) * HA + h * AA];
        size_t fo = (size_t)(n0 + tid) * HA + h * AA;
        const float* sr = &Sc[tid * 68];
        #pragma unroll
        for (int x = 0; x < 16; x++) {
            float4 v = *(const float4*)(sr + x * 4);
            float4 g = *(const float4*)(gp + x * 4);
            float o0 = v.x * inv * g.x, o1 = v.y * inv * g.y;
            float o2 = v.z * inv * g.z, o3 = v.w * inv * g.w;
            u32 h0 = pkbf(o0, o1), h1 = pkbf(o2, o3);
            float2 f0 = unbf(h0), f1 = unbf(h1);
            u32 l0 = pkbf(o0 - f0.x, o1 - f0.y), l1 = pkbf(o2 - f1.x, o3 - f1.y);
            *(uint2*)&g_fh[fo + x * 4] = make_uint2(h0, h1);
            *(uint2*)&g_fl[fo + x * 4] = make_uint2(l0, l1);
        }
    }
}

// ---------------- logits = sc0 + sc1 ---------------------------------------
__global__ void addlog_k(float* __restrict__ logits) {
    size_t i = ((size_t)blockIdx.x * 256 + threadIdx.x) * 4;
    float4 a = *(const float4*)&g_sc0[i];
    float4 b4 = *(const float4*)&g_sc1[i];
    *(float4*)&logits[i] = make_float4(a.x + b4.x, a.y + b4.y, a.z + b4.z, a.w + b4.w);
}

// ---------------- y = sqrt(2)*x + feat @ Wback + bback : mma ---------------
__global__ void __launch_bounds__(128) back_mma(const float* __restrict__ x,
                                                const float* __restrict__ bback) {
    __shared__ __align__(16) unsigned char sm[36864];
    const u32 SB = s2u(sm);
    int m0 = blockIdx.x * 64, n0 = blockIdx.y * 64;
    int tid = threadIdx.x, lane = tid & 31, w = tid >> 5;
    const int lr = lane & 15;
    const u32 brow = lr & 7, bc8 = (lr >> 3) * 8;
    const int r0 = 16 * w + (lane >> 2), cc0 = (lane & 3) * 2;
    u32 arow = 16 * w + (lane & 7) + ((lane >> 3) & 1) * 8;
    u32 acol = ((lane >> 4) & 1) * 8;
    float acc[8][4];
    #pragma unroll
    for (int cg = 0; cg < 8; cg++)
        acc[cg][0] = acc[cg][1] = acc[cg][2] = acc[cg][3] = 0.f;
    int r = tid >> 1, kh2 = (tid & 1) * 32;
    for (int kc = 0; kc < 8; kc++) {
        int k0 = kc * 64;
        {
            size_t fa = (size_t)(m0 + r) * HA + k0 + kh2;
            size_t wa = (size_t)(n0 + r) * HA + k0 + kh2;
            u32 ro = (u32)(r * 72 + kh2) * 2;
            #pragma unroll
            for (int u = 0; u < 4; u++) {
                *(uint4*)(sm + 0     + ro + u * 16) = *(const uint4*)(&g_fh[fa] + u * 8);
                *(uint4*)(sm + 9216  + ro + u * 16) = *(const uint4*)(&g_fl[fa] + u * 8);
                *(uint4*)(sm + 18432 + ro + u * 16) = *(const uint4*)(&g_wbh[wa] + u * 8);
                *(uint4*)(sm + 27648 + ro + u * 16) = *(const uint4*)(&g_wbl[wa] + u * 8);
            }
        }
        __syncthreads();
        u32 ahf[4][4], alf[4][4];
        #pragma unroll
        for (int k = 0; k < 4; k++) {
            ldmx4(ahf[k], SB + 0    + (arow * 72 + acol + 16 * k) * 2);
            ldmx4(alf[k], SB + 9216 + (arow * 72 + acol + 16 * k) * 2);
        }
        #pragma unroll
        for (int cg = 0; cg < 8; cg++) {
            #pragma unroll
            for (int k = 0; k < 4; k++) {
                u32 off = ((cg * 8 + brow) * 72 + 16 * k + bc8) * 2;
                u32 bh[2], bl[2];
                ldmx2(bh, SB + 18432 + off);
                ldmx2(bl, SB + 27648 + off);
                mma16816(acc[cg], ahf[k], bh);
                mma16816(acc[cg], ahf[k], bl);
                mma16816(acc[cg], alf[k], bh);
            }
        }
        __syncthreads();
    }
    const float rt2 = 1.41421356237309515f;
    #pragma unroll
    for (int cg = 0; cg < 8; cg++) {
        int c = n0 + cg * 8 + cc0;
        float b0 = bback[c], b1 = bback[c + 1];
        float2 x0 = *(const float2*)&x[(size_t)(m0 + r0) * IFZ + c];
        float2 x1 = *(const float2*)&x[(size_t)(m0 + r0 + 8) * IFZ + c];
        *(float2*)&g_y[(size_t)(m0 + r0) * IFZ + c] =
            make_float2(rt2 * x0.x + acc[cg][0] + b0, rt2 * x0.y + acc[cg][1] + b1);
        *(float2*)&g_y[(size_t)(m0 + r0 + 8) * IFZ + c] =
            make_float2(rt2 * x1.x + acc[cg][2] + b0, rt2 * x1.y + acc[cg][3] + b1);
    }
}

// ---------------- LayerNorm ------------------------------------------------
__global__ void __launch_bounds__(256) ln_k(const float* __restrict__ gamma,
                                            const float* __restrict__ beta,
                                            float* __restrict__ out) {
    int warp = threadIdx.x >> 5, lane = threadIdx.x & 31;
    int row = blockIdx.x * 8 + warp;
    float4 v0 = *(const float4*)&g_y[(size_t)row * IFZ + lane * 4];
    float4 v1 = *(const float4*)&g_y[(size_t)row * IFZ + 128 + lane * 4];
    float s = v0.x + v0.y + v0.z + v0.w + v1.x + v1.y + v1.z + v1.w;
    #pragma unroll
    for (int d = 16; d; d >>= 1) s += __shfl_xor_sync(0xffffffffu, s, d);
    float mu = s * (1.f / 256.f);
    float q = 0.f;
    q += (v0.x - mu) * (v0.x - mu); q += (v0.y - mu) * (v0.y - mu);
    q += (v0.z - mu) * (v0.z - mu); q += (v0.w - mu) * (v0.w - mu);
    q += (v1.x - mu) * (v1.x - mu); q += (v1.y - mu) * (v1.y - mu);
    q += (v1.z - mu) * (v1.z - mu); q += (v1.w - mu) * (v1.w - mu);
    #pragma unroll
    for (int d = 16; d; d >>= 1) q += __shfl_xor_sync(0xffffffffu, q, d);
    float inv = rsqrtf(q * (1.f / 256.f) + 1e-5f);
    float4 g0 = *(const float4*)&gamma[lane * 4];
    float4 b0 = *(const float4*)&beta[lane * 4];
    float4 g1 = *(const float4*)&gamma[128 + lane * 4];
    float4 b1 = *(const float4*)&beta[128 + lane * 4];
    float4 o0, o1;
    o0.x = (v0.x - mu) * inv * g0.x + b0.x;
    o0.y = (v0.y - mu) * inv * g0.y + b0.y;
    o0.z = (v0.z - mu) * inv * g0.z + b0.z;
    o0.w = (v0.w - mu) * inv * g0.w + b0.w;
    o1.x = (v1.x - mu) * inv * g1.x + b1.x;
    o1.y = (v1.y - mu) * inv * g1.y + b1.y;
    o1.z = (v1.z - mu) * inv * g1.z + b1.z;
    o1.w = (v1.w - mu) * inv * g1.w + b1.w;
    *(float4*)&out[(size_t)row * IFZ + lane * 4] = o0;
    *(float4*)&out[(size_t)row * IFZ + 128 + lane * 4] = o1;
}

// ---------------- launch ---------------------------------------------------
extern "C" void kernel_launch(void* const* d_in, const int* in_sizes, int n_in,
                              void* d_out, int out_size) {
    const float* x     = (const float*)d_in[0];
    const float* emb   = (const float*)d_in[1];
    const void*  mask  = d_in[2];
    const void*  batch = d_in[3];
    const float* Wq    = (const float*)d_in[4];
    const float* Wk    = (const float*)d_in[5];
    const float* Wv    = (const float*)d_in[6];
    const float* Wg    = (const float*)d_in[7];
    const float* bg    = (const float*)d_in[8];
    const float* Wback = (const float*)d_in[9];
    const float* bback = (const float*)d_in[10];
    const float* gamma = (const float*)d_in[11];
    const float* beta  = (const float*)d_in[12];
    float* out    = (float*)d_out;
    float* logits = out + (size_t)NN * IFZ;

    static int smem_set = 0;
    if (!smem_set) {
        cudaFuncSetAttribute(attn_mma, cudaFuncAttributeMaxDynamicSharedMemorySize,
                             ATTN_SMEMB);
        smem_set = 1;
    }

    prep_k<<<1, 256>>>(mask, batch);
    conv_e_k<<<1536, 256>>>(emb);
    conv_x_k<<<512, 256>>>(x);
    conv_w_k<<<dim3(6, 16), 128>>>(Wk, Wv);
    conv_wqg_k<<<dim3(4, 16), 128>>>(Wq, Wg);
    conv_wb_k<<<dim3(8, 4), 128>>>(Wback);
    proj_qg_mma<<<dim3(32, 16), 128>>>(bg);
    proj_kv_mma<<<dim3(64, 16), 128>>>();
    conv_v_k<<<dim3(16, HH, BBATCH), 128>>>();
    attn_mma<<<dim3(MAXT, HH), 128, ATTN_SMEMB>>>();
    addlog_k<<<2048, 256>>>(logits);
    back_mma<<<dim3(32, 4), 128>>>(x, bback);
    ln_k<<<256, 256>>>(gamma, beta, out);
}